// round 1
// baseline (speedup 1.0000x reference)
#include <cuda_runtime.h>
#include <math.h>
#include <stdint.h>

#define Bn 2
#define Cn 64
#define Hn 320
#define Wn 640
#define TFn 16
#define HIDDEN 48
#define GROUPS 8
#define CPG 6            // 48 / 8 channels per GN group
#define IN_CH 188        // 2*64 + 16 + 4 + 8*5
#define HW (Hn*Wn)       // 204800
#define GN_N (CPG*HW)    // elements per (b, group)
#define BHW (Bn*HW)      // 409600

// ---------------- scratch (device globals: allocation-free) ----------------
__device__ float  g_x [Bn*IN_CH*HW];   // 308 MB concat input
__device__ float  g_h1[Bn*HIDDEN*HW];  // 78.6 MB
__device__ float  g_h2[Bn*HIDDEN*HW];  // 78.6 MB
__device__ double g_stats[Bn*GROUPS*2];

// ---------------------------------------------------------------------------
// Kernel 1: build x = concat(fL, warp(fR,d), feat, d, sx, sy, conf, corr)
// One block per (b, y) row; 640 threads = one per pixel. fR rows staged in
// smem 8 channels (one corr group) at a time; gathers become LDS.
// ---------------------------------------------------------------------------
__global__ void __launch_bounds__(Wn) build_x_kernel(
    const float* __restrict__ dm, const float* __restrict__ sx,
    const float* __restrict__ sy, const float* __restrict__ feat,
    const float* __restrict__ conf, const float* __restrict__ fL,
    const float* __restrict__ fR)
{
    __shared__ float srow[8*Wn];           // 20 KB
    const int b = blockIdx.x / Hn;
    const int y = blockIdx.x % Hn;
    const int x = threadIdx.x;
    const int prow = b*HW + y*Wn;

    const float dval = dm[prow + x];
    int i0[5], i1[5]; float fr[5];
#pragma unroll
    for (int i = 0; i < 5; i++) {
        float xs = (float)x - dval - (float)(i-2);
        xs = fminf(fmaxf(xs, 0.f), (float)(Wn-1));
        float f0 = floorf(xs);
        i0[i] = (int)f0;
        fr[i] = xs - f0;
        i1[i] = min(i0[i]+1, Wn-1);
    }

    float* xb = g_x + (size_t)b*IN_CH*HW + (size_t)y*Wn + x;     // stride HW per channel
    const float* fLp = fL + (size_t)b*Cn*HW + (size_t)y*Wn + x;
    const float* fRp = fR + (size_t)b*Cn*HW + (size_t)y*Wn;

    for (int g = 0; g < 8; g++) {
        __syncthreads();
#pragma unroll
        for (int j = 0; j < 8; j++)
            srow[j*Wn + x] = fRp[(size_t)(g*8+j)*HW + x];
        __syncthreads();

        float acc[5] = {0.f,0.f,0.f,0.f,0.f};
#pragma unroll
        for (int j = 0; j < 8; j++) {
            const int c = g*8 + j;
            const float fl = fLp[(size_t)c*HW];
            xb[(size_t)c*HW] = fl;
#pragma unroll
            for (int i = 0; i < 5; i++) {
                float v = srow[j*Wn+i0[i]]*(1.f-fr[i]) + srow[j*Wn+i1[i]]*fr[i];
                acc[i] += fl*v;
                if (i == 2) xb[(size_t)(64+c)*HW] = v;   // warp == offset 0 sample
            }
        }
#pragma unroll
        for (int i = 0; i < 5; i++)
            xb[(size_t)(148 + g*5 + i)*HW] = acc[i]*(1.f/8.f);
    }
#pragma unroll
    for (int j = 0; j < TFn; j++)
        xb[(size_t)(128+j)*HW] = feat[((size_t)b*TFn + j)*HW + y*Wn + x];
    xb[(size_t)144*HW] = dval;
    xb[(size_t)145*HW] = sx[prow + x];
    xb[(size_t)146*HW] = sy[prow + x];
    xb[(size_t)147*HW] = conf[prow + x];
}

// ---------------------------------------------------------------------------
// Kernel 2: generic 3x3 conv, pad=1, no bias. 32x8 pixel tile per block,
// one thread per pixel holding all 48 output accumulators. If GN is set,
// the previous layer's GroupNorm+SiLU is fused into the tile load.
// ---------------------------------------------------------------------------
template<int IN, bool GN>
__global__ void __launch_bounds__(256) conv3x3_kernel(
    const float* __restrict__ in, const float* __restrict__ wgt,
    const float* __restrict__ gamma, const float* __restrict__ beta,
    float* __restrict__ out)
{
    __shared__ float tile[10*36];
    __shared__ float wsm[HIDDEN*12];       // padded stride 12 -> 16B aligned rows

    const int tid = threadIdx.x;
    const int tx = tid & 31, ty = tid >> 5;
    const int x0 = blockIdx.x*32, y0 = blockIdx.y*8;
    const int b  = blockIdx.z;

    float acc[HIDDEN];
#pragma unroll
    for (int o = 0; o < HIDDEN; o++) acc[o] = 0.f;

    for (int ci = 0; ci < IN; ci++) {
        float scale = 1.f, shift = 0.f;
        if (GN) {
            const int grp = ci / CPG;
            double s = g_stats[(b*GROUPS+grp)*2+0];
            double q = g_stats[(b*GROUPS+grp)*2+1];
            double mean = s / (double)GN_N;
            double var  = q / (double)GN_N - mean*mean;
            float inv = (float)rsqrt(var + 1e-5);
            scale = gamma[ci]*inv;
            shift = beta[ci] - (float)mean*scale;
        }
        const float* ip = in + (size_t)(b*IN + ci)*HW;
        for (int idx = tid; idx < 340; idx += 256) {
            int r = idx/34, cc = idx%34;
            int gy = y0-1+r, gx = x0-1+cc;
            float v = 0.f;
            if (gy >= 0 && gy < Hn && gx >= 0 && gx < Wn) {
                v = ip[gy*Wn + gx];
                if (GN) {
                    float z = v*scale + shift;
                    v = z / (1.f + expf(-z));   // SiLU
                }
            }
            tile[r*36 + cc] = v;
        }
        for (int idx = tid; idx < 432; idx += 256) {
            int o = idx/9, k = idx%9;
            wsm[o*12 + k] = wgt[((size_t)o*IN + ci)*9 + k];
        }
        __syncthreads();

        float v[9];
#pragma unroll
        for (int dy = 0; dy < 3; dy++)
#pragma unroll
            for (int dx = 0; dx < 3; dx++)
                v[dy*3+dx] = tile[(ty+dy)*36 + tx+dx];

        const float4* w4 = (const float4*)wsm;
#pragma unroll
        for (int o = 0; o < HIDDEN; o++) {
            float4 a0 = w4[o*3+0];
            float4 a1 = w4[o*3+1];
            float4 a2 = w4[o*3+2];
            acc[o] += a0.x*v[0] + a0.y*v[1] + a0.z*v[2] + a0.w*v[3]
                    + a1.x*v[4] + a1.y*v[5] + a1.z*v[6] + a1.w*v[7]
                    + a2.x*v[8];
        }
        __syncthreads();
    }

    float* op = out + (size_t)b*HIDDEN*HW + (size_t)(y0+ty)*Wn + (x0+tx);
#pragma unroll
    for (int o = 0; o < HIDDEN; o++)
        op[(size_t)o*HW] = acc[o];
}

// ---------------------------------------------------------------------------
// GN stats: zero + two-pass sum / sumsq in double
// ---------------------------------------------------------------------------
__global__ void zero_stats_kernel() {
    if (threadIdx.x < Bn*GROUPS*2) g_stats[threadIdx.x] = 0.0;
}

__global__ void __launch_bounds__(256) gn_reduce_kernel(const float* __restrict__ h)
{
    const int bc = blockIdx.x;          // b*48 + c, 0..95
    const int slice = blockIdx.y;       // 0..3
    const float4* p = (const float4*)(h + (size_t)bc*HW);
    const int base = slice*12800;

    double s = 0.0, q = 0.0;
#pragma unroll 4
    for (int k = 0; k < 50; k++) {
        float4 f = p[base + threadIdx.x + k*256];
        s += (double)f.x + (double)f.y + (double)f.z + (double)f.w;
        q += (double)f.x*f.x + (double)f.y*f.y + (double)f.z*f.z + (double)f.w*f.w;
    }
#pragma unroll
    for (int o = 16; o > 0; o >>= 1) {
        s += __shfl_down_sync(0xFFFFFFFFu, s, o);
        q += __shfl_down_sync(0xFFFFFFFFu, q, o);
    }
    __shared__ double ss[8], qq[8];
    if ((threadIdx.x & 31) == 0) { ss[threadIdx.x>>5] = s; qq[threadIdx.x>>5] = q; }
    __syncthreads();
    if (threadIdx.x == 0) {
        double S = 0.0, Q = 0.0;
#pragma unroll
        for (int w = 0; w < 8; w++) { S += ss[w]; Q += qq[w]; }
        const int b = bc / HIDDEN, c = bc % HIDDEN, g = c / CPG;
        atomicAdd(&g_stats[(b*GROUPS+g)*2+0], S);
        atomicAdd(&g_stats[(b*GROUPS+g)*2+1], Q);
    }
}

// ---------------------------------------------------------------------------
// Kernel 3: fused GN3+SiLU + five 1x1 heads + epilogues.
// Output layout: [d | sx | sy | feat(16ch) | conf], each flattened NCHW.
// ---------------------------------------------------------------------------
__global__ void __launch_bounds__(256) heads_kernel(
    const float* __restrict__ h,
    const float* __restrict__ gamma, const float* __restrict__ beta,
    const float* __restrict__ dm, const float* __restrict__ sxp,
    const float* __restrict__ syp, const float* __restrict__ feat,
    const float* __restrict__ conf,
    const float* __restrict__ hd_w,  const float* __restrict__ hd_b,
    const float* __restrict__ hsx_w, const float* __restrict__ hsx_b,
    const float* __restrict__ hsy_w, const float* __restrict__ hsy_b,
    const float* __restrict__ hc_w,  const float* __restrict__ hc_b,
    const float* __restrict__ hf_w,  const float* __restrict__ hf_b,
    float* __restrict__ out)
{
    __shared__ float wsm[20*HIDDEN];
    __shared__ float bia[20];
    __shared__ float sc[HIDDEN], sh[HIDDEN];

    const int tid = threadIdx.x;
    const int b   = blockIdx.y;

    for (int idx = tid; idx < 20*HIDDEN; idx += 256) {
        int o = idx / HIDDEN, c = idx % HIDDEN;
        float w;
        if (o == 0)      w = hd_w[c];
        else if (o == 1) w = hsx_w[c];
        else if (o == 2) w = hsy_w[c];
        else if (o == 3) w = hc_w[c];
        else             w = hf_w[(o-4)*HIDDEN + c];
        wsm[idx] = w;
    }
    if (tid < 20) {
        bia[tid] = (tid==0) ? hd_b[0] : (tid==1) ? hsx_b[0] : (tid==2) ? hsy_b[0]
                 : (tid==3) ? hc_b[0] : hf_b[tid-4];
    }
    if (tid < HIDDEN) {
        const int g = tid / CPG;
        double s = g_stats[(b*GROUPS+g)*2+0];
        double q = g_stats[(b*GROUPS+g)*2+1];
        double mean = s / (double)GN_N;
        double var  = q / (double)GN_N - mean*mean;
        float inv = (float)rsqrt(var + 1e-5);
        sc[tid] = gamma[tid]*inv;
        sh[tid] = beta[tid] - (float)mean*sc[tid];
    }
    __syncthreads();

    const int rem = blockIdx.x*256 + tid;          // 0..HW-1
    const float* hp = h + (size_t)b*HIDDEN*HW + rem;

    float acc[20];
#pragma unroll
    for (int o = 0; o < 20; o++) acc[o] = 0.f;
#pragma unroll 4
    for (int c = 0; c < HIDDEN; c++) {
        float z = hp[(size_t)c*HW]*sc[c] + sh[c];
        float a = z / (1.f + expf(-z));
#pragma unroll
        for (int o = 0; o < 20; o++) acc[o] += wsm[o*HIDDEN + c]*a;
    }

    const int p = b*HW + rem;
    // d_out = softplus(head + d)
    float t = acc[0] + bia[0] + dm[p];
    out[p] = fmaxf(t, 0.f) + log1pf(expf(-fabsf(t)));
    // sx / sy
    out[BHW   + p] = sxp[p] + (acc[1] + bia[1])*0.1f;
    out[2*BHW + p] = syp[p] + (acc[2] + bia[2])*0.1f;
    // feat_out (16 channels) at offset 3*BHW
#pragma unroll
    for (int j = 0; j < TFn; j++) {
        size_t fi = ((size_t)b*TFn + j)*HW + rem;
        out[3*(size_t)BHW + fi] = feat[fi] + acc[4+j] + bia[4+j];
    }
    // conf_out at offset 19*BHW
    float cz = acc[3] + bia[3] + 2.f*conf[p] - 1.f;
    out[19*(size_t)BHW + p] = 1.f / (1.f + expf(-cz));
}

// ---------------------------------------------------------------------------
extern "C" void kernel_launch(void* const* d_in, const int* in_sizes, int n_in,
                              void* d_out, int out_size)
{
    const float* dm   = (const float*)d_in[0];
    const float* sx   = (const float*)d_in[1];
    const float* sy   = (const float*)d_in[2];
    const float* feat = (const float*)d_in[3];
    const float* conf = (const float*)d_in[4];
    const float* fL   = (const float*)d_in[5];
    const float* fR   = (const float*)d_in[6];
    const float* w1   = (const float*)d_in[7];
    const float* w2   = (const float*)d_in[8];
    const float* w3   = (const float*)d_in[9];
    const float* g1g  = (const float*)d_in[10];
    const float* g1b  = (const float*)d_in[11];
    const float* g2g  = (const float*)d_in[12];
    const float* g2b  = (const float*)d_in[13];
    const float* g3g  = (const float*)d_in[14];
    const float* g3b  = (const float*)d_in[15];
    const float* hd_w  = (const float*)d_in[16];
    const float* hd_b  = (const float*)d_in[17];
    const float* hsx_w = (const float*)d_in[18];
    const float* hsx_b = (const float*)d_in[19];
    const float* hsy_w = (const float*)d_in[20];
    const float* hsy_b = (const float*)d_in[21];
    const float* hc_w  = (const float*)d_in[22];
    const float* hc_b  = (const float*)d_in[23];
    const float* hf_w  = (const float*)d_in[24];
    const float* hf_b  = (const float*)d_in[25];
    float* out = (float*)d_out;

    float *px, *ph1, *ph2;
    cudaGetSymbolAddress((void**)&px,  g_x);
    cudaGetSymbolAddress((void**)&ph1, g_h1);
    cudaGetSymbolAddress((void**)&ph2, g_h2);

    const dim3 cgrid(Wn/32, Hn/8, Bn);   // (20, 40, 2)
    const dim3 rgrid(Bn*HIDDEN, 4);      // (96, 4)
    const dim3 hgrid(HW/256, Bn);        // (800, 2)

    // 1) build concat input
    build_x_kernel<<<Bn*Hn, Wn>>>(dm, sx, sy, feat, conf, fL, fR);

    // 2) conv1 (raw input) -> h1 preact
    conv3x3_kernel<IN_CH, false><<<cgrid, 256>>>(px, w1, nullptr, nullptr, ph1);
    zero_stats_kernel<<<1, 64>>>();
    gn_reduce_kernel<<<rgrid, 256>>>(ph1);

    // 3) conv2 with fused GN1+SiLU on input -> h2 preact
    conv3x3_kernel<HIDDEN, true><<<cgrid, 256>>>(ph1, w2, g1g, g1b, ph2);
    zero_stats_kernel<<<1, 64>>>();
    gn_reduce_kernel<<<rgrid, 256>>>(ph2);

    // 4) conv3 with fused GN2+SiLU on input -> h1 preact (reuse)
    conv3x3_kernel<HIDDEN, true><<<cgrid, 256>>>(ph2, w3, g2g, g2b, ph1);
    zero_stats_kernel<<<1, 64>>>();
    gn_reduce_kernel<<<rgrid, 256>>>(ph1);

    // 5) fused GN3+SiLU + heads + epilogues
    heads_kernel<<<hgrid, 256>>>(ph1, g3g, g3b,
                                 dm, sx, sy, feat, conf,
                                 hd_w, hd_b, hsx_w, hsx_b, hsy_w, hsy_b,
                                 hc_w, hc_b, hf_w, hf_b, out);
}

// round 2
// speedup vs baseline: 1.1329x; 1.1329x over previous
#include <cuda_runtime.h>
#include <math.h>
#include <stdint.h>

#define Bn 2
#define Cn 64
#define Hn 320
#define Wn 640
#define TFn 16
#define HIDDEN 48
#define GROUPS 8
#define CPG 6
#define IN_CH 188
#define HW (Hn*Wn)
#define GN_N (CPG*HW)
#define BHW (Bn*HW)

// ---------------- scratch ----------------
__device__ float  g_x [Bn*IN_CH*HW];
__device__ float  g_h1[Bn*HIDDEN*HW];
__device__ float  g_h2[Bn*HIDDEN*HW];
__device__ double g_stats[Bn*GROUPS*2];
__device__ float  g_scale[Bn*HIDDEN];
__device__ float  g_shift[Bn*HIDDEN];

// ---------------------------------------------------------------------------
// Kernel 1: build x = concat(fL, warp(fR,d), feat, d, sx, sy, conf, corr)
// ---------------------------------------------------------------------------
__global__ void __launch_bounds__(Wn) build_x_kernel(
    const float* __restrict__ dm, const float* __restrict__ sx,
    const float* __restrict__ sy, const float* __restrict__ feat,
    const float* __restrict__ conf, const float* __restrict__ fL,
    const float* __restrict__ fR)
{
    __shared__ float srow[8*Wn];
    const int b = blockIdx.x / Hn;
    const int y = blockIdx.x % Hn;
    const int x = threadIdx.x;
    const int prow = b*HW + y*Wn;

    const float dval = dm[prow + x];
    int i0[5], i1[5]; float fr[5];
#pragma unroll
    for (int i = 0; i < 5; i++) {
        float xs = (float)x - dval - (float)(i-2);
        xs = fminf(fmaxf(xs, 0.f), (float)(Wn-1));
        float f0 = floorf(xs);
        i0[i] = (int)f0;
        fr[i] = xs - f0;
        i1[i] = min(i0[i]+1, Wn-1);
    }

    float* xb = g_x + (size_t)b*IN_CH*HW + (size_t)y*Wn + x;
    const float* fLp = fL + (size_t)b*Cn*HW + (size_t)y*Wn + x;
    const float* fRp = fR + (size_t)b*Cn*HW + (size_t)y*Wn;

    for (int g = 0; g < 8; g++) {
        __syncthreads();
#pragma unroll
        for (int j = 0; j < 8; j++)
            srow[j*Wn + x] = fRp[(size_t)(g*8+j)*HW + x];
        __syncthreads();

        float acc[5] = {0.f,0.f,0.f,0.f,0.f};
#pragma unroll
        for (int j = 0; j < 8; j++) {
            const int c = g*8 + j;
            const float fl = fLp[(size_t)c*HW];
            xb[(size_t)c*HW] = fl;
#pragma unroll
            for (int i = 0; i < 5; i++) {
                float v = srow[j*Wn+i0[i]]*(1.f-fr[i]) + srow[j*Wn+i1[i]]*fr[i];
                acc[i] += fl*v;
                if (i == 2) xb[(size_t)(64+c)*HW] = v;
            }
        }
#pragma unroll
        for (int i = 0; i < 5; i++)
            xb[(size_t)(148 + g*5 + i)*HW] = acc[i]*(1.f/8.f);
    }
#pragma unroll
    for (int j = 0; j < TFn; j++)
        xb[(size_t)(128+j)*HW] = feat[((size_t)b*TFn + j)*HW + y*Wn + x];
    xb[(size_t)144*HW] = dval;
    xb[(size_t)145*HW] = sx[prow + x];
    xb[(size_t)146*HW] = sy[prow + x];
    xb[(size_t)147*HW] = conf[prow + x];
}

// ---------------------------------------------------------------------------
// Kernel 2 v2: 3x3 conv, 64x8 tile, 2 adjacent px/thread, double-buffered smem,
// one __syncthreads per input channel. Optional fused GN+SiLU on input load.
// ---------------------------------------------------------------------------
template<int IN, bool HASGN>
__global__ void __launch_bounds__(256) conv3x3_v2(
    const float* __restrict__ in, const float* __restrict__ wgt,
    float* __restrict__ out, int b_scsh)
{
    __shared__ float ts[2][10*68];     // tile: 10 rows x 66 cols (pad to 68)
    __shared__ float ws[2][48*12];     // weights: 48 outs x 9 (pad to 12)

    const int tid = threadIdx.x;
    const int tx = tid & 31, ty = tid >> 5;
    const int x0 = blockIdx.x*64, y0 = blockIdx.y*8;
    const int b  = blockIdx.z;

    const float* inb = in + (size_t)b*IN*HW;
    const float* scb = g_scale + (b + b_scsh*0)*HIDDEN;   // only used if HASGN
    const float* shb = g_shift + b*HIDDEN;

    // precompute tile-load slots (3 per thread)
    int   toff[3], soff[3];
    bool  timg[3], tin[3];
#pragma unroll
    for (int j = 0; j < 3; j++) {
        int idx = tid + j*256;
        int r = idx/66, c = idx%66;
        int gy = y0-1+r, gx = x0-1+c;
        tin[j]  = (idx < 660);
        timg[j] = tin[j] && gy >= 0 && gy < Hn && gx >= 0 && gx < Wn;
        toff[j] = timg[j] ? gy*Wn + gx : 0;
        soff[j] = r*68 + c;
    }
    // weight-load slots (2 per thread)
    int wo[2], wk[2]; bool win[2];
#pragma unroll
    for (int j = 0; j < 2; j++) {
        int idx = tid + j*256;
        win[j] = (idx < 432);
        wo[j] = idx/9; wk[j] = idx%9;
        if (!win[j]) { wo[j] = 0; wk[j] = 0; }
    }

    float acc0[48], acc1[48];
#pragma unroll
    for (int o = 0; o < 48; o++) { acc0[o] = 0.f; acc1[o] = 0.f; }

    // prologue: load channel 0 into buffer 0
    {
        float sc = 1.f, sh = 0.f;
        if (HASGN) { sc = scb[0]; sh = shb[0]; }
#pragma unroll
        for (int j = 0; j < 3; j++) {
            if (tin[j]) {
                float v = 0.f;
                if (timg[j]) {
                    v = inb[toff[j]];
                    if (HASGN) { float z = v*sc + sh; v = z / (1.f + expf(-z)); }
                }
                ts[0][soff[j]] = v;
            }
        }
#pragma unroll
        for (int j = 0; j < 2; j++)
            if (win[j]) ws[0][wo[j]*12 + wk[j]] = wgt[((size_t)wo[j]*IN + 0)*9 + wk[j]];
    }
    __syncthreads();

    int cur = 0;
#pragma unroll 1
    for (int ci = 0; ci < IN; ci++) {
        // ---- issue LDGs for next channel into registers ----
        float tv[3] = {0.f,0.f,0.f};
        float wv[2] = {0.f,0.f};
        float sc = 1.f, sh = 0.f;
        const bool more = (ci + 1 < IN);
        if (more) {
            const float* ip = inb + (size_t)(ci+1)*HW;
#pragma unroll
            for (int j = 0; j < 3; j++)
                if (timg[j]) tv[j] = ip[toff[j]];
#pragma unroll
            for (int j = 0; j < 2; j++)
                if (win[j]) wv[j] = wgt[((size_t)wo[j]*IN + (ci+1))*9 + wk[j]];
            if (HASGN) { sc = scb[ci+1]; sh = shb[ci+1]; }
        }

        // ---- compute current channel ----
        float v00,v01,v02,v03, v10,v11,v12,v13, v20,v21,v22,v23;
        {
            const float* base = &ts[cur][ty*68 + 2*tx];
            float2 a0 = *(const float2*)(base + 0);
            float2 a1 = *(const float2*)(base + 2);
            float2 b0 = *(const float2*)(base + 68);
            float2 b1 = *(const float2*)(base + 70);
            float2 c0 = *(const float2*)(base + 136);
            float2 c1 = *(const float2*)(base + 138);
            v00=a0.x; v01=a0.y; v02=a1.x; v03=a1.y;
            v10=b0.x; v11=b0.y; v12=b1.x; v13=b1.y;
            v20=c0.x; v21=c0.y; v22=c1.x; v23=c1.y;
        }
        const float4* w4 = (const float4*)ws[cur];
#pragma unroll
        for (int o = 0; o < 48; o++) {
            float4 q0 = w4[o*3+0];
            float4 q1 = w4[o*3+1];
            float4 q2 = w4[o*3+2];
            acc0[o] += q0.x*v00 + q0.y*v01 + q0.z*v02
                     + q0.w*v10 + q1.x*v11 + q1.y*v12
                     + q1.z*v20 + q1.w*v21 + q2.x*v22;
            acc1[o] += q0.x*v01 + q0.y*v02 + q0.z*v03
                     + q0.w*v11 + q1.x*v12 + q1.y*v13
                     + q1.z*v21 + q1.w*v22 + q2.x*v23;
        }

        // ---- store next channel into other buffer ----
        if (more) {
            const int nb = cur ^ 1;
#pragma unroll
            for (int j = 0; j < 3; j++) {
                if (tin[j]) {
                    float v = tv[j];
                    if (HASGN && timg[j]) { float z = v*sc + sh; v = z / (1.f + expf(-z)); }
                    ts[nb][soff[j]] = v;
                }
            }
#pragma unroll
            for (int j = 0; j < 2; j++)
                if (win[j]) ws[nb][wo[j]*12 + wk[j]] = wv[j];
        }
        __syncthreads();
        cur ^= 1;
    }

    float* op = out + (size_t)b*HIDDEN*HW + (size_t)(y0+ty)*Wn + (x0 + 2*tx);
#pragma unroll
    for (int o = 0; o < 48; o++)
        *(float2*)&op[(size_t)o*HW] = make_float2(acc0[o], acc1[o]);
}

// ---------------------------------------------------------------------------
// GN stats
// ---------------------------------------------------------------------------
__global__ void zero_stats_kernel() {
    if (threadIdx.x < Bn*GROUPS*2) g_stats[threadIdx.x] = 0.0;
}

__global__ void __launch_bounds__(256) gn_reduce_kernel(const float* __restrict__ h)
{
    const int bc = blockIdx.x;          // 0..95
    const int slice = blockIdx.y;       // 0..7
    const float4* p = (const float4*)(h + (size_t)bc*HW) + slice*6400 + threadIdx.x;

    float s0=0.f,s1=0.f,s2=0.f,s3=0.f;
    float q0=0.f,q1=0.f,q2=0.f,q3=0.f;
#pragma unroll
    for (int k = 0; k < 25; k++) {
        float4 f = p[k*256];
        s0 += f.x; s1 += f.y; s2 += f.z; s3 += f.w;
        q0 += f.x*f.x; q1 += f.y*f.y; q2 += f.z*f.z; q3 += f.w*f.w;
    }
    double s = ((double)s0 + s1) + ((double)s2 + s3);
    double q = ((double)q0 + q1) + ((double)q2 + q3);
#pragma unroll
    for (int o = 16; o > 0; o >>= 1) {
        s += __shfl_down_sync(0xFFFFFFFFu, s, o);
        q += __shfl_down_sync(0xFFFFFFFFu, q, o);
    }
    __shared__ double ss[8], qq[8];
    if ((threadIdx.x & 31) == 0) { ss[threadIdx.x>>5] = s; qq[threadIdx.x>>5] = q; }
    __syncthreads();
    if (threadIdx.x == 0) {
        double S = 0.0, Q = 0.0;
#pragma unroll
        for (int w = 0; w < 8; w++) { S += ss[w]; Q += qq[w]; }
        const int b = bc / HIDDEN, c = bc % HIDDEN, g = c / CPG;
        atomicAdd(&g_stats[(b*GROUPS+g)*2+0], S);
        atomicAdd(&g_stats[(b*GROUPS+g)*2+1], Q);
    }
}

__global__ void finalize_stats_kernel(const float* __restrict__ gamma,
                                      const float* __restrict__ beta)
{
    const int i = threadIdx.x;           // 0..95
    if (i >= Bn*HIDDEN) return;
    const int b = i / HIDDEN, c = i % HIDDEN, g = c / CPG;
    double s = g_stats[(b*GROUPS+g)*2+0];
    double q = g_stats[(b*GROUPS+g)*2+1];
    double mean = s / (double)GN_N;
    double var  = q / (double)GN_N - mean*mean;
    float inv = (float)rsqrt(var + 1e-5);
    float sc = gamma[c]*inv;
    g_scale[i] = sc;
    g_shift[i] = beta[c] - (float)mean*sc;
}

// ---------------------------------------------------------------------------
// Kernel 3: fused GN3+SiLU + five 1x1 heads + epilogues.
// ---------------------------------------------------------------------------
__global__ void __launch_bounds__(256) heads_kernel(
    const float* __restrict__ h,
    const float* __restrict__ dm, const float* __restrict__ sxp,
    const float* __restrict__ syp, const float* __restrict__ feat,
    const float* __restrict__ conf,
    const float* __restrict__ hd_w,  const float* __restrict__ hd_b,
    const float* __restrict__ hsx_w, const float* __restrict__ hsx_b,
    const float* __restrict__ hsy_w, const float* __restrict__ hsy_b,
    const float* __restrict__ hc_w,  const float* __restrict__ hc_b,
    const float* __restrict__ hf_w,  const float* __restrict__ hf_b,
    float* __restrict__ out)
{
    __shared__ float wsmT[HIDDEN*20];   // transposed: [c][o], rows 80B (16B aligned)
    __shared__ float bia[20];
    __shared__ float sc[HIDDEN], sh[HIDDEN];

    const int tid = threadIdx.x;
    const int b   = blockIdx.y;

    for (int idx = tid; idx < 20*HIDDEN; idx += 256) {
        int c = idx / 20, o = idx % 20;
        float w;
        if (o == 0)      w = hd_w[c];
        else if (o == 1) w = hsx_w[c];
        else if (o == 2) w = hsy_w[c];
        else if (o == 3) w = hc_w[c];
        else             w = hf_w[(o-4)*HIDDEN + c];
        wsmT[idx] = w;
    }
    if (tid < 20) {
        bia[tid] = (tid==0) ? hd_b[0] : (tid==1) ? hsx_b[0] : (tid==2) ? hsy_b[0]
                 : (tid==3) ? hc_b[0] : hf_b[tid-4];
    }
    if (tid < HIDDEN) {
        sc[tid] = g_scale[b*HIDDEN + tid];
        sh[tid] = g_shift[b*HIDDEN + tid];
    }
    __syncthreads();

    const int rem = blockIdx.x*256 + tid;
    const float* hp = h + (size_t)b*HIDDEN*HW + rem;

    float acc[20];
#pragma unroll
    for (int o = 0; o < 20; o++) acc[o] = 0.f;
#pragma unroll 4
    for (int c = 0; c < HIDDEN; c++) {
        float z = hp[(size_t)c*HW]*sc[c] + sh[c];
        float a = z / (1.f + expf(-z));
        const float4* w4 = (const float4*)&wsmT[c*20];
#pragma unroll
        for (int q = 0; q < 5; q++) {
            float4 w = w4[q];
            acc[4*q+0] += w.x*a;
            acc[4*q+1] += w.y*a;
            acc[4*q+2] += w.z*a;
            acc[4*q+3] += w.w*a;
        }
    }

    const int p = b*HW + rem;
    float t = acc[0] + bia[0] + dm[p];
    out[p] = fmaxf(t, 0.f) + log1pf(expf(-fabsf(t)));
    out[BHW   + p] = sxp[p] + (acc[1] + bia[1])*0.1f;
    out[2*BHW + p] = syp[p] + (acc[2] + bia[2])*0.1f;
#pragma unroll
    for (int j = 0; j < TFn; j++) {
        size_t fi = ((size_t)b*TFn + j)*HW + rem;
        out[3*(size_t)BHW + fi] = feat[fi] + acc[4+j] + bia[4+j];
    }
    float cz = acc[3] + bia[3] + 2.f*conf[p] - 1.f;
    out[19*(size_t)BHW + p] = 1.f / (1.f + expf(-cz));
}

// ---------------------------------------------------------------------------
extern "C" void kernel_launch(void* const* d_in, const int* in_sizes, int n_in,
                              void* d_out, int out_size)
{
    const float* dm   = (const float*)d_in[0];
    const float* sx   = (const float*)d_in[1];
    const float* sy   = (const float*)d_in[2];
    const float* feat = (const float*)d_in[3];
    const float* conf = (const float*)d_in[4];
    const float* fL   = (const float*)d_in[5];
    const float* fR   = (const float*)d_in[6];
    const float* w1   = (const float*)d_in[7];
    const float* w2   = (const float*)d_in[8];
    const float* w3   = (const float*)d_in[9];
    const float* g1g  = (const float*)d_in[10];
    const float* g1b  = (const float*)d_in[11];
    const float* g2g  = (const float*)d_in[12];
    const float* g2b  = (const float*)d_in[13];
    const float* g3g  = (const float*)d_in[14];
    const float* g3b  = (const float*)d_in[15];
    const float* hd_w  = (const float*)d_in[16];
    const float* hd_b  = (const float*)d_in[17];
    const float* hsx_w = (const float*)d_in[18];
    const float* hsx_b = (const float*)d_in[19];
    const float* hsy_w = (const float*)d_in[20];
    const float* hsy_b = (const float*)d_in[21];
    const float* hc_w  = (const float*)d_in[22];
    const float* hc_b  = (const float*)d_in[23];
    const float* hf_w  = (const float*)d_in[24];
    const float* hf_b  = (const float*)d_in[25];
    float* out = (float*)d_out;

    float *px, *ph1, *ph2;
    cudaGetSymbolAddress((void**)&px,  g_x);
    cudaGetSymbolAddress((void**)&ph1, g_h1);
    cudaGetSymbolAddress((void**)&ph2, g_h2);

    const dim3 cgrid(Wn/64, Hn/8, Bn);   // (10, 40, 2)
    const dim3 rgrid(Bn*HIDDEN, 8);      // (96, 8)
    const dim3 hgrid(HW/256, Bn);        // (800, 2)

    build_x_kernel<<<Bn*Hn, Wn>>>(dm, sx, sy, feat, conf, fL, fR);

    conv3x3_v2<IN_CH, false><<<cgrid, 256>>>(px, w1, ph1, 0);
    zero_stats_kernel<<<1, 64>>>();
    gn_reduce_kernel<<<rgrid, 256>>>(ph1);
    finalize_stats_kernel<<<1, 96>>>(g1g, g1b);

    conv3x3_v2<HIDDEN, true><<<cgrid, 256>>>(ph1, w2, ph2, 0);
    zero_stats_kernel<<<1, 64>>>();
    gn_reduce_kernel<<<rgrid, 256>>>(ph2);
    finalize_stats_kernel<<<1, 96>>>(g2g, g2b);

    conv3x3_v2<HIDDEN, true><<<cgrid, 256>>>(ph2, w3, ph1, 0);
    zero_stats_kernel<<<1, 64>>>();
    gn_reduce_kernel<<<rgrid, 256>>>(ph1);
    finalize_stats_kernel<<<1, 96>>>(g3g, g3b);

    heads_kernel<<<hgrid, 256>>>(ph1,
                                 dm, sx, sy, feat, conf,
                                 hd_w, hd_b, hsx_w, hsx_b, hsy_w, hsy_b,
                                 hc_w, hc_b, hf_w, hf_b, out);
}

// round 3
// speedup vs baseline: 1.1802x; 1.0417x over previous
#include <cuda_runtime.h>
#include <math.h>
#include <stdint.h>

#define Bn 2
#define Cn 64
#define Hn 320
#define Wn 640
#define TFn 16
#define HIDDEN 48
#define GROUPS 8
#define CPG 6
#define IN_CH 188
#define HW (Hn*Wn)
#define GN_N (CPG*HW)
#define BHW (Bn*HW)

// ---------------- scratch ----------------
__device__ float  g_x [Bn*IN_CH*HW];
__device__ float  g_h1[Bn*HIDDEN*HW];
__device__ float  g_h2[Bn*HIDDEN*HW];
__device__ double g_stats[Bn*GROUPS*2];
__device__ float  g_scale[Bn*HIDDEN];
__device__ float  g_shift[Bn*HIDDEN];

// ---------------------------------------------------------------------------
// Kernel 1: build x = concat(fL, warp(fR,d), feat, d, sx, sy, conf, corr)
// ---------------------------------------------------------------------------
__global__ void __launch_bounds__(Wn) build_x_kernel(
    const float* __restrict__ dm, const float* __restrict__ sx,
    const float* __restrict__ sy, const float* __restrict__ feat,
    const float* __restrict__ conf, const float* __restrict__ fL,
    const float* __restrict__ fR)
{
    __shared__ float srow[8*Wn];
    const int b = blockIdx.x / Hn;
    const int y = blockIdx.x % Hn;
    const int x = threadIdx.x;
    const int prow = b*HW + y*Wn;

    const float dval = dm[prow + x];
    int i0[5], i1[5]; float fr[5];
#pragma unroll
    for (int i = 0; i < 5; i++) {
        float xs = (float)x - dval - (float)(i-2);
        xs = fminf(fmaxf(xs, 0.f), (float)(Wn-1));
        float f0 = floorf(xs);
        i0[i] = (int)f0;
        fr[i] = xs - f0;
        i1[i] = min(i0[i]+1, Wn-1);
    }

    float* xb = g_x + (size_t)b*IN_CH*HW + (size_t)y*Wn + x;
    const float* fLp = fL + (size_t)b*Cn*HW + (size_t)y*Wn + x;
    const float* fRp = fR + (size_t)b*Cn*HW + (size_t)y*Wn;

    for (int g = 0; g < 8; g++) {
        __syncthreads();
#pragma unroll
        for (int j = 0; j < 8; j++)
            srow[j*Wn + x] = fRp[(size_t)(g*8+j)*HW + x];
        __syncthreads();

        float acc[5] = {0.f,0.f,0.f,0.f,0.f};
#pragma unroll
        for (int j = 0; j < 8; j++) {
            const int c = g*8 + j;
            const float fl = fLp[(size_t)c*HW];
            xb[(size_t)c*HW] = fl;
#pragma unroll
            for (int i = 0; i < 5; i++) {
                float v = srow[j*Wn+i0[i]]*(1.f-fr[i]) + srow[j*Wn+i1[i]]*fr[i];
                acc[i] += fl*v;
                if (i == 2) xb[(size_t)(64+c)*HW] = v;
            }
        }
#pragma unroll
        for (int i = 0; i < 5; i++)
            xb[(size_t)(148 + g*5 + i)*HW] = acc[i]*(1.f/8.f);
    }
#pragma unroll
    for (int j = 0; j < TFn; j++)
        xb[(size_t)(128+j)*HW] = feat[((size_t)b*TFn + j)*HW + y*Wn + x];
    xb[(size_t)144*HW] = dval;
    xb[(size_t)145*HW] = sx[prow + x];
    xb[(size_t)146*HW] = sy[prow + x];
    xb[(size_t)147*HW] = conf[prow + x];
}

// ---------------------------------------------------------------------------
// Kernel 2 v2: 3x3 conv, 64x8 tile, 2 adjacent px/thread, double-buffered smem,
// one __syncthreads per input channel. Optional fused GN+SiLU on input load.
// ---------------------------------------------------------------------------
template<int IN, bool HASGN>
__global__ void __launch_bounds__(256) conv3x3_v2(
    const float* __restrict__ in, const float* __restrict__ wgt,
    float* __restrict__ out, int b_scsh)
{
    __shared__ float ts[2][10*68];     // tile: 10 rows x 66 cols (pad to 68)
    __shared__ float ws[2][48*12];     // weights: 48 outs x 9 (pad to 12)

    const int tid = threadIdx.x;
    const int tx = tid & 31, ty = tid >> 5;
    const int x0 = blockIdx.x*64, y0 = blockIdx.y*8;
    const int b  = blockIdx.z;

    const float* inb = in + (size_t)b*IN*HW;
    const float* scb = g_scale + (b + b_scsh*0)*HIDDEN;   // only used if HASGN
    const float* shb = g_shift + b*HIDDEN;

    // precompute tile-load slots (3 per thread)
    int   toff[3], soff[3];
    bool  timg[3], tin[3];
#pragma unroll
    for (int j = 0; j < 3; j++) {
        int idx = tid + j*256;
        int r = idx/66, c = idx%66;
        int gy = y0-1+r, gx = x0-1+c;
        tin[j]  = (idx < 660);
        timg[j] = tin[j] && gy >= 0 && gy < Hn && gx >= 0 && gx < Wn;
        toff[j] = timg[j] ? gy*Wn + gx : 0;
        soff[j] = r*68 + c;
    }
    // weight-load slots (2 per thread)
    int wo[2], wk[2]; bool win[2];
#pragma unroll
    for (int j = 0; j < 2; j++) {
        int idx = tid + j*256;
        win[j] = (idx < 432);
        wo[j] = idx/9; wk[j] = idx%9;
        if (!win[j]) { wo[j] = 0; wk[j] = 0; }
    }

    float acc0[48], acc1[48];
#pragma unroll
    for (int o = 0; o < 48; o++) { acc0[o] = 0.f; acc1[o] = 0.f; }

    // prologue: load channel 0 into buffer 0
    {
        float sc = 1.f, sh = 0.f;
        if (HASGN) { sc = scb[0]; sh = shb[0]; }
#pragma unroll
        for (int j = 0; j < 3; j++) {
            if (tin[j]) {
                float v = 0.f;
                if (timg[j]) {
                    v = inb[toff[j]];
                    if (HASGN) { float z = v*sc + sh; v = z / (1.f + expf(-z)); }
                }
                ts[0][soff[j]] = v;
            }
        }
#pragma unroll
        for (int j = 0; j < 2; j++)
            if (win[j]) ws[0][wo[j]*12 + wk[j]] = wgt[((size_t)wo[j]*IN + 0)*9 + wk[j]];
    }
    __syncthreads();

    int cur = 0;
#pragma unroll 1
    for (int ci = 0; ci < IN; ci++) {
        // ---- issue LDGs for next channel into registers ----
        float tv[3] = {0.f,0.f,0.f};
        float wv[2] = {0.f,0.f};
        float sc = 1.f, sh = 0.f;
        const bool more = (ci + 1 < IN);
        if (more) {
            const float* ip = inb + (size_t)(ci+1)*HW;
#pragma unroll
            for (int j = 0; j < 3; j++)
                if (timg[j]) tv[j] = ip[toff[j]];
#pragma unroll
            for (int j = 0; j < 2; j++)
                if (win[j]) wv[j] = wgt[((size_t)wo[j]*IN + (ci+1))*9 + wk[j]];
            if (HASGN) { sc = scb[ci+1]; sh = shb[ci+1]; }
        }

        // ---- compute current channel ----
        float v00,v01,v02,v03, v10,v11,v12,v13, v20,v21,v22,v23;
        {
            const float* base = &ts[cur][ty*68 + 2*tx];
            float2 a0 = *(const float2*)(base + 0);
            float2 a1 = *(const float2*)(base + 2);
            float2 b0 = *(const float2*)(base + 68);
            float2 b1 = *(const float2*)(base + 70);
            float2 c0 = *(const float2*)(base + 136);
            float2 c1 = *(const float2*)(base + 138);
            v00=a0.x; v01=a0.y; v02=a1.x; v03=a1.y;
            v10=b0.x; v11=b0.y; v12=b1.x; v13=b1.y;
            v20=c0.x; v21=c0.y; v22=c1.x; v23=c1.y;
        }
        const float4* w4 = (const float4*)ws[cur];
#pragma unroll
        for (int o = 0; o < 48; o++) {
            float4 q0 = w4[o*3+0];
            float4 q1 = w4[o*3+1];
            float4 q2 = w4[o*3+2];
            acc0[o] += q0.x*v00 + q0.y*v01 + q0.z*v02
                     + q0.w*v10 + q1.x*v11 + q1.y*v12
                     + q1.z*v20 + q1.w*v21 + q2.x*v22;
            acc1[o] += q0.x*v01 + q0.y*v02 + q0.z*v03
                     + q0.w*v11 + q1.x*v12 + q1.y*v13
                     + q1.z*v21 + q1.w*v22 + q2.x*v23;
        }

        // ---- store next channel into other buffer ----
        if (more) {
            const int nb = cur ^ 1;
#pragma unroll
            for (int j = 0; j < 3; j++) {
                if (tin[j]) {
                    float v = tv[j];
                    if (HASGN && timg[j]) { float z = v*sc + sh; v = z / (1.f + expf(-z)); }
                    ts[nb][soff[j]] = v;
                }
            }
#pragma unroll
            for (int j = 0; j < 2; j++)
                if (win[j]) ws[nb][wo[j]*12 + wk[j]] = wv[j];
        }
        __syncthreads();
        cur ^= 1;
    }

    float* op = out + (size_t)b*HIDDEN*HW + (size_t)(y0+ty)*Wn + (x0 + 2*tx);
#pragma unroll
    for (int o = 0; o < 48; o++)
        *(float2*)&op[(size_t)o*HW] = make_float2(acc0[o], acc1[o]);
}

// ---------------------------------------------------------------------------
// GN stats
// ---------------------------------------------------------------------------
__global__ void zero_stats_kernel() {
    if (threadIdx.x < Bn*GROUPS*2) g_stats[threadIdx.x] = 0.0;
}

__global__ void __launch_bounds__(256) gn_reduce_kernel(const float* __restrict__ h)
{
    const int bc = blockIdx.x;          // 0..95
    const int slice = blockIdx.y;       // 0..7
    const float4* p = (const float4*)(h + (size_t)bc*HW) + slice*6400 + threadIdx.x;

    float s0=0.f,s1=0.f,s2=0.f,s3=0.f;
    float q0=0.f,q1=0.f,q2=0.f,q3=0.f;
#pragma unroll
    for (int k = 0; k < 25; k++) {
        float4 f = p[k*256];
        s0 += f.x; s1 += f.y; s2 += f.z; s3 += f.w;
        q0 += f.x*f.x; q1 += f.y*f.y; q2 += f.z*f.z; q3 += f.w*f.w;
    }
    double s = ((double)s0 + s1) + ((double)s2 + s3);
    double q = ((double)q0 + q1) + ((double)q2 + q3);
#pragma unroll
    for (int o = 16; o > 0; o >>= 1) {
        s += __shfl_down_sync(0xFFFFFFFFu, s, o);
        q += __shfl_down_sync(0xFFFFFFFFu, q, o);
    }
    __shared__ double ss[8], qq[8];
    if ((threadIdx.x & 31) == 0) { ss[threadIdx.x>>5] = s; qq[threadIdx.x>>5] = q; }
    __syncthreads();
    if (threadIdx.x == 0) {
        double S = 0.0, Q = 0.0;
#pragma unroll
        for (int w = 0; w < 8; w++) { S += ss[w]; Q += qq[w]; }
        const int b = bc / HIDDEN, c = bc % HIDDEN, g = c / CPG;
        atomicAdd(&g_stats[(b*GROUPS+g)*2+0], S);
        atomicAdd(&g_stats[(b*GROUPS+g)*2+1], Q);
    }
}

__global__ void finalize_stats_kernel(const float* __restrict__ gamma,
                                      const float* __restrict__ beta)
{
    const int i = threadIdx.x;           // 0..95
    if (i >= Bn*HIDDEN) return;
    const int b = i / HIDDEN, c = i % HIDDEN, g = c / CPG;
    double s = g_stats[(b*GROUPS+g)*2+0];
    double q = g_stats[(b*GROUPS+g)*2+1];
    double mean = s / (double)GN_N;
    double var  = q / (double)GN_N - mean*mean;
    float inv = (float)rsqrt(var + 1e-5);
    float sc = gamma[c]*inv;
    g_scale[i] = sc;
    g_shift[i] = beta[c] - (float)mean*sc;
}

// ---------------------------------------------------------------------------
// Kernel 3: fused GN3+SiLU + five 1x1 heads + epilogues.
// ---------------------------------------------------------------------------
__global__ void __launch_bounds__(256) heads_kernel(
    const float* __restrict__ h,
    const float* __restrict__ dm, const float* __restrict__ sxp,
    const float* __restrict__ syp, const float* __restrict__ feat,
    const float* __restrict__ conf,
    const float* __restrict__ hd_w,  const float* __restrict__ hd_b,
    const float* __restrict__ hsx_w, const float* __restrict__ hsx_b,
    const float* __restrict__ hsy_w, const float* __restrict__ hsy_b,
    const float* __restrict__ hc_w,  const float* __restrict__ hc_b,
    const float* __restrict__ hf_w,  const float* __restrict__ hf_b,
    float* __restrict__ out)
{
    __shared__ float wsmT[HIDDEN*20];   // transposed: [c][o], rows 80B (16B aligned)
    __shared__ float bia[20];
    __shared__ float sc[HIDDEN], sh[HIDDEN];

    const int tid = threadIdx.x;
    const int b   = blockIdx.y;

    for (int idx = tid; idx < 20*HIDDEN; idx += 256) {
        int c = idx / 20, o = idx % 20;
        float w;
        if (o == 0)      w = hd_w[c];
        else if (o == 1) w = hsx_w[c];
        else if (o == 2) w = hsy_w[c];
        else if (o == 3) w = hc_w[c];
        else             w = hf_w[(o-4)*HIDDEN + c];
        wsmT[idx] = w;
    }
    if (tid < 20) {
        bia[tid] = (tid==0) ? hd_b[0] : (tid==1) ? hsx_b[0] : (tid==2) ? hsy_b[0]
                 : (tid==3) ? hc_b[0] : hf_b[tid-4];
    }
    if (tid < HIDDEN) {
        sc[tid] = g_scale[b*HIDDEN + tid];
        sh[tid] = g_shift[b*HIDDEN + tid];
    }
    __syncthreads();

    const int rem = blockIdx.x*256 + tid;
    const float* hp = h + (size_t)b*HIDDEN*HW + rem;

    float acc[20];
#pragma unroll
    for (int o = 0; o < 20; o++) acc[o] = 0.f;
#pragma unroll 4
    for (int c = 0; c < HIDDEN; c++) {
        float z = hp[(size_t)c*HW]*sc[c] + sh[c];
        float a = z / (1.f + expf(-z));
        const float4* w4 = (const float4*)&wsmT[c*20];
#pragma unroll
        for (int q = 0; q < 5; q++) {
            float4 w = w4[q];
            acc[4*q+0] += w.x*a;
            acc[4*q+1] += w.y*a;
            acc[4*q+2] += w.z*a;
            acc[4*q+3] += w.w*a;
        }
    }

    const int p = b*HW + rem;
    float t = acc[0] + bia[0] + dm[p];
    out[p] = fmaxf(t, 0.f) + log1pf(expf(-fabsf(t)));
    out[BHW   + p] = sxp[p] + (acc[1] + bia[1])*0.1f;
    out[2*BHW + p] = syp[p] + (acc[2] + bia[2])*0.1f;
#pragma unroll
    for (int j = 0; j < TFn; j++) {
        size_t fi = ((size_t)b*TFn + j)*HW + rem;
        out[3*(size_t)BHW + fi] = feat[fi] + acc[4+j] + bia[4+j];
    }
    float cz = acc[3] + bia[3] + 2.f*conf[p] - 1.f;
    out[19*(size_t)BHW + p] = 1.f / (1.f + expf(-cz));
}

// ---------------------------------------------------------------------------
extern "C" void kernel_launch(void* const* d_in, const int* in_sizes, int n_in,
                              void* d_out, int out_size)
{
    const float* dm   = (const float*)d_in[0];
    const float* sx   = (const float*)d_in[1];
    const float* sy   = (const float*)d_in[2];
    const float* feat = (const float*)d_in[3];
    const float* conf = (const float*)d_in[4];
    const float* fL   = (const float*)d_in[5];
    const float* fR   = (const float*)d_in[6];
    const float* w1   = (const float*)d_in[7];
    const float* w2   = (const float*)d_in[8];
    const float* w3   = (const float*)d_in[9];
    const float* g1g  = (const float*)d_in[10];
    const float* g1b  = (const float*)d_in[11];
    const float* g2g  = (const float*)d_in[12];
    const float* g2b  = (const float*)d_in[13];
    const float* g3g  = (const float*)d_in[14];
    const float* g3b  = (const float*)d_in[15];
    const float* hd_w  = (const float*)d_in[16];
    const float* hd_b  = (const float*)d_in[17];
    const float* hsx_w = (const float*)d_in[18];
    const float* hsx_b = (const float*)d_in[19];
    const float* hsy_w = (const float*)d_in[20];
    const float* hsy_b = (const float*)d_in[21];
    const float* hc_w  = (const float*)d_in[22];
    const float* hc_b  = (const float*)d_in[23];
    const float* hf_w  = (const float*)d_in[24];
    const float* hf_b  = (const float*)d_in[25];
    float* out = (float*)d_out;

    float *px, *ph1, *ph2;
    cudaGetSymbolAddress((void**)&px,  g_x);
    cudaGetSymbolAddress((void**)&ph1, g_h1);
    cudaGetSymbolAddress((void**)&ph2, g_h2);

    const dim3 cgrid(Wn/64, Hn/8, Bn);   // (10, 40, 2)
    const dim3 rgrid(Bn*HIDDEN, 8);      // (96, 8)
    const dim3 hgrid(HW/256, Bn);        // (800, 2)

    build_x_kernel<<<Bn*Hn, Wn>>>(dm, sx, sy, feat, conf, fL, fR);

    conv3x3_v2<IN_CH, false><<<cgrid, 256>>>(px, w1, ph1, 0);
    zero_stats_kernel<<<1, 64>>>();
    gn_reduce_kernel<<<rgrid, 256>>>(ph1);
    finalize_stats_kernel<<<1, 96>>>(g1g, g1b);

    conv3x3_v2<HIDDEN, true><<<cgrid, 256>>>(ph1, w2, ph2, 0);
    zero_stats_kernel<<<1, 64>>>();
    gn_reduce_kernel<<<rgrid, 256>>>(ph2);
    finalize_stats_kernel<<<1, 96>>>(g2g, g2b);

    conv3x3_v2<HIDDEN, true><<<cgrid, 256>>>(ph2, w3, ph1, 0);
    zero_stats_kernel<<<1, 64>>>();
    gn_reduce_kernel<<<rgrid, 256>>>(ph1);
    finalize_stats_kernel<<<1, 96>>>(g3g, g3b);

    heads_kernel<<<hgrid, 256>>>(ph1,
                                 dm, sx, sy, feat, conf,
                                 hd_w, hd_b, hsx_w, hsx_b, hsy_w, hsy_b,
                                 hc_w, hc_b, hf_w, hf_b, out);
}

// round 4
// speedup vs baseline: 1.1859x; 1.0049x over previous
#include <cuda_runtime.h>
#include <math.h>
#include <stdint.h>

#define Bn 2
#define Cn 64
#define Hn 320
#define Wn 640
#define TFn 16
#define HIDDEN 48
#define GROUPS 8
#define CPG 6
#define IN_CH 188
#define HW (Hn*Wn)
#define GN_N (CPG*HW)
#define BHW (Bn*HW)

// ---------------- scratch ----------------
__device__ float  g_x [Bn*IN_CH*HW];
__device__ float  g_h1[Bn*HIDDEN*HW];
__device__ float  g_h2[Bn*HIDDEN*HW];
__device__ double g_stats[Bn*GROUPS*2];
__device__ float  g_scale[Bn*HIDDEN];
__device__ float  g_shift[Bn*HIDDEN];

// ---------------------------------------------------------------------------
// Kernel 1: build x = concat(fL, warp(fR,d), feat, d, sx, sy, conf, corr)
// ---------------------------------------------------------------------------
__global__ void __launch_bounds__(Wn) build_x_kernel(
    const float* __restrict__ dm, const float* __restrict__ sx,
    const float* __restrict__ sy, const float* __restrict__ feat,
    const float* __restrict__ conf, const float* __restrict__ fL,
    const float* __restrict__ fR)
{
    __shared__ float srow[8*Wn];
    const int b = blockIdx.x / Hn;
    const int y = blockIdx.x % Hn;
    const int x = threadIdx.x;
    const int prow = b*HW + y*Wn;

    const float dval = dm[prow + x];
    int i0[5], i1[5]; float fr[5];
#pragma unroll
    for (int i = 0; i < 5; i++) {
        float xs = (float)x - dval - (float)(i-2);
        xs = fminf(fmaxf(xs, 0.f), (float)(Wn-1));
        float f0 = floorf(xs);
        i0[i] = (int)f0;
        fr[i] = xs - f0;
        i1[i] = min(i0[i]+1, Wn-1);
    }

    float* xb = g_x + (size_t)b*IN_CH*HW + (size_t)y*Wn + x;
    const float* fLp = fL + (size_t)b*Cn*HW + (size_t)y*Wn + x;
    const float* fRp = fR + (size_t)b*Cn*HW + (size_t)y*Wn;

    for (int g = 0; g < 8; g++) {
        __syncthreads();
#pragma unroll
        for (int j = 0; j < 8; j++)
            srow[j*Wn + x] = fRp[(size_t)(g*8+j)*HW + x];
        __syncthreads();

        float acc[5] = {0.f,0.f,0.f,0.f,0.f};
#pragma unroll
        for (int j = 0; j < 8; j++) {
            const int c = g*8 + j;
            const float fl = fLp[(size_t)c*HW];
            xb[(size_t)c*HW] = fl;
#pragma unroll
            for (int i = 0; i < 5; i++) {
                float v = srow[j*Wn+i0[i]]*(1.f-fr[i]) + srow[j*Wn+i1[i]]*fr[i];
                acc[i] += fl*v;
                if (i == 2) xb[(size_t)(64+c)*HW] = v;
            }
        }
#pragma unroll
        for (int i = 0; i < 5; i++)
            xb[(size_t)(148 + g*5 + i)*HW] = acc[i]*(1.f/8.f);
    }
#pragma unroll
    for (int j = 0; j < TFn; j++)
        xb[(size_t)(128+j)*HW] = feat[((size_t)b*TFn + j)*HW + y*Wn + x];
    xb[(size_t)144*HW] = dval;
    xb[(size_t)145*HW] = sx[prow + x];
    xb[(size_t)146*HW] = sy[prow + x];
    xb[(size_t)147*HW] = conf[prow + x];
}

// ---------------------------------------------------------------------------
// Kernel 2 v2: 3x3 conv, 64x8 tile, 2 adjacent px/thread, double-buffered smem,
// one __syncthreads per input channel. Optional fused GN+SiLU on input load.
// ---------------------------------------------------------------------------
template<int IN, bool HASGN>
__global__ void __launch_bounds__(256) conv3x3_v2(
    const float* __restrict__ in, const float* __restrict__ wgt,
    float* __restrict__ out, int b_scsh)
{
    __shared__ float ts[2][10*68];     // tile: 10 rows x 66 cols (pad to 68)
    __shared__ float ws[2][48*12];     // weights: 48 outs x 9 (pad to 12)

    const int tid = threadIdx.x;
    const int tx = tid & 31, ty = tid >> 5;
    const int x0 = blockIdx.x*64, y0 = blockIdx.y*8;
    const int b  = blockIdx.z;

    const float* inb = in + (size_t)b*IN*HW;
    const float* scb = g_scale + (b + b_scsh*0)*HIDDEN;   // only used if HASGN
    const float* shb = g_shift + b*HIDDEN;

    // precompute tile-load slots (3 per thread)
    int   toff[3], soff[3];
    bool  timg[3], tin[3];
#pragma unroll
    for (int j = 0; j < 3; j++) {
        int idx = tid + j*256;
        int r = idx/66, c = idx%66;
        int gy = y0-1+r, gx = x0-1+c;
        tin[j]  = (idx < 660);
        timg[j] = tin[j] && gy >= 0 && gy < Hn && gx >= 0 && gx < Wn;
        toff[j] = timg[j] ? gy*Wn + gx : 0;
        soff[j] = r*68 + c;
    }
    // weight-load slots (2 per thread)
    int wo[2], wk[2]; bool win[2];
#pragma unroll
    for (int j = 0; j < 2; j++) {
        int idx = tid + j*256;
        win[j] = (idx < 432);
        wo[j] = idx/9; wk[j] = idx%9;
        if (!win[j]) { wo[j] = 0; wk[j] = 0; }
    }

    float acc0[48], acc1[48];
#pragma unroll
    for (int o = 0; o < 48; o++) { acc0[o] = 0.f; acc1[o] = 0.f; }

    // prologue: load channel 0 into buffer 0
    {
        float sc = 1.f, sh = 0.f;
        if (HASGN) { sc = scb[0]; sh = shb[0]; }
#pragma unroll
        for (int j = 0; j < 3; j++) {
            if (tin[j]) {
                float v = 0.f;
                if (timg[j]) {
                    v = inb[toff[j]];
                    if (HASGN) { float z = v*sc + sh; v = z / (1.f + expf(-z)); }
                }
                ts[0][soff[j]] = v;
            }
        }
#pragma unroll
        for (int j = 0; j < 2; j++)
            if (win[j]) ws[0][wo[j]*12 + wk[j]] = wgt[((size_t)wo[j]*IN + 0)*9 + wk[j]];
    }
    __syncthreads();

    int cur = 0;
#pragma unroll 1
    for (int ci = 0; ci < IN; ci++) {
        // ---- issue LDGs for next channel into registers ----
        float tv[3] = {0.f,0.f,0.f};
        float wv[2] = {0.f,0.f};
        float sc = 1.f, sh = 0.f;
        const bool more = (ci + 1 < IN);
        if (more) {
            const float* ip = inb + (size_t)(ci+1)*HW;
#pragma unroll
            for (int j = 0; j < 3; j++)
                if (timg[j]) tv[j] = ip[toff[j]];
#pragma unroll
            for (int j = 0; j < 2; j++)
                if (win[j]) wv[j] = wgt[((size_t)wo[j]*IN + (ci+1))*9 + wk[j]];
            if (HASGN) { sc = scb[ci+1]; sh = shb[ci+1]; }
        }

        // ---- compute current channel ----
        float v00,v01,v02,v03, v10,v11,v12,v13, v20,v21,v22,v23;
        {
            const float* base = &ts[cur][ty*68 + 2*tx];
            float2 a0 = *(const float2*)(base + 0);
            float2 a1 = *(const float2*)(base + 2);
            float2 b0 = *(const float2*)(base + 68);
            float2 b1 = *(const float2*)(base + 70);
            float2 c0 = *(const float2*)(base + 136);
            float2 c1 = *(const float2*)(base + 138);
            v00=a0.x; v01=a0.y; v02=a1.x; v03=a1.y;
            v10=b0.x; v11=b0.y; v12=b1.x; v13=b1.y;
            v20=c0.x; v21=c0.y; v22=c1.x; v23=c1.y;
        }
        const float4* w4 = (const float4*)ws[cur];
#pragma unroll
        for (int o = 0; o < 48; o++) {
            float4 q0 = w4[o*3+0];
            float4 q1 = w4[o*3+1];
            float4 q2 = w4[o*3+2];
            acc0[o] += q0.x*v00 + q0.y*v01 + q0.z*v02
                     + q0.w*v10 + q1.x*v11 + q1.y*v12
                     + q1.z*v20 + q1.w*v21 + q2.x*v22;
            acc1[o] += q0.x*v01 + q0.y*v02 + q0.z*v03
                     + q0.w*v11 + q1.x*v12 + q1.y*v13
                     + q1.z*v21 + q1.w*v22 + q2.x*v23;
        }

        // ---- store next channel into other buffer ----
        if (more) {
            const int nb = cur ^ 1;
#pragma unroll
            for (int j = 0; j < 3; j++) {
                if (tin[j]) {
                    float v = tv[j];
                    if (HASGN && timg[j]) { float z = v*sc + sh; v = z / (1.f + expf(-z)); }
                    ts[nb][soff[j]] = v;
                }
            }
#pragma unroll
            for (int j = 0; j < 2; j++)
                if (win[j]) ws[nb][wo[j]*12 + wk[j]] = wv[j];
        }
        __syncthreads();
        cur ^= 1;
    }

    float* op = out + (size_t)b*HIDDEN*HW + (size_t)(y0+ty)*Wn + (x0 + 2*tx);
#pragma unroll
    for (int o = 0; o < 48; o++)
        *(float2*)&op[(size_t)o*HW] = make_float2(acc0[o], acc1[o]);
}

// ---------------------------------------------------------------------------
// GN stats
// ---------------------------------------------------------------------------
__global__ void zero_stats_kernel() {
    if (threadIdx.x < Bn*GROUPS*2) g_stats[threadIdx.x] = 0.0;
}

__global__ void __launch_bounds__(256) gn_reduce_kernel(const float* __restrict__ h)
{
    const int bc = blockIdx.x;          // 0..95
    const int slice = blockIdx.y;       // 0..7
    const float4* p = (const float4*)(h + (size_t)bc*HW) + slice*6400 + threadIdx.x;

    float s0=0.f,s1=0.f,s2=0.f,s3=0.f;
    float q0=0.f,q1=0.f,q2=0.f,q3=0.f;
#pragma unroll
    for (int k = 0; k < 25; k++) {
        float4 f = p[k*256];
        s0 += f.x; s1 += f.y; s2 += f.z; s3 += f.w;
        q0 += f.x*f.x; q1 += f.y*f.y; q2 += f.z*f.z; q3 += f.w*f.w;
    }
    double s = ((double)s0 + s1) + ((double)s2 + s3);
    double q = ((double)q0 + q1) + ((double)q2 + q3);
#pragma unroll
    for (int o = 16; o > 0; o >>= 1) {
        s += __shfl_down_sync(0xFFFFFFFFu, s, o);
        q += __shfl_down_sync(0xFFFFFFFFu, q, o);
    }
    __shared__ double ss[8], qq[8];
    if ((threadIdx.x & 31) == 0) { ss[threadIdx.x>>5] = s; qq[threadIdx.x>>5] = q; }
    __syncthreads();
    if (threadIdx.x == 0) {
        double S = 0.0, Q = 0.0;
#pragma unroll
        for (int w = 0; w < 8; w++) { S += ss[w]; Q += qq[w]; }
        const int b = bc / HIDDEN, c = bc % HIDDEN, g = c / CPG;
        atomicAdd(&g_stats[(b*GROUPS+g)*2+0], S);
        atomicAdd(&g_stats[(b*GROUPS+g)*2+1], Q);
    }
}

__global__ void finalize_stats_kernel(const float* __restrict__ gamma,
                                      const float* __restrict__ beta)
{
    const int i = threadIdx.x;           // 0..95
    if (i >= Bn*HIDDEN) return;
    const int b = i / HIDDEN, c = i % HIDDEN, g = c / CPG;
    double s = g_stats[(b*GROUPS+g)*2+0];
    double q = g_stats[(b*GROUPS+g)*2+1];
    double mean = s / (double)GN_N;
    double var  = q / (double)GN_N - mean*mean;
    float inv = (float)rsqrt(var + 1e-5);
    float sc = gamma[c]*inv;
    g_scale[i] = sc;
    g_shift[i] = beta[c] - (float)mean*sc;
}

// ---------------------------------------------------------------------------
// Kernel 3: fused GN3+SiLU + five 1x1 heads + epilogues.
// ---------------------------------------------------------------------------
__global__ void __launch_bounds__(256) heads_kernel(
    const float* __restrict__ h,
    const float* __restrict__ dm, const float* __restrict__ sxp,
    const float* __restrict__ syp, const float* __restrict__ feat,
    const float* __restrict__ conf,
    const float* __restrict__ hd_w,  const float* __restrict__ hd_b,
    const float* __restrict__ hsx_w, const float* __restrict__ hsx_b,
    const float* __restrict__ hsy_w, const float* __restrict__ hsy_b,
    const float* __restrict__ hc_w,  const float* __restrict__ hc_b,
    const float* __restrict__ hf_w,  const float* __restrict__ hf_b,
    float* __restrict__ out)
{
    __shared__ float wsmT[HIDDEN*20];   // transposed: [c][o], rows 80B (16B aligned)
    __shared__ float bia[20];
    __shared__ float sc[HIDDEN], sh[HIDDEN];

    const int tid = threadIdx.x;
    const int b   = blockIdx.y;

    for (int idx = tid; idx < 20*HIDDEN; idx += 256) {
        int c = idx / 20, o = idx % 20;
        float w;
        if (o == 0)      w = hd_w[c];
        else if (o == 1) w = hsx_w[c];
        else if (o == 2) w = hsy_w[c];
        else if (o == 3) w = hc_w[c];
        else             w = hf_w[(o-4)*HIDDEN + c];
        wsmT[idx] = w;
    }
    if (tid < 20) {
        bia[tid] = (tid==0) ? hd_b[0] : (tid==1) ? hsx_b[0] : (tid==2) ? hsy_b[0]
                 : (tid==3) ? hc_b[0] : hf_b[tid-4];
    }
    if (tid < HIDDEN) {
        sc[tid] = g_scale[b*HIDDEN + tid];
        sh[tid] = g_shift[b*HIDDEN + tid];
    }
    __syncthreads();

    const int rem = blockIdx.x*256 + tid;
    const float* hp = h + (size_t)b*HIDDEN*HW + rem;

    float acc[20];
#pragma unroll
    for (int o = 0; o < 20; o++) acc[o] = 0.f;
#pragma unroll 4
    for (int c = 0; c < HIDDEN; c++) {
        float z = hp[(size_t)c*HW]*sc[c] + sh[c];
        float a = z / (1.f + expf(-z));
        const float4* w4 = (const float4*)&wsmT[c*20];
#pragma unroll
        for (int q = 0; q < 5; q++) {
            float4 w = w4[q];
            acc[4*q+0] += w.x*a;
            acc[4*q+1] += w.y*a;
            acc[4*q+2] += w.z*a;
            acc[4*q+3] += w.w*a;
        }
    }

    const int p = b*HW + rem;
    float t = acc[0] + bia[0] + dm[p];
    out[p] = fmaxf(t, 0.f) + log1pf(expf(-fabsf(t)));
    out[BHW   + p] = sxp[p] + (acc[1] + bia[1])*0.1f;
    out[2*BHW + p] = syp[p] + (acc[2] + bia[2])*0.1f;
#pragma unroll
    for (int j = 0; j < TFn; j++) {
        size_t fi = ((size_t)b*TFn + j)*HW + rem;
        out[3*(size_t)BHW + fi] = feat[fi] + acc[4+j] + bia[4+j];
    }
    float cz = acc[3] + bia[3] + 2.f*conf[p] - 1.f;
    out[19*(size_t)BHW + p] = 1.f / (1.f + expf(-cz));
}

// ---------------------------------------------------------------------------
extern "C" void kernel_launch(void* const* d_in, const int* in_sizes, int n_in,
                              void* d_out, int out_size)
{
    const float* dm   = (const float*)d_in[0];
    const float* sx   = (const float*)d_in[1];
    const float* sy   = (const float*)d_in[2];
    const float* feat = (const float*)d_in[3];
    const float* conf = (const float*)d_in[4];
    const float* fL   = (const float*)d_in[5];
    const float* fR   = (const float*)d_in[6];
    const float* w1   = (const float*)d_in[7];
    const float* w2   = (const float*)d_in[8];
    const float* w3   = (const float*)d_in[9];
    const float* g1g  = (const float*)d_in[10];
    const float* g1b  = (const float*)d_in[11];
    const float* g2g  = (const float*)d_in[12];
    const float* g2b  = (const float*)d_in[13];
    const float* g3g  = (const float*)d_in[14];
    const float* g3b  = (const float*)d_in[15];
    const float* hd_w  = (const float*)d_in[16];
    const float* hd_b  = (const float*)d_in[17];
    const float* hsx_w = (const float*)d_in[18];
    const float* hsx_b = (const float*)d_in[19];
    const float* hsy_w = (const float*)d_in[20];
    const float* hsy_b = (const float*)d_in[21];
    const float* hc_w  = (const float*)d_in[22];
    const float* hc_b  = (const float*)d_in[23];
    const float* hf_w  = (const float*)d_in[24];
    const float* hf_b  = (const float*)d_in[25];
    float* out = (float*)d_out;

    float *px, *ph1, *ph2;
    cudaGetSymbolAddress((void**)&px,  g_x);
    cudaGetSymbolAddress((void**)&ph1, g_h1);
    cudaGetSymbolAddress((void**)&ph2, g_h2);

    const dim3 cgrid(Wn/64, Hn/8, Bn);   // (10, 40, 2)
    const dim3 rgrid(Bn*HIDDEN, 8);      // (96, 8)
    const dim3 hgrid(HW/256, Bn);        // (800, 2)

    build_x_kernel<<<Bn*Hn, Wn>>>(dm, sx, sy, feat, conf, fL, fR);

    conv3x3_v2<IN_CH, false><<<cgrid, 256>>>(px, w1, ph1, 0);
    zero_stats_kernel<<<1, 64>>>();
    gn_reduce_kernel<<<rgrid, 256>>>(ph1);
    finalize_stats_kernel<<<1, 96>>>(g1g, g1b);

    conv3x3_v2<HIDDEN, true><<<cgrid, 256>>>(ph1, w2, ph2, 0);
    zero_stats_kernel<<<1, 64>>>();
    gn_reduce_kernel<<<rgrid, 256>>>(ph2);
    finalize_stats_kernel<<<1, 96>>>(g2g, g2b);

    conv3x3_v2<HIDDEN, true><<<cgrid, 256>>>(ph2, w3, ph1, 0);
    zero_stats_kernel<<<1, 64>>>();
    gn_reduce_kernel<<<rgrid, 256>>>(ph1);
    finalize_stats_kernel<<<1, 96>>>(g3g, g3b);

    heads_kernel<<<hgrid, 256>>>(ph1,
                                 dm, sx, sy, feat, conf,
                                 hd_w, hd_b, hsx_w, hsx_b, hsy_w, hsy_b,
                                 hc_w, hc_b, hf_w, hf_b, out);
}

// round 5
// speedup vs baseline: 1.6656x; 1.4045x over previous
#include <cuda_runtime.h>
#include <math.h>
#include <stdint.h>

#define Bn 2
#define Cn 64
#define Hn 320
#define Wn 640
#define TFn 16
#define HIDDEN 48
#define GROUPS 8
#define CPG 6
#define IN_CH 188
#define HW (Hn*Wn)
#define GN_N (CPG*HW)
#define BHW (Bn*HW)

typedef unsigned long long ull;

// Blackwell packed-f32 FMA: 2 MACs per lane per issue (ptxas never emits this
// from plain C++; PTX-only).
#define PACK2(d, lo, hi) asm("mov.b64 %0, {%1,%2};" : "=l"(d) : "f"(lo), "f"(hi))
#define UNPACK2(lo, hi, v) asm("mov.b64 {%0,%1}, %2;" : "=f"(lo), "=f"(hi) : "l"(v))
#define FMA2(acc, a, b)  asm("fma.rn.f32x2 %0, %1, %2, %0;" : "+l"(acc) : "l"(a), "l"(b))

// ---------------- scratch ----------------
__device__ float  g_x [Bn*IN_CH*HW];
__device__ float  g_h1[Bn*HIDDEN*HW];
__device__ float  g_h2[Bn*HIDDEN*HW];
__device__ double g_stats[Bn*GROUPS*2];
__device__ float  g_scale[Bn*HIDDEN];
__device__ float  g_shift[Bn*HIDDEN];

// ---------------------------------------------------------------------------
// Kernel 1: build x = concat(fL, warp(fR,d), feat, d, sx, sy, conf, corr)
// ---------------------------------------------------------------------------
__global__ void __launch_bounds__(Wn) build_x_kernel(
    const float* __restrict__ dm, const float* __restrict__ sx,
    const float* __restrict__ sy, const float* __restrict__ feat,
    const float* __restrict__ conf, const float* __restrict__ fL,
    const float* __restrict__ fR)
{
    __shared__ float srow[8*Wn];
    const int b = blockIdx.x / Hn;
    const int y = blockIdx.x % Hn;
    const int x = threadIdx.x;
    const int prow = b*HW + y*Wn;

    const float dval = dm[prow + x];
    int i0[5], i1[5]; float fr[5];
#pragma unroll
    for (int i = 0; i < 5; i++) {
        float xs = (float)x - dval - (float)(i-2);
        xs = fminf(fmaxf(xs, 0.f), (float)(Wn-1));
        float f0 = floorf(xs);
        i0[i] = (int)f0;
        fr[i] = xs - f0;
        i1[i] = min(i0[i]+1, Wn-1);
    }

    float* xb = g_x + (size_t)b*IN_CH*HW + (size_t)y*Wn + x;
    const float* fLp = fL + (size_t)b*Cn*HW + (size_t)y*Wn + x;
    const float* fRp = fR + (size_t)b*Cn*HW + (size_t)y*Wn;

    for (int g = 0; g < 8; g++) {
        __syncthreads();
#pragma unroll
        for (int j = 0; j < 8; j++)
            srow[j*Wn + x] = fRp[(size_t)(g*8+j)*HW + x];
        __syncthreads();

        float acc[5] = {0.f,0.f,0.f,0.f,0.f};
#pragma unroll
        for (int j = 0; j < 8; j++) {
            const int c = g*8 + j;
            const float fl = fLp[(size_t)c*HW];
            xb[(size_t)c*HW] = fl;
#pragma unroll
            for (int i = 0; i < 5; i++) {
                float v = srow[j*Wn+i0[i]]*(1.f-fr[i]) + srow[j*Wn+i1[i]]*fr[i];
                acc[i] += fl*v;
                if (i == 2) xb[(size_t)(64+c)*HW] = v;
            }
        }
#pragma unroll
        for (int i = 0; i < 5; i++)
            xb[(size_t)(148 + g*5 + i)*HW] = acc[i]*(1.f/8.f);
    }
#pragma unroll
    for (int j = 0; j < TFn; j++)
        xb[(size_t)(128+j)*HW] = feat[((size_t)b*TFn + j)*HW + y*Wn + x];
    xb[(size_t)144*HW] = dval;
    xb[(size_t)145*HW] = sx[prow + x];
    xb[(size_t)146*HW] = sy[prow + x];
    xb[(size_t)147*HW] = conf[prow + x];
}

// ---------------------------------------------------------------------------
// Kernel 2 v3: 3x3 conv via packed f32x2 FMA. 64x8 tile, 2 px/thread.
// f32x2 lanes hold an OUTPUT-CHANNEL PAIR (2q, 2q+1): weight pairs are
// pre-interleaved in smem (free), activations lane-duplicated (12 movs/ch).
// Double-buffered smem, one __syncthreads per input channel.
// ---------------------------------------------------------------------------
template<int IN, bool HASGN>
__global__ void __launch_bounds__(256) conv3x3_v3(
    const float* __restrict__ in, const float* __restrict__ wgt,
    float* __restrict__ out)
{
    __shared__ float ts[2][10*68];
    __shared__ __align__(16) float2 ws[2][24*10];   // [q][tap], tap padded to 10

    const int tid = threadIdx.x;
    const int tx = tid & 31, ty = tid >> 5;
    const int x0 = blockIdx.x*64, y0 = blockIdx.y*8;
    const int b  = blockIdx.z;

    const float* inb = in + (size_t)b*IN*HW;
    const float* scb = g_scale + b*HIDDEN;
    const float* shb = g_shift + b*HIDDEN;

    // tile-load slots (3 per thread)
    int   toff[3], soff[3];
    bool  timg[3], tin[3];
#pragma unroll
    for (int j = 0; j < 3; j++) {
        int idx = tid + j*256;
        int r = idx/66, c = idx%66;
        int gy = y0-1+r, gx = x0-1+c;
        tin[j]  = (idx < 660);
        timg[j] = tin[j] && gy >= 0 && gy < Hn && gx >= 0 && gx < Wn;
        toff[j] = timg[j] ? gy*Wn + gx : 0;
        soff[j] = r*68 + c;
    }
    // weight-pair slot: tid<216 handles (q, k)
    const bool wact = tid < 216;
    const int wq = wact ? tid/9 : 0, wk = wact ? tid%9 : 0;
    const size_t wo0 = (size_t)(2*wq)*IN*9 + wk;
    const size_t wo1 = (size_t)(2*wq+1)*IN*9 + wk;

    ull acc[48];                       // [q*2 + px], lanes = (out 2q, out 2q+1)
#pragma unroll
    for (int i = 0; i < 48; i++) acc[i] = 0ull;

    // prologue: channel 0
    {
        float sc = 1.f, sh = 0.f;
        if (HASGN) { sc = scb[0]; sh = shb[0]; }
#pragma unroll
        for (int j = 0; j < 3; j++) {
            if (tin[j]) {
                float v = 0.f;
                if (timg[j]) {
                    v = inb[toff[j]];
                    if (HASGN) { float z = v*sc + sh; v = z / (1.f + expf(-z)); }
                }
                ts[0][soff[j]] = v;
            }
        }
        if (wact) ws[0][wq*10 + wk] = make_float2(wgt[wo0], wgt[wo1]);
    }
    __syncthreads();

    int cur = 0;
#pragma unroll 1
    for (int ci = 0; ci < IN; ci++) {
        // ---- prefetch next channel into registers ----
        float tv[3] = {0.f,0.f,0.f};
        float wv0 = 0.f, wv1 = 0.f;
        float sc = 1.f, sh = 0.f;
        const bool more = (ci + 1 < IN);
        if (more) {
            const float* ip = inb + (size_t)(ci+1)*HW;
#pragma unroll
            for (int j = 0; j < 3; j++)
                if (timg[j]) tv[j] = ip[toff[j]];
            if (wact) {
                wv0 = wgt[wo0 + (size_t)(ci+1)*9];
                wv1 = wgt[wo1 + (size_t)(ci+1)*9];
            }
            if (HASGN) { sc = scb[ci+1]; sh = shb[ci+1]; }
        }

        // ---- compute current channel ----
        ull dv[12];
        {
            const float* base = &ts[cur][ty*68 + 2*tx];
            float2 a0 = *(const float2*)(base + 0);
            float2 a1 = *(const float2*)(base + 2);
            float2 b0 = *(const float2*)(base + 68);
            float2 b1 = *(const float2*)(base + 70);
            float2 c0 = *(const float2*)(base + 136);
            float2 c1 = *(const float2*)(base + 138);
            PACK2(dv[0], a0.x, a0.x); PACK2(dv[1],  a0.y, a0.y);
            PACK2(dv[2], a1.x, a1.x); PACK2(dv[3],  a1.y, a1.y);
            PACK2(dv[4], b0.x, b0.x); PACK2(dv[5],  b0.y, b0.y);
            PACK2(dv[6], b1.x, b1.x); PACK2(dv[7],  b1.y, b1.y);
            PACK2(dv[8], c0.x, c0.x); PACK2(dv[9],  c0.y, c0.y);
            PACK2(dv[10],c1.x, c1.x); PACK2(dv[11], c1.y, c1.y);
        }
#pragma unroll
        for (int q = 0; q < 24; q++) {
            const ull* wrow = (const ull*)&ws[cur][q*10];
            ulonglong2 w01 = *(const ulonglong2*)(wrow + 0);
            ulonglong2 w23 = *(const ulonglong2*)(wrow + 2);
            ulonglong2 w45 = *(const ulonglong2*)(wrow + 4);
            ulonglong2 w67 = *(const ulonglong2*)(wrow + 6);
            ull w8 = wrow[8];
            ull a0 = acc[2*q], a1 = acc[2*q+1];
            FMA2(a0, w01.x, dv[0]);  FMA2(a1, w01.x, dv[1]);
            FMA2(a0, w01.y, dv[1]);  FMA2(a1, w01.y, dv[2]);
            FMA2(a0, w23.x, dv[2]);  FMA2(a1, w23.x, dv[3]);
            FMA2(a0, w23.y, dv[4]);  FMA2(a1, w23.y, dv[5]);
            FMA2(a0, w45.x, dv[5]);  FMA2(a1, w45.x, dv[6]);
            FMA2(a0, w45.y, dv[6]);  FMA2(a1, w45.y, dv[7]);
            FMA2(a0, w67.x, dv[8]);  FMA2(a1, w67.x, dv[9]);
            FMA2(a0, w67.y, dv[9]);  FMA2(a1, w67.y, dv[10]);
            FMA2(a0, w8,    dv[10]); FMA2(a1, w8,    dv[11]);
            acc[2*q] = a0; acc[2*q+1] = a1;
        }

        // ---- stage next channel ----
        if (more) {
            const int nb = cur ^ 1;
#pragma unroll
            for (int j = 0; j < 3; j++) {
                if (tin[j]) {
                    float v = tv[j];
                    if (HASGN && timg[j]) { float z = v*sc + sh; v = z / (1.f + expf(-z)); }
                    ts[nb][soff[j]] = v;
                }
            }
            if (wact) ws[nb][wq*10 + wk] = make_float2(wv0, wv1);
        }
        __syncthreads();
        cur ^= 1;
    }

    float* op = out + (size_t)b*HIDDEN*HW + (size_t)(y0+ty)*Wn + (x0 + 2*tx);
#pragma unroll
    for (int q = 0; q < 24; q++) {
        float p0o0, p0o1, p1o0, p1o1;
        UNPACK2(p0o0, p0o1, acc[2*q]);
        UNPACK2(p1o0, p1o1, acc[2*q+1]);
        *(float2*)&op[(size_t)(2*q  )*HW] = make_float2(p0o0, p1o0);
        *(float2*)&op[(size_t)(2*q+1)*HW] = make_float2(p0o1, p1o1);
    }
}

// ---------------------------------------------------------------------------
// GN stats
// ---------------------------------------------------------------------------
__global__ void zero_stats_kernel() {
    if (threadIdx.x < Bn*GROUPS*2) g_stats[threadIdx.x] = 0.0;
}

__global__ void __launch_bounds__(256) gn_reduce_kernel(const float* __restrict__ h)
{
    const int bc = blockIdx.x;
    const int slice = blockIdx.y;
    const float4* p = (const float4*)(h + (size_t)bc*HW) + slice*6400 + threadIdx.x;

    float s0=0.f,s1=0.f,s2=0.f,s3=0.f;
    float q0=0.f,q1=0.f,q2=0.f,q3=0.f;
#pragma unroll
    for (int k = 0; k < 25; k++) {
        float4 f = p[k*256];
        s0 += f.x; s1 += f.y; s2 += f.z; s3 += f.w;
        q0 += f.x*f.x; q1 += f.y*f.y; q2 += f.z*f.z; q3 += f.w*f.w;
    }
    double s = ((double)s0 + s1) + ((double)s2 + s3);
    double q = ((double)q0 + q1) + ((double)q2 + q3);
#pragma unroll
    for (int o = 16; o > 0; o >>= 1) {
        s += __shfl_down_sync(0xFFFFFFFFu, s, o);
        q += __shfl_down_sync(0xFFFFFFFFu, q, o);
    }
    __shared__ double ss[8], qq[8];
    if ((threadIdx.x & 31) == 0) { ss[threadIdx.x>>5] = s; qq[threadIdx.x>>5] = q; }
    __syncthreads();
    if (threadIdx.x == 0) {
        double S = 0.0, Q = 0.0;
#pragma unroll
        for (int w = 0; w < 8; w++) { S += ss[w]; Q += qq[w]; }
        const int b = bc / HIDDEN, c = bc % HIDDEN, g = c / CPG;
        atomicAdd(&g_stats[(b*GROUPS+g)*2+0], S);
        atomicAdd(&g_stats[(b*GROUPS+g)*2+1], Q);
    }
}

__global__ void finalize_stats_kernel(const float* __restrict__ gamma,
                                      const float* __restrict__ beta)
{
    const int i = threadIdx.x;
    if (i >= Bn*HIDDEN) return;
    const int b = i / HIDDEN, c = i % HIDDEN, g = c / CPG;
    double s = g_stats[(b*GROUPS+g)*2+0];
    double q = g_stats[(b*GROUPS+g)*2+1];
    double mean = s / (double)GN_N;
    double var  = q / (double)GN_N - mean*mean;
    float inv = (float)rsqrt(var + 1e-5);
    float sc = gamma[c]*inv;
    g_scale[i] = sc;
    g_shift[i] = beta[c] - (float)mean*sc;
}

// ---------------------------------------------------------------------------
// Kernel 3: fused GN3+SiLU + five 1x1 heads + epilogues (f32x2 output pairs).
// ---------------------------------------------------------------------------
__global__ void __launch_bounds__(256) heads_kernel(
    const float* __restrict__ h,
    const float* __restrict__ dm, const float* __restrict__ sxp,
    const float* __restrict__ syp, const float* __restrict__ feat,
    const float* __restrict__ conf,
    const float* __restrict__ hd_w,  const float* __restrict__ hd_b,
    const float* __restrict__ hsx_w, const float* __restrict__ hsx_b,
    const float* __restrict__ hsy_w, const float* __restrict__ hsy_b,
    const float* __restrict__ hc_w,  const float* __restrict__ hc_b,
    const float* __restrict__ hf_w,  const float* __restrict__ hf_b,
    float* __restrict__ out)
{
    __shared__ __align__(16) float2 wsmT[HIDDEN*10];   // [c][pair q], 80B rows
    __shared__ float bia[20];
    __shared__ float sc[HIDDEN], sh[HIDDEN];

    const int tid = threadIdx.x;
    const int b   = blockIdx.y;

    for (int idx = tid; idx < 10*HIDDEN; idx += 256) {
        int c = idx / 10, q = idx % 10;
        float w[2];
#pragma unroll
        for (int j = 0; j < 2; j++) {
            int o = 2*q + j;
            if (o == 0)      w[j] = hd_w[c];
            else if (o == 1) w[j] = hsx_w[c];
            else if (o == 2) w[j] = hsy_w[c];
            else if (o == 3) w[j] = hc_w[c];
            else             w[j] = hf_w[(o-4)*HIDDEN + c];
        }
        wsmT[idx] = make_float2(w[0], w[1]);
    }
    if (tid < 20) {
        bia[tid] = (tid==0) ? hd_b[0] : (tid==1) ? hsx_b[0] : (tid==2) ? hsy_b[0]
                 : (tid==3) ? hc_b[0] : hf_b[tid-4];
    }
    if (tid < HIDDEN) {
        sc[tid] = g_scale[b*HIDDEN + tid];
        sh[tid] = g_shift[b*HIDDEN + tid];
    }
    __syncthreads();

    const int rem = blockIdx.x*256 + tid;
    const float* hp = h + (size_t)b*HIDDEN*HW + rem;

    ull acc[10];
#pragma unroll
    for (int q = 0; q < 10; q++) acc[q] = 0ull;
#pragma unroll 4
    for (int c = 0; c < HIDDEN; c++) {
        float z = hp[(size_t)c*HW]*sc[c] + sh[c];
        float a = z / (1.f + expf(-z));
        ull da; PACK2(da, a, a);
        const ull* wrow = (const ull*)&wsmT[c*10];
        ulonglong2 w01 = *(const ulonglong2*)(wrow + 0);
        ulonglong2 w23 = *(const ulonglong2*)(wrow + 2);
        ulonglong2 w45 = *(const ulonglong2*)(wrow + 4);
        ulonglong2 w67 = *(const ulonglong2*)(wrow + 6);
        ulonglong2 w89 = *(const ulonglong2*)(wrow + 8);
        FMA2(acc[0], w01.x, da); FMA2(acc[1], w01.y, da);
        FMA2(acc[2], w23.x, da); FMA2(acc[3], w23.y, da);
        FMA2(acc[4], w45.x, da); FMA2(acc[5], w45.y, da);
        FMA2(acc[6], w67.x, da); FMA2(acc[7], w67.y, da);
        FMA2(acc[8], w89.x, da); FMA2(acc[9], w89.y, da);
    }

    float ao[20];
#pragma unroll
    for (int q = 0; q < 10; q++) UNPACK2(ao[2*q], ao[2*q+1], acc[q]);

    const int p = b*HW + rem;
    float t = ao[0] + bia[0] + dm[p];
    out[p] = fmaxf(t, 0.f) + log1pf(expf(-fabsf(t)));
    out[BHW   + p] = sxp[p] + (ao[1] + bia[1])*0.1f;
    out[2*BHW + p] = syp[p] + (ao[2] + bia[2])*0.1f;
#pragma unroll
    for (int j = 0; j < TFn; j++) {
        size_t fi = ((size_t)b*TFn + j)*HW + rem;
        out[3*(size_t)BHW + fi] = feat[fi] + ao[4+j] + bia[4+j];
    }
    float cz = ao[3] + bia[3] + 2.f*conf[p] - 1.f;
    out[19*(size_t)BHW + p] = 1.f / (1.f + expf(-cz));
}

// ---------------------------------------------------------------------------
extern "C" void kernel_launch(void* const* d_in, const int* in_sizes, int n_in,
                              void* d_out, int out_size)
{
    const float* dm   = (const float*)d_in[0];
    const float* sx   = (const float*)d_in[1];
    const float* sy   = (const float*)d_in[2];
    const float* feat = (const float*)d_in[3];
    const float* conf = (const float*)d_in[4];
    const float* fL   = (const float*)d_in[5];
    const float* fR   = (const float*)d_in[6];
    const float* w1   = (const float*)d_in[7];
    const float* w2   = (const float*)d_in[8];
    const float* w3   = (const float*)d_in[9];
    const float* g1g  = (const float*)d_in[10];
    const float* g1b  = (const float*)d_in[11];
    const float* g2g  = (const float*)d_in[12];
    const float* g2b  = (const float*)d_in[13];
    const float* g3g  = (const float*)d_in[14];
    const float* g3b  = (const float*)d_in[15];
    const float* hd_w  = (const float*)d_in[16];
    const float* hd_b  = (const float*)d_in[17];
    const float* hsx_w = (const float*)d_in[18];
    const float* hsx_b = (const float*)d_in[19];
    const float* hsy_w = (const float*)d_in[20];
    const float* hsy_b = (const float*)d_in[21];
    const float* hc_w  = (const float*)d_in[22];
    const float* hc_b  = (const float*)d_in[23];
    const float* hf_w  = (const float*)d_in[24];
    const float* hf_b  = (const float*)d_in[25];
    float* out = (float*)d_out;

    float *px, *ph1, *ph2;
    cudaGetSymbolAddress((void**)&px,  g_x);
    cudaGetSymbolAddress((void**)&ph1, g_h1);
    cudaGetSymbolAddress((void**)&ph2, g_h2);

    const dim3 cgrid(Wn/64, Hn/8, Bn);   // (10, 40, 2)
    const dim3 rgrid(Bn*HIDDEN, 8);      // (96, 8)
    const dim3 hgrid(HW/256, Bn);        // (800, 2)

    build_x_kernel<<<Bn*Hn, Wn>>>(dm, sx, sy, feat, conf, fL, fR);

    conv3x3_v3<IN_CH, false><<<cgrid, 256>>>(px, w1, ph1);
    zero_stats_kernel<<<1, 64>>>();
    gn_reduce_kernel<<<rgrid, 256>>>(ph1);
    finalize_stats_kernel<<<1, 96>>>(g1g, g1b);

    conv3x3_v3<HIDDEN, true><<<cgrid, 256>>>(ph1, w2, ph2);
    zero_stats_kernel<<<1, 64>>>();
    gn_reduce_kernel<<<rgrid, 256>>>(ph2);
    finalize_stats_kernel<<<1, 96>>>(g2g, g2b);

    conv3x3_v3<HIDDEN, true><<<cgrid, 256>>>(ph2, w3, ph1);
    zero_stats_kernel<<<1, 64>>>();
    gn_reduce_kernel<<<rgrid, 256>>>(ph1);
    finalize_stats_kernel<<<1, 96>>>(g3g, g3b);

    heads_kernel<<<hgrid, 256>>>(ph1,
                                 dm, sx, sy, feat, conf,
                                 hd_w, hd_b, hsx_w, hsx_b, hsy_w, hsy_b,
                                 hc_w, hc_b, hf_w, hf_b, out);
}

// round 6
// speedup vs baseline: 1.6755x; 1.0059x over previous
#include <cuda_runtime.h>
#include <math.h>
#include <stdint.h>

#define Bn 2
#define Cn 64
#define Hn 320
#define Wn 640
#define TFn 16
#define HIDDEN 48
#define GROUPS 8
#define CPG 6
#define IN_CH 188
#define HW (Hn*Wn)
#define GN_N (CPG*HW)
#define BHW (Bn*HW)

typedef unsigned long long ull;

// Blackwell packed-f32 FMA: 2 MACs per lane per issue (ptxas never emits this
// from plain C++; PTX-only).
#define PACK2(d, lo, hi) asm("mov.b64 %0, {%1,%2};" : "=l"(d) : "f"(lo), "f"(hi))
#define UNPACK2(lo, hi, v) asm("mov.b64 {%0,%1}, %2;" : "=f"(lo), "=f"(hi) : "l"(v))
#define FMA2(acc, a, b)  asm("fma.rn.f32x2 %0, %1, %2, %0;" : "+l"(acc) : "l"(a), "l"(b))

// ---------------- scratch ----------------
__device__ float  g_x [Bn*IN_CH*HW];
__device__ float  g_h1[Bn*HIDDEN*HW];
__device__ float  g_h2[Bn*HIDDEN*HW];
__device__ double g_stats[Bn*GROUPS*2];
__device__ float  g_scale[Bn*HIDDEN];
__device__ float  g_shift[Bn*HIDDEN];

// ---------------------------------------------------------------------------
// Kernel 1: build x = concat(fL, warp(fR,d), feat, d, sx, sy, conf, corr)
// ---------------------------------------------------------------------------
__global__ void __launch_bounds__(Wn) build_x_kernel(
    const float* __restrict__ dm, const float* __restrict__ sx,
    const float* __restrict__ sy, const float* __restrict__ feat,
    const float* __restrict__ conf, const float* __restrict__ fL,
    const float* __restrict__ fR)
{
    __shared__ float srow[8*Wn];
    const int b = blockIdx.x / Hn;
    const int y = blockIdx.x % Hn;
    const int x = threadIdx.x;
    const int prow = b*HW + y*Wn;

    const float dval = dm[prow + x];
    int i0[5], i1[5]; float fr[5];
#pragma unroll
    for (int i = 0; i < 5; i++) {
        float xs = (float)x - dval - (float)(i-2);
        xs = fminf(fmaxf(xs, 0.f), (float)(Wn-1));
        float f0 = floorf(xs);
        i0[i] = (int)f0;
        fr[i] = xs - f0;
        i1[i] = min(i0[i]+1, Wn-1);
    }

    float* xb = g_x + (size_t)b*IN_CH*HW + (size_t)y*Wn + x;
    const float* fLp = fL + (size_t)b*Cn*HW + (size_t)y*Wn + x;
    const float* fRp = fR + (size_t)b*Cn*HW + (size_t)y*Wn;

    for (int g = 0; g < 8; g++) {
        __syncthreads();
#pragma unroll
        for (int j = 0; j < 8; j++)
            srow[j*Wn + x] = fRp[(size_t)(g*8+j)*HW + x];
        __syncthreads();

        float acc[5] = {0.f,0.f,0.f,0.f,0.f};
#pragma unroll
        for (int j = 0; j < 8; j++) {
            const int c = g*8 + j;
            const float fl = fLp[(size_t)c*HW];
            xb[(size_t)c*HW] = fl;
#pragma unroll
            for (int i = 0; i < 5; i++) {
                float v = srow[j*Wn+i0[i]]*(1.f-fr[i]) + srow[j*Wn+i1[i]]*fr[i];
                acc[i] += fl*v;
                if (i == 2) xb[(size_t)(64+c)*HW] = v;
            }
        }
#pragma unroll
        for (int i = 0; i < 5; i++)
            xb[(size_t)(148 + g*5 + i)*HW] = acc[i]*(1.f/8.f);
    }
#pragma unroll
    for (int j = 0; j < TFn; j++)
        xb[(size_t)(128+j)*HW] = feat[((size_t)b*TFn + j)*HW + y*Wn + x];
    xb[(size_t)144*HW] = dval;
    xb[(size_t)145*HW] = sx[prow + x];
    xb[(size_t)146*HW] = sy[prow + x];
    xb[(size_t)147*HW] = conf[prow + x];
}

// ---------------------------------------------------------------------------
// Kernel 2 v3: 3x3 conv via packed f32x2 FMA. 64x8 tile, 2 px/thread.
// f32x2 lanes hold an OUTPUT-CHANNEL PAIR (2q, 2q+1): weight pairs are
// pre-interleaved in smem (free), activations lane-duplicated (12 movs/ch).
// Double-buffered smem, one __syncthreads per input channel.
// ---------------------------------------------------------------------------
template<int IN, bool HASGN>
__global__ void __launch_bounds__(256) conv3x3_v3(
    const float* __restrict__ in, const float* __restrict__ wgt,
    float* __restrict__ out)
{
    __shared__ float ts[2][10*68];
    __shared__ __align__(16) float2 ws[2][24*10];   // [q][tap], tap padded to 10

    const int tid = threadIdx.x;
    const int tx = tid & 31, ty = tid >> 5;
    const int x0 = blockIdx.x*64, y0 = blockIdx.y*8;
    const int b  = blockIdx.z;

    const float* inb = in + (size_t)b*IN*HW;
    const float* scb = g_scale + b*HIDDEN;
    const float* shb = g_shift + b*HIDDEN;

    // tile-load slots (3 per thread)
    int   toff[3], soff[3];
    bool  timg[3], tin[3];
#pragma unroll
    for (int j = 0; j < 3; j++) {
        int idx = tid + j*256;
        int r = idx/66, c = idx%66;
        int gy = y0-1+r, gx = x0-1+c;
        tin[j]  = (idx < 660);
        timg[j] = tin[j] && gy >= 0 && gy < Hn && gx >= 0 && gx < Wn;
        toff[j] = timg[j] ? gy*Wn + gx : 0;
        soff[j] = r*68 + c;
    }
    // weight-pair slot: tid<216 handles (q, k)
    const bool wact = tid < 216;
    const int wq = wact ? tid/9 : 0, wk = wact ? tid%9 : 0;
    const size_t wo0 = (size_t)(2*wq)*IN*9 + wk;
    const size_t wo1 = (size_t)(2*wq+1)*IN*9 + wk;

    ull acc[48];                       // [q*2 + px], lanes = (out 2q, out 2q+1)
#pragma unroll
    for (int i = 0; i < 48; i++) acc[i] = 0ull;

    // prologue: channel 0
    {
        float sc = 1.f, sh = 0.f;
        if (HASGN) { sc = scb[0]; sh = shb[0]; }
#pragma unroll
        for (int j = 0; j < 3; j++) {
            if (tin[j]) {
                float v = 0.f;
                if (timg[j]) {
                    v = inb[toff[j]];
                    if (HASGN) { float z = v*sc + sh; v = z / (1.f + expf(-z)); }
                }
                ts[0][soff[j]] = v;
            }
        }
        if (wact) ws[0][wq*10 + wk] = make_float2(wgt[wo0], wgt[wo1]);
    }
    __syncthreads();

    int cur = 0;
#pragma unroll 1
    for (int ci = 0; ci < IN; ci++) {
        // ---- prefetch next channel into registers ----
        float tv[3] = {0.f,0.f,0.f};
        float wv0 = 0.f, wv1 = 0.f;
        float sc = 1.f, sh = 0.f;
        const bool more = (ci + 1 < IN);
        if (more) {
            const float* ip = inb + (size_t)(ci+1)*HW;
#pragma unroll
            for (int j = 0; j < 3; j++)
                if (timg[j]) tv[j] = ip[toff[j]];
            if (wact) {
                wv0 = wgt[wo0 + (size_t)(ci+1)*9];
                wv1 = wgt[wo1 + (size_t)(ci+1)*9];
            }
            if (HASGN) { sc = scb[ci+1]; sh = shb[ci+1]; }
        }

        // ---- compute current channel ----
        ull dv[12];
        {
            const float* base = &ts[cur][ty*68 + 2*tx];
            float2 a0 = *(const float2*)(base + 0);
            float2 a1 = *(const float2*)(base + 2);
            float2 b0 = *(const float2*)(base + 68);
            float2 b1 = *(const float2*)(base + 70);
            float2 c0 = *(const float2*)(base + 136);
            float2 c1 = *(const float2*)(base + 138);
            PACK2(dv[0], a0.x, a0.x); PACK2(dv[1],  a0.y, a0.y);
            PACK2(dv[2], a1.x, a1.x); PACK2(dv[3],  a1.y, a1.y);
            PACK2(dv[4], b0.x, b0.x); PACK2(dv[5],  b0.y, b0.y);
            PACK2(dv[6], b1.x, b1.x); PACK2(dv[7],  b1.y, b1.y);
            PACK2(dv[8], c0.x, c0.x); PACK2(dv[9],  c0.y, c0.y);
            PACK2(dv[10],c1.x, c1.x); PACK2(dv[11], c1.y, c1.y);
        }
#pragma unroll
        for (int q = 0; q < 24; q++) {
            const ull* wrow = (const ull*)&ws[cur][q*10];
            ulonglong2 w01 = *(const ulonglong2*)(wrow + 0);
            ulonglong2 w23 = *(const ulonglong2*)(wrow + 2);
            ulonglong2 w45 = *(const ulonglong2*)(wrow + 4);
            ulonglong2 w67 = *(const ulonglong2*)(wrow + 6);
            ull w8 = wrow[8];
            ull a0 = acc[2*q], a1 = acc[2*q+1];
            FMA2(a0, w01.x, dv[0]);  FMA2(a1, w01.x, dv[1]);
            FMA2(a0, w01.y, dv[1]);  FMA2(a1, w01.y, dv[2]);
            FMA2(a0, w23.x, dv[2]);  FMA2(a1, w23.x, dv[3]);
            FMA2(a0, w23.y, dv[4]);  FMA2(a1, w23.y, dv[5]);
            FMA2(a0, w45.x, dv[5]);  FMA2(a1, w45.x, dv[6]);
            FMA2(a0, w45.y, dv[6]);  FMA2(a1, w45.y, dv[7]);
            FMA2(a0, w67.x, dv[8]);  FMA2(a1, w67.x, dv[9]);
            FMA2(a0, w67.y, dv[9]);  FMA2(a1, w67.y, dv[10]);
            FMA2(a0, w8,    dv[10]); FMA2(a1, w8,    dv[11]);
            acc[2*q] = a0; acc[2*q+1] = a1;
        }

        // ---- stage next channel ----
        if (more) {
            const int nb = cur ^ 1;
#pragma unroll
            for (int j = 0; j < 3; j++) {
                if (tin[j]) {
                    float v = tv[j];
                    if (HASGN && timg[j]) { float z = v*sc + sh; v = z / (1.f + expf(-z)); }
                    ts[nb][soff[j]] = v;
                }
            }
            if (wact) ws[nb][wq*10 + wk] = make_float2(wv0, wv1);
        }
        __syncthreads();
        cur ^= 1;
    }

    float* op = out + (size_t)b*HIDDEN*HW + (size_t)(y0+ty)*Wn + (x0 + 2*tx);
#pragma unroll
    for (int q = 0; q < 24; q++) {
        float p0o0, p0o1, p1o0, p1o1;
        UNPACK2(p0o0, p0o1, acc[2*q]);
        UNPACK2(p1o0, p1o1, acc[2*q+1]);
        *(float2*)&op[(size_t)(2*q  )*HW] = make_float2(p0o0, p1o0);
        *(float2*)&op[(size_t)(2*q+1)*HW] = make_float2(p0o1, p1o1);
    }
}

// ---------------------------------------------------------------------------
// GN stats
// ---------------------------------------------------------------------------
__global__ void zero_stats_kernel() {
    if (threadIdx.x < Bn*GROUPS*2) g_stats[threadIdx.x] = 0.0;
}

__global__ void __launch_bounds__(256) gn_reduce_kernel(const float* __restrict__ h)
{
    const int bc = blockIdx.x;
    const int slice = blockIdx.y;
    const float4* p = (const float4*)(h + (size_t)bc*HW) + slice*6400 + threadIdx.x;

    float s0=0.f,s1=0.f,s2=0.f,s3=0.f;
    float q0=0.f,q1=0.f,q2=0.f,q3=0.f;
#pragma unroll
    for (int k = 0; k < 25; k++) {
        float4 f = p[k*256];
        s0 += f.x; s1 += f.y; s2 += f.z; s3 += f.w;
        q0 += f.x*f.x; q1 += f.y*f.y; q2 += f.z*f.z; q3 += f.w*f.w;
    }
    double s = ((double)s0 + s1) + ((double)s2 + s3);
    double q = ((double)q0 + q1) + ((double)q2 + q3);
#pragma unroll
    for (int o = 16; o > 0; o >>= 1) {
        s += __shfl_down_sync(0xFFFFFFFFu, s, o);
        q += __shfl_down_sync(0xFFFFFFFFu, q, o);
    }
    __shared__ double ss[8], qq[8];
    if ((threadIdx.x & 31) == 0) { ss[threadIdx.x>>5] = s; qq[threadIdx.x>>5] = q; }
    __syncthreads();
    if (threadIdx.x == 0) {
        double S = 0.0, Q = 0.0;
#pragma unroll
        for (int w = 0; w < 8; w++) { S += ss[w]; Q += qq[w]; }
        const int b = bc / HIDDEN, c = bc % HIDDEN, g = c / CPG;
        atomicAdd(&g_stats[(b*GROUPS+g)*2+0], S);
        atomicAdd(&g_stats[(b*GROUPS+g)*2+1], Q);
    }
}

__global__ void finalize_stats_kernel(const float* __restrict__ gamma,
                                      const float* __restrict__ beta)
{
    const int i = threadIdx.x;
    if (i >= Bn*HIDDEN) return;
    const int b = i / HIDDEN, c = i % HIDDEN, g = c / CPG;
    double s = g_stats[(b*GROUPS+g)*2+0];
    double q = g_stats[(b*GROUPS+g)*2+1];
    double mean = s / (double)GN_N;
    double var  = q / (double)GN_N - mean*mean;
    float inv = (float)rsqrt(var + 1e-5);
    float sc = gamma[c]*inv;
    g_scale[i] = sc;
    g_shift[i] = beta[c] - (float)mean*sc;
}

// ---------------------------------------------------------------------------
// Kernel 3: fused GN3+SiLU + five 1x1 heads + epilogues (f32x2 output pairs).
// ---------------------------------------------------------------------------
__global__ void __launch_bounds__(256) heads_kernel(
    const float* __restrict__ h,
    const float* __restrict__ dm, const float* __restrict__ sxp,
    const float* __restrict__ syp, const float* __restrict__ feat,
    const float* __restrict__ conf,
    const float* __restrict__ hd_w,  const float* __restrict__ hd_b,
    const float* __restrict__ hsx_w, const float* __restrict__ hsx_b,
    const float* __restrict__ hsy_w, const float* __restrict__ hsy_b,
    const float* __restrict__ hc_w,  const float* __restrict__ hc_b,
    const float* __restrict__ hf_w,  const float* __restrict__ hf_b,
    float* __restrict__ out)
{
    __shared__ __align__(16) float2 wsmT[HIDDEN*10];   // [c][pair q], 80B rows
    __shared__ float bia[20];
    __shared__ float sc[HIDDEN], sh[HIDDEN];

    const int tid = threadIdx.x;
    const int b   = blockIdx.y;

    for (int idx = tid; idx < 10*HIDDEN; idx += 256) {
        int c = idx / 10, q = idx % 10;
        float w[2];
#pragma unroll
        for (int j = 0; j < 2; j++) {
            int o = 2*q + j;
            if (o == 0)      w[j] = hd_w[c];
            else if (o == 1) w[j] = hsx_w[c];
            else if (o == 2) w[j] = hsy_w[c];
            else if (o == 3) w[j] = hc_w[c];
            else             w[j] = hf_w[(o-4)*HIDDEN + c];
        }
        wsmT[idx] = make_float2(w[0], w[1]);
    }
    if (tid < 20) {
        bia[tid] = (tid==0) ? hd_b[0] : (tid==1) ? hsx_b[0] : (tid==2) ? hsy_b[0]
                 : (tid==3) ? hc_b[0] : hf_b[tid-4];
    }
    if (tid < HIDDEN) {
        sc[tid] = g_scale[b*HIDDEN + tid];
        sh[tid] = g_shift[b*HIDDEN + tid];
    }
    __syncthreads();

    const int rem = blockIdx.x*256 + tid;
    const float* hp = h + (size_t)b*HIDDEN*HW + rem;

    ull acc[10];
#pragma unroll
    for (int q = 0; q < 10; q++) acc[q] = 0ull;
#pragma unroll 4
    for (int c = 0; c < HIDDEN; c++) {
        float z = hp[(size_t)c*HW]*sc[c] + sh[c];
        float a = z / (1.f + expf(-z));
        ull da; PACK2(da, a, a);
        const ull* wrow = (const ull*)&wsmT[c*10];
        ulonglong2 w01 = *(const ulonglong2*)(wrow + 0);
        ulonglong2 w23 = *(const ulonglong2*)(wrow + 2);
        ulonglong2 w45 = *(const ulonglong2*)(wrow + 4);
        ulonglong2 w67 = *(const ulonglong2*)(wrow + 6);
        ulonglong2 w89 = *(const ulonglong2*)(wrow + 8);
        FMA2(acc[0], w01.x, da); FMA2(acc[1], w01.y, da);
        FMA2(acc[2], w23.x, da); FMA2(acc[3], w23.y, da);
        FMA2(acc[4], w45.x, da); FMA2(acc[5], w45.y, da);
        FMA2(acc[6], w67.x, da); FMA2(acc[7], w67.y, da);
        FMA2(acc[8], w89.x, da); FMA2(acc[9], w89.y, da);
    }

    float ao[20];
#pragma unroll
    for (int q = 0; q < 10; q++) UNPACK2(ao[2*q], ao[2*q+1], acc[q]);

    const int p = b*HW + rem;
    float t = ao[0] + bia[0] + dm[p];
    out[p] = fmaxf(t, 0.f) + log1pf(expf(-fabsf(t)));
    out[BHW   + p] = sxp[p] + (ao[1] + bia[1])*0.1f;
    out[2*BHW + p] = syp[p] + (ao[2] + bia[2])*0.1f;
#pragma unroll
    for (int j = 0; j < TFn; j++) {
        size_t fi = ((size_t)b*TFn + j)*HW + rem;
        out[3*(size_t)BHW + fi] = feat[fi] + ao[4+j] + bia[4+j];
    }
    float cz = ao[3] + bia[3] + 2.f*conf[p] - 1.f;
    out[19*(size_t)BHW + p] = 1.f / (1.f + expf(-cz));
}

// ---------------------------------------------------------------------------
extern "C" void kernel_launch(void* const* d_in, const int* in_sizes, int n_in,
                              void* d_out, int out_size)
{
    const float* dm   = (const float*)d_in[0];
    const float* sx   = (const float*)d_in[1];
    const float* sy   = (const float*)d_in[2];
    const float* feat = (const float*)d_in[3];
    const float* conf = (const float*)d_in[4];
    const float* fL   = (const float*)d_in[5];
    const float* fR   = (const float*)d_in[6];
    const float* w1   = (const float*)d_in[7];
    const float* w2   = (const float*)d_in[8];
    const float* w3   = (const float*)d_in[9];
    const float* g1g  = (const float*)d_in[10];
    const float* g1b  = (const float*)d_in[11];
    const float* g2g  = (const float*)d_in[12];
    const float* g2b  = (const float*)d_in[13];
    const float* g3g  = (const float*)d_in[14];
    const float* g3b  = (const float*)d_in[15];
    const float* hd_w  = (const float*)d_in[16];
    const float* hd_b  = (const float*)d_in[17];
    const float* hsx_w = (const float*)d_in[18];
    const float* hsx_b = (const float*)d_in[19];
    const float* hsy_w = (const float*)d_in[20];
    const float* hsy_b = (const float*)d_in[21];
    const float* hc_w  = (const float*)d_in[22];
    const float* hc_b  = (const float*)d_in[23];
    const float* hf_w  = (const float*)d_in[24];
    const float* hf_b  = (const float*)d_in[25];
    float* out = (float*)d_out;

    float *px, *ph1, *ph2;
    cudaGetSymbolAddress((void**)&px,  g_x);
    cudaGetSymbolAddress((void**)&ph1, g_h1);
    cudaGetSymbolAddress((void**)&ph2, g_h2);

    const dim3 cgrid(Wn/64, Hn/8, Bn);   // (10, 40, 2)
    const dim3 rgrid(Bn*HIDDEN, 8);      // (96, 8)
    const dim3 hgrid(HW/256, Bn);        // (800, 2)

    build_x_kernel<<<Bn*Hn, Wn>>>(dm, sx, sy, feat, conf, fL, fR);

    conv3x3_v3<IN_CH, false><<<cgrid, 256>>>(px, w1, ph1);
    zero_stats_kernel<<<1, 64>>>();
    gn_reduce_kernel<<<rgrid, 256>>>(ph1);
    finalize_stats_kernel<<<1, 96>>>(g1g, g1b);

    conv3x3_v3<HIDDEN, true><<<cgrid, 256>>>(ph1, w2, ph2);
    zero_stats_kernel<<<1, 64>>>();
    gn_reduce_kernel<<<rgrid, 256>>>(ph2);
    finalize_stats_kernel<<<1, 96>>>(g2g, g2b);

    conv3x3_v3<HIDDEN, true><<<cgrid, 256>>>(ph2, w3, ph1);
    zero_stats_kernel<<<1, 64>>>();
    gn_reduce_kernel<<<rgrid, 256>>>(ph1);
    finalize_stats_kernel<<<1, 96>>>(g3g, g3b);

    heads_kernel<<<hgrid, 256>>>(ph1,
                                 dm, sx, sy, feat, conf,
                                 hd_w, hd_b, hsx_w, hsx_b, hsy_w, hsy_b,
                                 hc_w, hc_b, hf_w, hf_b, out);
}

// round 7
// speedup vs baseline: 2.5521x; 1.5232x over previous
#include <cuda_runtime.h>
#include <math.h>
#include <stdint.h>

#define Bn 2
#define Cn 64
#define Hn 320
#define Wn 640
#define TFn 16
#define HIDDEN 48
#define GROUPS 8
#define CPG 6
#define IN_CH 188
#define HW (Hn*Wn)
#define GN_N (CPG*HW)
#define BHW (Bn*HW)

typedef unsigned long long ull;

// Blackwell packed-f32 FMA (PTX-only; ptxas never emits from C++).
#define PACK2(d, lo, hi) asm("mov.b64 %0, {%1,%2};" : "=l"(d) : "f"(lo), "f"(hi))
#define UNPACK2(lo, hi, v) asm("mov.b64 {%0,%1}, %2;" : "=f"(lo), "=f"(hi) : "l"(v))
#define FMA2(acc, a, b)  asm("fma.rn.f32x2 %0, %1, %2, %0;" : "+l"(acc) : "l"(a), "l"(b))

// ---------------- scratch ----------------
__device__ float  g_x [Bn*IN_CH*HW];
__device__ float  g_h1[Bn*HIDDEN*HW];
__device__ float  g_h2[Bn*HIDDEN*HW];
__device__ double g_stats[Bn*GROUPS*2];
__device__ float  g_scale[Bn*HIDDEN];
__device__ float  g_shift[Bn*HIDDEN];
// repacked weights: [ci][pair p=q*9+k] float2 = (w[2q][ci][k], w[2q+1][ci][k])
__device__ float2 g_w1p[IN_CH*216];
__device__ float2 g_w2p[HIDDEN*216];
__device__ float2 g_w3p[HIDDEN*216];

// ---------------------------------------------------------------------------
// Weight repack: [o][ci][k] -> [ci][pair] (216 pairs = 24 q x 9 taps)
// ---------------------------------------------------------------------------
template<int IN>
__global__ void repack_w_kernel(const float* __restrict__ w, float2* __restrict__ d)
{
    int idx = blockIdx.x*256 + threadIdx.x;
    if (idx >= IN*216) return;
    int ci = idx/216, p = idx%216, q = p/9, k = p%9;
    d[idx] = make_float2(w[((size_t)(2*q  )*IN + ci)*9 + k],
                         w[((size_t)(2*q+1)*IN + ci)*9 + k]);
}

// ---------------------------------------------------------------------------
// Kernel 1: build x = concat(fL, warp(fR,d), feat, d, sx, sy, conf, corr)
// ---------------------------------------------------------------------------
__global__ void __launch_bounds__(Wn) build_x_kernel(
    const float* __restrict__ dm, const float* __restrict__ sx,
    const float* __restrict__ sy, const float* __restrict__ feat,
    const float* __restrict__ conf, const float* __restrict__ fL,
    const float* __restrict__ fR)
{
    __shared__ float srow[8*Wn];
    const int b = blockIdx.x / Hn;
    const int y = blockIdx.x % Hn;
    const int x = threadIdx.x;
    const int prow = b*HW + y*Wn;

    const float dval = dm[prow + x];
    int i0[5], i1[5]; float fr[5];
#pragma unroll
    for (int i = 0; i < 5; i++) {
        float xs = (float)x - dval - (float)(i-2);
        xs = fminf(fmaxf(xs, 0.f), (float)(Wn-1));
        float f0 = floorf(xs);
        i0[i] = (int)f0;
        fr[i] = xs - f0;
        i1[i] = min(i0[i]+1, Wn-1);
    }

    float* xb = g_x + (size_t)b*IN_CH*HW + (size_t)y*Wn + x;
    const float* fLp = fL + (size_t)b*Cn*HW + (size_t)y*Wn + x;
    const float* fRp = fR + (size_t)b*Cn*HW + (size_t)y*Wn;

    for (int g = 0; g < 8; g++) {
        __syncthreads();
#pragma unroll
        for (int j = 0; j < 8; j++)
            srow[j*Wn + x] = fRp[(size_t)(g*8+j)*HW + x];
        __syncthreads();

        float acc[5] = {0.f,0.f,0.f,0.f,0.f};
#pragma unroll
        for (int j = 0; j < 8; j++) {
            const int c = g*8 + j;
            const float fl = fLp[(size_t)c*HW];
            xb[(size_t)c*HW] = fl;
#pragma unroll
            for (int i = 0; i < 5; i++) {
                float v = srow[j*Wn+i0[i]]*(1.f-fr[i]) + srow[j*Wn+i1[i]]*fr[i];
                acc[i] += fl*v;
                if (i == 2) xb[(size_t)(64+c)*HW] = v;
            }
        }
#pragma unroll
        for (int i = 0; i < 5; i++)
            xb[(size_t)(148 + g*5 + i)*HW] = acc[i]*(1.f/8.f);
    }
#pragma unroll
    for (int j = 0; j < TFn; j++)
        xb[(size_t)(128+j)*HW] = feat[((size_t)b*TFn + j)*HW + y*Wn + x];
    xb[(size_t)144*HW] = dval;
    xb[(size_t)145*HW] = sx[prow + x];
    xb[(size_t)146*HW] = sy[prow + x];
    xb[(size_t)147*HW] = conf[prow + x];
}

// ---------------------------------------------------------------------------
// Kernel 2 v4: 3x3 conv, f32x2 FMA, 64x4 tile, 128 threads, 3 CTAs/SM.
// Two input channels per pipeline stage (one barrier per 2 channels).
// Weights from repacked [ci][pair] layout: 1 coalesced LDG.128/thread/channel.
// ---------------------------------------------------------------------------
template<int IN, bool HASGN>
__global__ void __launch_bounds__(128, 3) conv3x3_v4(
    const float* __restrict__ in, const float2* __restrict__ wp,
    float* __restrict__ out)
{
    __shared__ float ts[2][2][6*68];                  // [buf][ch][row*68]
    __shared__ __align__(16) float2 ws[2][2][24*10];  // [buf][ch][q*10+k]

    const int tid = threadIdx.x;
    const int tx = tid & 31, ty = tid >> 5;           // 32 x-pairs, 4 rows
    const int x0 = blockIdx.x*64, y0 = blockIdx.y*4;
    const int b  = blockIdx.z;

    const float* inb = in + (size_t)b*IN*HW;
    const float* scb = g_scale + b*HIDDEN;
    const float* shb = g_shift + b*HIDDEN;

    // tile-load slots (4 per thread; 396 = 6 rows x 66 cols)
    int   toff[4], soff[4];
    bool  timg[4], tin[4];
#pragma unroll
    for (int j = 0; j < 4; j++) {
        int idx = tid + j*128;
        int r = idx/66, c = idx%66;
        int gy = y0-1+r, gx = x0-1+c;
        tin[j]  = (idx < 396);
        timg[j] = tin[j] && gy >= 0 && gy < Hn && gx >= 0 && gx < Wn;
        toff[j] = timg[j] ? gy*Wn + gx : 0;
        soff[j] = r*68 + c;
    }
    // weight slot: tid<108 loads one float4 (= pairs 2*tid, 2*tid+1)
    const bool wact = tid < 108;
    const int p0 = 2*tid, p1 = 2*tid + 1;
    const int wd0 = (p0/9)*10 + p0%9;
    const int wd1 = (p1/9)*10 + p1%9;
    const float4* wp4 = (const float4*)wp;

    ull acc[48];
#pragma unroll
    for (int i = 0; i < 48; i++) acc[i] = 0ull;

    // ---- prologue: stage 0 (channels 0,1) ----
#pragma unroll
    for (int c2 = 0; c2 < 2; c2++) {
        float sc = 1.f, sh = 0.f;
        if (HASGN) { sc = scb[c2]; sh = shb[c2]; }
        const float* ip = inb + (size_t)c2*HW;
#pragma unroll
        for (int j = 0; j < 4; j++) {
            if (tin[j]) {
                float v = 0.f;
                if (timg[j]) {
                    v = ip[toff[j]];
                    if (HASGN) { float z = v*sc + sh; v = z / (1.f + expf(-z)); }
                }
                ts[0][c2][soff[j]] = v;
            }
        }
        if (wact) {
            float4 w = wp4[(size_t)c2*108 + tid];
            ws[0][c2][wd0] = make_float2(w.x, w.y);
            ws[0][c2][wd1] = make_float2(w.z, w.w);
        }
    }
    __syncthreads();

    const int NST = IN/2;
    int cur = 0;
#pragma unroll 1
    for (int s = 0; s < NST; s++) {
        // ---- prefetch stage s+1 into registers ----
        float tv[2][4];
        float4 wv[2];
        float psc[2], psh[2];
        const bool more = (s + 1 < NST);
        if (more) {
#pragma unroll
            for (int c2 = 0; c2 < 2; c2++) {
                const int ci = 2*(s+1) + c2;
                const float* ip = inb + (size_t)ci*HW;
#pragma unroll
                for (int j = 0; j < 4; j++)
                    tv[c2][j] = timg[j] ? ip[toff[j]] : 0.f;
                if (wact) wv[c2] = wp4[(size_t)ci*108 + tid];
                if (HASGN) { psc[c2] = scb[ci]; psh[c2] = shb[ci]; }
            }
        }

        // ---- compute both channels of current stage ----
#pragma unroll
        for (int c2 = 0; c2 < 2; c2++) {
            ull dv[12];
            {
                const float* base = &ts[cur][c2][ty*68 + 2*tx];
                float2 a0 = *(const float2*)(base + 0);
                float2 a1 = *(const float2*)(base + 2);
                float2 b0 = *(const float2*)(base + 68);
                float2 b1 = *(const float2*)(base + 70);
                float2 c0 = *(const float2*)(base + 136);
                float2 c1 = *(const float2*)(base + 138);
                PACK2(dv[0], a0.x, a0.x); PACK2(dv[1],  a0.y, a0.y);
                PACK2(dv[2], a1.x, a1.x); PACK2(dv[3],  a1.y, a1.y);
                PACK2(dv[4], b0.x, b0.x); PACK2(dv[5],  b0.y, b0.y);
                PACK2(dv[6], b1.x, b1.x); PACK2(dv[7],  b1.y, b1.y);
                PACK2(dv[8], c0.x, c0.x); PACK2(dv[9],  c0.y, c0.y);
                PACK2(dv[10],c1.x, c1.x); PACK2(dv[11], c1.y, c1.y);
            }
#pragma unroll
            for (int q = 0; q < 24; q++) {
                const ull* wrow = (const ull*)&ws[cur][c2][q*10];
                ulonglong2 w01 = *(const ulonglong2*)(wrow + 0);
                ulonglong2 w23 = *(const ulonglong2*)(wrow + 2);
                ulonglong2 w45 = *(const ulonglong2*)(wrow + 4);
                ulonglong2 w67 = *(const ulonglong2*)(wrow + 6);
                ull w8 = wrow[8];
                ull a0 = acc[2*q], a1 = acc[2*q+1];
                FMA2(a0, w01.x, dv[0]);  FMA2(a1, w01.x, dv[1]);
                FMA2(a0, w01.y, dv[1]);  FMA2(a1, w01.y, dv[2]);
                FMA2(a0, w23.x, dv[2]);  FMA2(a1, w23.x, dv[3]);
                FMA2(a0, w23.y, dv[4]);  FMA2(a1, w23.y, dv[5]);
                FMA2(a0, w45.x, dv[5]);  FMA2(a1, w45.x, dv[6]);
                FMA2(a0, w45.y, dv[6]);  FMA2(a1, w45.y, dv[7]);
                FMA2(a0, w67.x, dv[8]);  FMA2(a1, w67.x, dv[9]);
                FMA2(a0, w67.y, dv[9]);  FMA2(a1, w67.y, dv[10]);
                FMA2(a0, w8,    dv[10]); FMA2(a1, w8,    dv[11]);
                acc[2*q] = a0; acc[2*q+1] = a1;
            }
        }

        // ---- stage prefetched data ----
        if (more) {
            const int nb = cur ^ 1;
#pragma unroll
            for (int c2 = 0; c2 < 2; c2++) {
#pragma unroll
                for (int j = 0; j < 4; j++) {
                    if (tin[j]) {
                        float v = tv[c2][j];
                        if (HASGN && timg[j]) {
                            float z = v*psc[c2] + psh[c2];
                            v = z / (1.f + expf(-z));
                        }
                        ts[nb][c2][soff[j]] = v;
                    }
                }
                if (wact) {
                    ws[nb][c2][wd0] = make_float2(wv[c2].x, wv[c2].y);
                    ws[nb][c2][wd1] = make_float2(wv[c2].z, wv[c2].w);
                }
            }
        }
        __syncthreads();
        cur ^= 1;
    }

    float* op = out + (size_t)b*HIDDEN*HW + (size_t)(y0+ty)*Wn + (x0 + 2*tx);
#pragma unroll
    for (int q = 0; q < 24; q++) {
        float p0o0, p0o1, p1o0, p1o1;
        UNPACK2(p0o0, p0o1, acc[2*q]);
        UNPACK2(p1o0, p1o1, acc[2*q+1]);
        *(float2*)&op[(size_t)(2*q  )*HW] = make_float2(p0o0, p1o0);
        *(float2*)&op[(size_t)(2*q+1)*HW] = make_float2(p0o1, p1o1);
    }
}

// ---------------------------------------------------------------------------
// GN stats
// ---------------------------------------------------------------------------
__global__ void zero_stats_kernel() {
    if (threadIdx.x < Bn*GROUPS*2) g_stats[threadIdx.x] = 0.0;
}

__global__ void __launch_bounds__(256) gn_reduce_kernel(const float* __restrict__ h)
{
    const int bc = blockIdx.x;
    const int slice = blockIdx.y;
    const float4* p = (const float4*)(h + (size_t)bc*HW) + slice*6400 + threadIdx.x;

    float s0=0.f,s1=0.f,s2=0.f,s3=0.f;
    float q0=0.f,q1=0.f,q2=0.f,q3=0.f;
#pragma unroll
    for (int k = 0; k < 25; k++) {
        float4 f = p[k*256];
        s0 += f.x; s1 += f.y; s2 += f.z; s3 += f.w;
        q0 += f.x*f.x; q1 += f.y*f.y; q2 += f.z*f.z; q3 += f.w*f.w;
    }
    double s = ((double)s0 + s1) + ((double)s2 + s3);
    double q = ((double)q0 + q1) + ((double)q2 + q3);
#pragma unroll
    for (int o = 16; o > 0; o >>= 1) {
        s += __shfl_down_sync(0xFFFFFFFFu, s, o);
        q += __shfl_down_sync(0xFFFFFFFFu, q, o);
    }
    __shared__ double ss[8], qq[8];
    if ((threadIdx.x & 31) == 0) { ss[threadIdx.x>>5] = s; qq[threadIdx.x>>5] = q; }
    __syncthreads();
    if (threadIdx.x == 0) {
        double S = 0.0, Q = 0.0;
#pragma unroll
        for (int w = 0; w < 8; w++) { S += ss[w]; Q += qq[w]; }
        const int b = bc / HIDDEN, c = bc % HIDDEN, g = c / CPG;
        atomicAdd(&g_stats[(b*GROUPS+g)*2+0], S);
        atomicAdd(&g_stats[(b*GROUPS+g)*2+1], Q);
    }
}

__global__ void finalize_stats_kernel(const float* __restrict__ gamma,
                                      const float* __restrict__ beta)
{
    const int i = threadIdx.x;
    if (i >= Bn*HIDDEN) return;
    const int b = i / HIDDEN, c = i % HIDDEN, g = c / CPG;
    double s = g_stats[(b*GROUPS+g)*2+0];
    double q = g_stats[(b*GROUPS+g)*2+1];
    double mean = s / (double)GN_N;
    double var  = q / (double)GN_N - mean*mean;
    float inv = (float)rsqrt(var + 1e-5);
    float sc = gamma[c]*inv;
    g_scale[i] = sc;
    g_shift[i] = beta[c] - (float)mean*sc;
}

// ---------------------------------------------------------------------------
// Kernel 3: fused GN3+SiLU + five 1x1 heads + epilogues (f32x2 output pairs).
// ---------------------------------------------------------------------------
__global__ void __launch_bounds__(256) heads_kernel(
    const float* __restrict__ h,
    const float* __restrict__ dm, const float* __restrict__ sxp,
    const float* __restrict__ syp, const float* __restrict__ feat,
    const float* __restrict__ conf,
    const float* __restrict__ hd_w,  const float* __restrict__ hd_b,
    const float* __restrict__ hsx_w, const float* __restrict__ hsx_b,
    const float* __restrict__ hsy_w, const float* __restrict__ hsy_b,
    const float* __restrict__ hc_w,  const float* __restrict__ hc_b,
    const float* __restrict__ hf_w,  const float* __restrict__ hf_b,
    float* __restrict__ out)
{
    __shared__ __align__(16) float2 wsmT[HIDDEN*10];
    __shared__ float bia[20];
    __shared__ float sc[HIDDEN], sh[HIDDEN];

    const int tid = threadIdx.x;
    const int b   = blockIdx.y;

    for (int idx = tid; idx < 10*HIDDEN; idx += 256) {
        int c = idx / 10, q = idx % 10;
        float w[2];
#pragma unroll
        for (int j = 0; j < 2; j++) {
            int o = 2*q + j;
            if (o == 0)      w[j] = hd_w[c];
            else if (o == 1) w[j] = hsx_w[c];
            else if (o == 2) w[j] = hsy_w[c];
            else if (o == 3) w[j] = hc_w[c];
            else             w[j] = hf_w[(o-4)*HIDDEN + c];
        }
        wsmT[idx] = make_float2(w[0], w[1]);
    }
    if (tid < 20) {
        bia[tid] = (tid==0) ? hd_b[0] : (tid==1) ? hsx_b[0] : (tid==2) ? hsy_b[0]
                 : (tid==3) ? hc_b[0] : hf_b[tid-4];
    }
    if (tid < HIDDEN) {
        sc[tid] = g_scale[b*HIDDEN + tid];
        sh[tid] = g_shift[b*HIDDEN + tid];
    }
    __syncthreads();

    const int rem = blockIdx.x*256 + tid;
    const float* hp = h + (size_t)b*HIDDEN*HW + rem;

    ull acc[10];
#pragma unroll
    for (int q = 0; q < 10; q++) acc[q] = 0ull;
#pragma unroll 4
    for (int c = 0; c < HIDDEN; c++) {
        float z = hp[(size_t)c*HW]*sc[c] + sh[c];
        float a = z / (1.f + expf(-z));
        ull da; PACK2(da, a, a);
        const ull* wrow = (const ull*)&wsmT[c*10];
        ulonglong2 w01 = *(const ulonglong2*)(wrow + 0);
        ulonglong2 w23 = *(const ulonglong2*)(wrow + 2);
        ulonglong2 w45 = *(const ulonglong2*)(wrow + 4);
        ulonglong2 w67 = *(const ulonglong2*)(wrow + 6);
        ulonglong2 w89 = *(const ulonglong2*)(wrow + 8);
        FMA2(acc[0], w01.x, da); FMA2(acc[1], w01.y, da);
        FMA2(acc[2], w23.x, da); FMA2(acc[3], w23.y, da);
        FMA2(acc[4], w45.x, da); FMA2(acc[5], w45.y, da);
        FMA2(acc[6], w67.x, da); FMA2(acc[7], w67.y, da);
        FMA2(acc[8], w89.x, da); FMA2(acc[9], w89.y, da);
    }

    float ao[20];
#pragma unroll
    for (int q = 0; q < 10; q++) UNPACK2(ao[2*q], ao[2*q+1], acc[q]);

    const int p = b*HW + rem;
    float t = ao[0] + bia[0] + dm[p];
    out[p] = fmaxf(t, 0.f) + log1pf(expf(-fabsf(t)));
    out[BHW   + p] = sxp[p] + (ao[1] + bia[1])*0.1f;
    out[2*BHW + p] = syp[p] + (ao[2] + bia[2])*0.1f;
#pragma unroll
    for (int j = 0; j < TFn; j++) {
        size_t fi = ((size_t)b*TFn + j)*HW + rem;
        out[3*(size_t)BHW + fi] = feat[fi] + ao[4+j] + bia[4+j];
    }
    float cz = ao[3] + bia[3] + 2.f*conf[p] - 1.f;
    out[19*(size_t)BHW + p] = 1.f / (1.f + expf(-cz));
}

// ---------------------------------------------------------------------------
extern "C" void kernel_launch(void* const* d_in, const int* in_sizes, int n_in,
                              void* d_out, int out_size)
{
    const float* dm   = (const float*)d_in[0];
    const float* sx   = (const float*)d_in[1];
    const float* sy   = (const float*)d_in[2];
    const float* feat = (const float*)d_in[3];
    const float* conf = (const float*)d_in[4];
    const float* fL   = (const float*)d_in[5];
    const float* fR   = (const float*)d_in[6];
    const float* w1   = (const float*)d_in[7];
    const float* w2   = (const float*)d_in[8];
    const float* w3   = (const float*)d_in[9];
    const float* g1g  = (const float*)d_in[10];
    const float* g1b  = (const float*)d_in[11];
    const float* g2g  = (const float*)d_in[12];
    const float* g2b  = (const float*)d_in[13];
    const float* g3g  = (const float*)d_in[14];
    const float* g3b  = (const float*)d_in[15];
    const float* hd_w  = (const float*)d_in[16];
    const float* hd_b  = (const float*)d_in[17];
    const float* hsx_w = (const float*)d_in[18];
    const float* hsx_b = (const float*)d_in[19];
    const float* hsy_w = (const float*)d_in[20];
    const float* hsy_b = (const float*)d_in[21];
    const float* hc_w  = (const float*)d_in[22];
    const float* hc_b  = (const float*)d_in[23];
    const float* hf_w  = (const float*)d_in[24];
    const float* hf_b  = (const float*)d_in[25];
    float* out = (float*)d_out;

    float *px, *ph1, *ph2;
    float2 *pw1, *pw2, *pw3;
    cudaGetSymbolAddress((void**)&px,  g_x);
    cudaGetSymbolAddress((void**)&ph1, g_h1);
    cudaGetSymbolAddress((void**)&ph2, g_h2);
    cudaGetSymbolAddress((void**)&pw1, g_w1p);
    cudaGetSymbolAddress((void**)&pw2, g_w2p);
    cudaGetSymbolAddress((void**)&pw3, g_w3p);

    const dim3 cgrid(Wn/64, Hn/4, Bn);   // (10, 80, 2)
    const dim3 rgrid(Bn*HIDDEN, 8);      // (96, 8)
    const dim3 hgrid(HW/256, Bn);        // (800, 2)

    // weight repacks (tiny; overlap with build_x on same stream order)
    repack_w_kernel<IN_CH><<<(IN_CH*216+255)/256, 256>>>(w1, pw1);
    repack_w_kernel<HIDDEN><<<(HIDDEN*216+255)/256, 256>>>(w2, pw2);
    repack_w_kernel<HIDDEN><<<(HIDDEN*216+255)/256, 256>>>(w3, pw3);

    build_x_kernel<<<Bn*Hn, Wn>>>(dm, sx, sy, feat, conf, fL, fR);

    conv3x3_v4<IN_CH, false><<<cgrid, 128>>>(px, pw1, ph1);
    zero_stats_kernel<<<1, 64>>>();
    gn_reduce_kernel<<<rgrid, 256>>>(ph1);
    finalize_stats_kernel<<<1, 96>>>(g1g, g1b);

    conv3x3_v4<HIDDEN, true><<<cgrid, 128>>>(ph1, pw2, ph2);
    zero_stats_kernel<<<1, 64>>>();
    gn_reduce_kernel<<<rgrid, 256>>>(ph2);
    finalize_stats_kernel<<<1, 96>>>(g2g, g2b);

    conv3x3_v4<HIDDEN, true><<<cgrid, 128>>>(ph2, pw3, ph1);
    zero_stats_kernel<<<1, 64>>>();
    gn_reduce_kernel<<<rgrid, 256>>>(ph1);
    finalize_stats_kernel<<<1, 96>>>(g3g, g3b);

    heads_kernel<<<hgrid, 256>>>(ph1,
                                 dm, sx, sy, feat, conf,
                                 hd_w, hd_b, hsx_w, hsx_b, hsy_w, hsy_b,
                                 hc_w, hc_b, hf_w, hf_b, out);
}

// round 8
// speedup vs baseline: 2.5551x; 1.0012x over previous
#include <cuda_runtime.h>
#include <math.h>
#include <stdint.h>

#define Bn 2
#define Cn 64
#define Hn 320
#define Wn 640
#define TFn 16
#define HIDDEN 48
#define GROUPS 8
#define CPG 6
#define IN_CH 188
#define HW (Hn*Wn)
#define GN_N (CPG*HW)
#define BHW (Bn*HW)

typedef unsigned long long ull;

// Blackwell packed-f32 FMA (PTX-only; ptxas never emits from C++).
#define PACK2(d, lo, hi) asm("mov.b64 %0, {%1,%2};" : "=l"(d) : "f"(lo), "f"(hi))
#define UNPACK2(lo, hi, v) asm("mov.b64 {%0,%1}, %2;" : "=f"(lo), "=f"(hi) : "l"(v))
#define FMA2(acc, a, b)  asm("fma.rn.f32x2 %0, %1, %2, %0;" : "+l"(acc) : "l"(a), "l"(b))

// ---------------- scratch ----------------
__device__ float  g_x [Bn*IN_CH*HW];
__device__ float  g_h1[Bn*HIDDEN*HW];
__device__ float  g_h2[Bn*HIDDEN*HW];
__device__ double g_stats[Bn*GROUPS*2];
__device__ float  g_scale[Bn*HIDDEN];
__device__ float  g_shift[Bn*HIDDEN];
// repacked weights: [ci][pair p=q*9+k] float2 = (w[2q][ci][k], w[2q+1][ci][k])
__device__ float2 g_w1p[IN_CH*216];
__device__ float2 g_w2p[HIDDEN*216];
__device__ float2 g_w3p[HIDDEN*216];

// ---------------------------------------------------------------------------
// Weight repack: [o][ci][k] -> [ci][pair] (216 pairs = 24 q x 9 taps)
// ---------------------------------------------------------------------------
template<int IN>
__global__ void repack_w_kernel(const float* __restrict__ w, float2* __restrict__ d)
{
    int idx = blockIdx.x*256 + threadIdx.x;
    if (idx >= IN*216) return;
    int ci = idx/216, p = idx%216, q = p/9, k = p%9;
    d[idx] = make_float2(w[((size_t)(2*q  )*IN + ci)*9 + k],
                         w[((size_t)(2*q+1)*IN + ci)*9 + k]);
}

// ---------------------------------------------------------------------------
// Kernel 1: build x = concat(fL, warp(fR,d), feat, d, sx, sy, conf, corr)
// ---------------------------------------------------------------------------
__global__ void __launch_bounds__(Wn) build_x_kernel(
    const float* __restrict__ dm, const float* __restrict__ sx,
    const float* __restrict__ sy, const float* __restrict__ feat,
    const float* __restrict__ conf, const float* __restrict__ fL,
    const float* __restrict__ fR)
{
    __shared__ float srow[8*Wn];
    const int b = blockIdx.x / Hn;
    const int y = blockIdx.x % Hn;
    const int x = threadIdx.x;
    const int prow = b*HW + y*Wn;

    const float dval = dm[prow + x];
    int i0[5], i1[5]; float fr[5];
#pragma unroll
    for (int i = 0; i < 5; i++) {
        float xs = (float)x - dval - (float)(i-2);
        xs = fminf(fmaxf(xs, 0.f), (float)(Wn-1));
        float f0 = floorf(xs);
        i0[i] = (int)f0;
        fr[i] = xs - f0;
        i1[i] = min(i0[i]+1, Wn-1);
    }

    float* xb = g_x + (size_t)b*IN_CH*HW + (size_t)y*Wn + x;
    const float* fLp = fL + (size_t)b*Cn*HW + (size_t)y*Wn + x;
    const float* fRp = fR + (size_t)b*Cn*HW + (size_t)y*Wn;

    for (int g = 0; g < 8; g++) {
        __syncthreads();
#pragma unroll
        for (int j = 0; j < 8; j++)
            srow[j*Wn + x] = fRp[(size_t)(g*8+j)*HW + x];
        __syncthreads();

        float acc[5] = {0.f,0.f,0.f,0.f,0.f};
#pragma unroll
        for (int j = 0; j < 8; j++) {
            const int c = g*8 + j;
            const float fl = fLp[(size_t)c*HW];
            xb[(size_t)c*HW] = fl;
#pragma unroll
            for (int i = 0; i < 5; i++) {
                float v = srow[j*Wn+i0[i]]*(1.f-fr[i]) + srow[j*Wn+i1[i]]*fr[i];
                acc[i] += fl*v;
                if (i == 2) xb[(size_t)(64+c)*HW] = v;
            }
        }
#pragma unroll
        for (int i = 0; i < 5; i++)
            xb[(size_t)(148 + g*5 + i)*HW] = acc[i]*(1.f/8.f);
    }
#pragma unroll
    for (int j = 0; j < TFn; j++)
        xb[(size_t)(128+j)*HW] = feat[((size_t)b*TFn + j)*HW + y*Wn + x];
    xb[(size_t)144*HW] = dval;
    xb[(size_t)145*HW] = sx[prow + x];
    xb[(size_t)146*HW] = sy[prow + x];
    xb[(size_t)147*HW] = conf[prow + x];
}

// ---------------------------------------------------------------------------
// Kernel 2 v4: 3x3 conv, f32x2 FMA, 64x4 tile, 128 threads, 3 CTAs/SM.
// Two input channels per pipeline stage (one barrier per 2 channels).
// Weights from repacked [ci][pair] layout: 1 coalesced LDG.128/thread/channel.
// ---------------------------------------------------------------------------
template<int IN, bool HASGN>
__global__ void __launch_bounds__(128, 3) conv3x3_v4(
    const float* __restrict__ in, const float2* __restrict__ wp,
    float* __restrict__ out)
{
    __shared__ float ts[2][2][6*68];                  // [buf][ch][row*68]
    __shared__ __align__(16) float2 ws[2][2][24*10];  // [buf][ch][q*10+k]

    const int tid = threadIdx.x;
    const int tx = tid & 31, ty = tid >> 5;           // 32 x-pairs, 4 rows
    const int x0 = blockIdx.x*64, y0 = blockIdx.y*4;
    const int b  = blockIdx.z;

    const float* inb = in + (size_t)b*IN*HW;
    const float* scb = g_scale + b*HIDDEN;
    const float* shb = g_shift + b*HIDDEN;

    // tile-load slots (4 per thread; 396 = 6 rows x 66 cols)
    int   toff[4], soff[4];
    bool  timg[4], tin[4];
#pragma unroll
    for (int j = 0; j < 4; j++) {
        int idx = tid + j*128;
        int r = idx/66, c = idx%66;
        int gy = y0-1+r, gx = x0-1+c;
        tin[j]  = (idx < 396);
        timg[j] = tin[j] && gy >= 0 && gy < Hn && gx >= 0 && gx < Wn;
        toff[j] = timg[j] ? gy*Wn + gx : 0;
        soff[j] = r*68 + c;
    }
    // weight slot: tid<108 loads one float4 (= pairs 2*tid, 2*tid+1)
    const bool wact = tid < 108;
    const int p0 = 2*tid, p1 = 2*tid + 1;
    const int wd0 = (p0/9)*10 + p0%9;
    const int wd1 = (p1/9)*10 + p1%9;
    const float4* wp4 = (const float4*)wp;

    ull acc[48];
#pragma unroll
    for (int i = 0; i < 48; i++) acc[i] = 0ull;

    // ---- prologue: stage 0 (channels 0,1) ----
#pragma unroll
    for (int c2 = 0; c2 < 2; c2++) {
        float sc = 1.f, sh = 0.f;
        if (HASGN) { sc = scb[c2]; sh = shb[c2]; }
        const float* ip = inb + (size_t)c2*HW;
#pragma unroll
        for (int j = 0; j < 4; j++) {
            if (tin[j]) {
                float v = 0.f;
                if (timg[j]) {
                    v = ip[toff[j]];
                    if (HASGN) { float z = v*sc + sh; v = z / (1.f + expf(-z)); }
                }
                ts[0][c2][soff[j]] = v;
            }
        }
        if (wact) {
            float4 w = wp4[(size_t)c2*108 + tid];
            ws[0][c2][wd0] = make_float2(w.x, w.y);
            ws[0][c2][wd1] = make_float2(w.z, w.w);
        }
    }
    __syncthreads();

    const int NST = IN/2;
    int cur = 0;
#pragma unroll 1
    for (int s = 0; s < NST; s++) {
        // ---- prefetch stage s+1 into registers ----
        float tv[2][4];
        float4 wv[2];
        float psc[2], psh[2];
        const bool more = (s + 1 < NST);
        if (more) {
#pragma unroll
            for (int c2 = 0; c2 < 2; c2++) {
                const int ci = 2*(s+1) + c2;
                const float* ip = inb + (size_t)ci*HW;
#pragma unroll
                for (int j = 0; j < 4; j++)
                    tv[c2][j] = timg[j] ? ip[toff[j]] : 0.f;
                if (wact) wv[c2] = wp4[(size_t)ci*108 + tid];
                if (HASGN) { psc[c2] = scb[ci]; psh[c2] = shb[ci]; }
            }
        }

        // ---- compute both channels of current stage ----
#pragma unroll
        for (int c2 = 0; c2 < 2; c2++) {
            ull dv[12];
            {
                const float* base = &ts[cur][c2][ty*68 + 2*tx];
                float2 a0 = *(const float2*)(base + 0);
                float2 a1 = *(const float2*)(base + 2);
                float2 b0 = *(const float2*)(base + 68);
                float2 b1 = *(const float2*)(base + 70);
                float2 c0 = *(const float2*)(base + 136);
                float2 c1 = *(const float2*)(base + 138);
                PACK2(dv[0], a0.x, a0.x); PACK2(dv[1],  a0.y, a0.y);
                PACK2(dv[2], a1.x, a1.x); PACK2(dv[3],  a1.y, a1.y);
                PACK2(dv[4], b0.x, b0.x); PACK2(dv[5],  b0.y, b0.y);
                PACK2(dv[6], b1.x, b1.x); PACK2(dv[7],  b1.y, b1.y);
                PACK2(dv[8], c0.x, c0.x); PACK2(dv[9],  c0.y, c0.y);
                PACK2(dv[10],c1.x, c1.x); PACK2(dv[11], c1.y, c1.y);
            }
#pragma unroll
            for (int q = 0; q < 24; q++) {
                const ull* wrow = (const ull*)&ws[cur][c2][q*10];
                ulonglong2 w01 = *(const ulonglong2*)(wrow + 0);
                ulonglong2 w23 = *(const ulonglong2*)(wrow + 2);
                ulonglong2 w45 = *(const ulonglong2*)(wrow + 4);
                ulonglong2 w67 = *(const ulonglong2*)(wrow + 6);
                ull w8 = wrow[8];
                ull a0 = acc[2*q], a1 = acc[2*q+1];
                FMA2(a0, w01.x, dv[0]);  FMA2(a1, w01.x, dv[1]);
                FMA2(a0, w01.y, dv[1]);  FMA2(a1, w01.y, dv[2]);
                FMA2(a0, w23.x, dv[2]);  FMA2(a1, w23.x, dv[3]);
                FMA2(a0, w23.y, dv[4]);  FMA2(a1, w23.y, dv[5]);
                FMA2(a0, w45.x, dv[5]);  FMA2(a1, w45.x, dv[6]);
                FMA2(a0, w45.y, dv[6]);  FMA2(a1, w45.y, dv[7]);
                FMA2(a0, w67.x, dv[8]);  FMA2(a1, w67.x, dv[9]);
                FMA2(a0, w67.y, dv[9]);  FMA2(a1, w67.y, dv[10]);
                FMA2(a0, w8,    dv[10]); FMA2(a1, w8,    dv[11]);
                acc[2*q] = a0; acc[2*q+1] = a1;
            }
        }

        // ---- stage prefetched data ----
        if (more) {
            const int nb = cur ^ 1;
#pragma unroll
            for (int c2 = 0; c2 < 2; c2++) {
#pragma unroll
                for (int j = 0; j < 4; j++) {
                    if (tin[j]) {
                        float v = tv[c2][j];
                        if (HASGN && timg[j]) {
                            float z = v*psc[c2] + psh[c2];
                            v = z / (1.f + expf(-z));
                        }
                        ts[nb][c2][soff[j]] = v;
                    }
                }
                if (wact) {
                    ws[nb][c2][wd0] = make_float2(wv[c2].x, wv[c2].y);
                    ws[nb][c2][wd1] = make_float2(wv[c2].z, wv[c2].w);
                }
            }
        }
        __syncthreads();
        cur ^= 1;
    }

    float* op = out + (size_t)b*HIDDEN*HW + (size_t)(y0+ty)*Wn + (x0 + 2*tx);
#pragma unroll
    for (int q = 0; q < 24; q++) {
        float p0o0, p0o1, p1o0, p1o1;
        UNPACK2(p0o0, p0o1, acc[2*q]);
        UNPACK2(p1o0, p1o1, acc[2*q+1]);
        *(float2*)&op[(size_t)(2*q  )*HW] = make_float2(p0o0, p1o0);
        *(float2*)&op[(size_t)(2*q+1)*HW] = make_float2(p0o1, p1o1);
    }
}

// ---------------------------------------------------------------------------
// GN stats
// ---------------------------------------------------------------------------
__global__ void zero_stats_kernel() {
    if (threadIdx.x < Bn*GROUPS*2) g_stats[threadIdx.x] = 0.0;
}

__global__ void __launch_bounds__(256) gn_reduce_kernel(const float* __restrict__ h)
{
    const int bc = blockIdx.x;
    const int slice = blockIdx.y;
    const float4* p = (const float4*)(h + (size_t)bc*HW) + slice*6400 + threadIdx.x;

    float s0=0.f,s1=0.f,s2=0.f,s3=0.f;
    float q0=0.f,q1=0.f,q2=0.f,q3=0.f;
#pragma unroll
    for (int k = 0; k < 25; k++) {
        float4 f = p[k*256];
        s0 += f.x; s1 += f.y; s2 += f.z; s3 += f.w;
        q0 += f.x*f.x; q1 += f.y*f.y; q2 += f.z*f.z; q3 += f.w*f.w;
    }
    double s = ((double)s0 + s1) + ((double)s2 + s3);
    double q = ((double)q0 + q1) + ((double)q2 + q3);
#pragma unroll
    for (int o = 16; o > 0; o >>= 1) {
        s += __shfl_down_sync(0xFFFFFFFFu, s, o);
        q += __shfl_down_sync(0xFFFFFFFFu, q, o);
    }
    __shared__ double ss[8], qq[8];
    if ((threadIdx.x & 31) == 0) { ss[threadIdx.x>>5] = s; qq[threadIdx.x>>5] = q; }
    __syncthreads();
    if (threadIdx.x == 0) {
        double S = 0.0, Q = 0.0;
#pragma unroll
        for (int w = 0; w < 8; w++) { S += ss[w]; Q += qq[w]; }
        const int b = bc / HIDDEN, c = bc % HIDDEN, g = c / CPG;
        atomicAdd(&g_stats[(b*GROUPS+g)*2+0], S);
        atomicAdd(&g_stats[(b*GROUPS+g)*2+1], Q);
    }
}

__global__ void finalize_stats_kernel(const float* __restrict__ gamma,
                                      const float* __restrict__ beta)
{
    const int i = threadIdx.x;
    if (i >= Bn*HIDDEN) return;
    const int b = i / HIDDEN, c = i % HIDDEN, g = c / CPG;
    double s = g_stats[(b*GROUPS+g)*2+0];
    double q = g_stats[(b*GROUPS+g)*2+1];
    double mean = s / (double)GN_N;
    double var  = q / (double)GN_N - mean*mean;
    float inv = (float)rsqrt(var + 1e-5);
    float sc = gamma[c]*inv;
    g_scale[i] = sc;
    g_shift[i] = beta[c] - (float)mean*sc;
}

// ---------------------------------------------------------------------------
// Kernel 3: fused GN3+SiLU + five 1x1 heads + epilogues (f32x2 output pairs).
// ---------------------------------------------------------------------------
__global__ void __launch_bounds__(256) heads_kernel(
    const float* __restrict__ h,
    const float* __restrict__ dm, const float* __restrict__ sxp,
    const float* __restrict__ syp, const float* __restrict__ feat,
    const float* __restrict__ conf,
    const float* __restrict__ hd_w,  const float* __restrict__ hd_b,
    const float* __restrict__ hsx_w, const float* __restrict__ hsx_b,
    const float* __restrict__ hsy_w, const float* __restrict__ hsy_b,
    const float* __restrict__ hc_w,  const float* __restrict__ hc_b,
    const float* __restrict__ hf_w,  const float* __restrict__ hf_b,
    float* __restrict__ out)
{
    __shared__ __align__(16) float2 wsmT[HIDDEN*10];
    __shared__ float bia[20];
    __shared__ float sc[HIDDEN], sh[HIDDEN];

    const int tid = threadIdx.x;
    const int b   = blockIdx.y;

    for (int idx = tid; idx < 10*HIDDEN; idx += 256) {
        int c = idx / 10, q = idx % 10;
        float w[2];
#pragma unroll
        for (int j = 0; j < 2; j++) {
            int o = 2*q + j;
            if (o == 0)      w[j] = hd_w[c];
            else if (o == 1) w[j] = hsx_w[c];
            else if (o == 2) w[j] = hsy_w[c];
            else if (o == 3) w[j] = hc_w[c];
            else             w[j] = hf_w[(o-4)*HIDDEN + c];
        }
        wsmT[idx] = make_float2(w[0], w[1]);
    }
    if (tid < 20) {
        bia[tid] = (tid==0) ? hd_b[0] : (tid==1) ? hsx_b[0] : (tid==2) ? hsy_b[0]
                 : (tid==3) ? hc_b[0] : hf_b[tid-4];
    }
    if (tid < HIDDEN) {
        sc[tid] = g_scale[b*HIDDEN + tid];
        sh[tid] = g_shift[b*HIDDEN + tid];
    }
    __syncthreads();

    const int rem = blockIdx.x*256 + tid;
    const float* hp = h + (size_t)b*HIDDEN*HW + rem;

    ull acc[10];
#pragma unroll
    for (int q = 0; q < 10; q++) acc[q] = 0ull;
#pragma unroll 4
    for (int c = 0; c < HIDDEN; c++) {
        float z = hp[(size_t)c*HW]*sc[c] + sh[c];
        float a = z / (1.f + expf(-z));
        ull da; PACK2(da, a, a);
        const ull* wrow = (const ull*)&wsmT[c*10];
        ulonglong2 w01 = *(const ulonglong2*)(wrow + 0);
        ulonglong2 w23 = *(const ulonglong2*)(wrow + 2);
        ulonglong2 w45 = *(const ulonglong2*)(wrow + 4);
        ulonglong2 w67 = *(const ulonglong2*)(wrow + 6);
        ulonglong2 w89 = *(const ulonglong2*)(wrow + 8);
        FMA2(acc[0], w01.x, da); FMA2(acc[1], w01.y, da);
        FMA2(acc[2], w23.x, da); FMA2(acc[3], w23.y, da);
        FMA2(acc[4], w45.x, da); FMA2(acc[5], w45.y, da);
        FMA2(acc[6], w67.x, da); FMA2(acc[7], w67.y, da);
        FMA2(acc[8], w89.x, da); FMA2(acc[9], w89.y, da);
    }

    float ao[20];
#pragma unroll
    for (int q = 0; q < 10; q++) UNPACK2(ao[2*q], ao[2*q+1], acc[q]);

    const int p = b*HW + rem;
    float t = ao[0] + bia[0] + dm[p];
    out[p] = fmaxf(t, 0.f) + log1pf(expf(-fabsf(t)));
    out[BHW   + p] = sxp[p] + (ao[1] + bia[1])*0.1f;
    out[2*BHW + p] = syp[p] + (ao[2] + bia[2])*0.1f;
#pragma unroll
    for (int j = 0; j < TFn; j++) {
        size_t fi = ((size_t)b*TFn + j)*HW + rem;
        out[3*(size_t)BHW + fi] = feat[fi] + ao[4+j] + bia[4+j];
    }
    float cz = ao[3] + bia[3] + 2.f*conf[p] - 1.f;
    out[19*(size_t)BHW + p] = 1.f / (1.f + expf(-cz));
}

// ---------------------------------------------------------------------------
extern "C" void kernel_launch(void* const* d_in, const int* in_sizes, int n_in,
                              void* d_out, int out_size)
{
    const float* dm   = (const float*)d_in[0];
    const float* sx   = (const float*)d_in[1];
    const float* sy   = (const float*)d_in[2];
    const float* feat = (const float*)d_in[3];
    const float* conf = (const float*)d_in[4];
    const float* fL   = (const float*)d_in[5];
    const float* fR   = (const float*)d_in[6];
    const float* w1   = (const float*)d_in[7];
    const float* w2   = (const float*)d_in[8];
    const float* w3   = (const float*)d_in[9];
    const float* g1g  = (const float*)d_in[10];
    const float* g1b  = (const float*)d_in[11];
    const float* g2g  = (const float*)d_in[12];
    const float* g2b  = (const float*)d_in[13];
    const float* g3g  = (const float*)d_in[14];
    const float* g3b  = (const float*)d_in[15];
    const float* hd_w  = (const float*)d_in[16];
    const float* hd_b  = (const float*)d_in[17];
    const float* hsx_w = (const float*)d_in[18];
    const float* hsx_b = (const float*)d_in[19];
    const float* hsy_w = (const float*)d_in[20];
    const float* hsy_b = (const float*)d_in[21];
    const float* hc_w  = (const float*)d_in[22];
    const float* hc_b  = (const float*)d_in[23];
    const float* hf_w  = (const float*)d_in[24];
    const float* hf_b  = (const float*)d_in[25];
    float* out = (float*)d_out;

    float *px, *ph1, *ph2;
    float2 *pw1, *pw2, *pw3;
    cudaGetSymbolAddress((void**)&px,  g_x);
    cudaGetSymbolAddress((void**)&ph1, g_h1);
    cudaGetSymbolAddress((void**)&ph2, g_h2);
    cudaGetSymbolAddress((void**)&pw1, g_w1p);
    cudaGetSymbolAddress((void**)&pw2, g_w2p);
    cudaGetSymbolAddress((void**)&pw3, g_w3p);

    const dim3 cgrid(Wn/64, Hn/4, Bn);   // (10, 80, 2)
    const dim3 rgrid(Bn*HIDDEN, 8);      // (96, 8)
    const dim3 hgrid(HW/256, Bn);        // (800, 2)

    // weight repacks (tiny; overlap with build_x on same stream order)
    repack_w_kernel<IN_CH><<<(IN_CH*216+255)/256, 256>>>(w1, pw1);
    repack_w_kernel<HIDDEN><<<(HIDDEN*216+255)/256, 256>>>(w2, pw2);
    repack_w_kernel<HIDDEN><<<(HIDDEN*216+255)/256, 256>>>(w3, pw3);

    build_x_kernel<<<Bn*Hn, Wn>>>(dm, sx, sy, feat, conf, fL, fR);

    conv3x3_v4<IN_CH, false><<<cgrid, 128>>>(px, pw1, ph1);
    zero_stats_kernel<<<1, 64>>>();
    gn_reduce_kernel<<<rgrid, 256>>>(ph1);
    finalize_stats_kernel<<<1, 96>>>(g1g, g1b);

    conv3x3_v4<HIDDEN, true><<<cgrid, 128>>>(ph1, pw2, ph2);
    zero_stats_kernel<<<1, 64>>>();
    gn_reduce_kernel<<<rgrid, 256>>>(ph2);
    finalize_stats_kernel<<<1, 96>>>(g2g, g2b);

    conv3x3_v4<HIDDEN, true><<<cgrid, 128>>>(ph2, pw3, ph1);
    zero_stats_kernel<<<1, 64>>>();
    gn_reduce_kernel<<<rgrid, 256>>>(ph1);
    finalize_stats_kernel<<<1, 96>>>(g3g, g3b);

    heads_kernel<<<hgrid, 256>>>(ph1,
                                 dm, sx, sy, feat, conf,
                                 hd_w, hd_b, hsx_w, hsx_b, hsy_w, hsy_b,
                                 hc_w, hc_b, hf_w, hf_b, out);
}

// round 9
// speedup vs baseline: 2.5552x; 1.0000x over previous
#include <cuda_runtime.h>
#include <math.h>
#include <stdint.h>

#define Bn 2
#define Cn 64
#define Hn 320
#define Wn 640
#define TFn 16
#define HIDDEN 48
#define GROUPS 8
#define CPG 6
#define IN_CH 188
#define HW (Hn*Wn)
#define GN_N (CPG*HW)
#define BHW (Bn*HW)

typedef unsigned long long ull;

// Blackwell packed-f32 FMA (PTX-only; ptxas never emits from C++).
#define PACK2(d, lo, hi) asm("mov.b64 %0, {%1,%2};" : "=l"(d) : "f"(lo), "f"(hi))
#define UNPACK2(lo, hi, v) asm("mov.b64 {%0,%1}, %2;" : "=f"(lo), "=f"(hi) : "l"(v))
#define FMA2(acc, a, b)  asm("fma.rn.f32x2 %0, %1, %2, %0;" : "+l"(acc) : "l"(a), "l"(b))

// ---------------- scratch ----------------
__device__ float  g_x [Bn*IN_CH*HW];
__device__ float  g_h1[Bn*HIDDEN*HW];
__device__ float  g_h2[Bn*HIDDEN*HW];
__device__ double g_stats[Bn*GROUPS*2];
__device__ float  g_scale[Bn*HIDDEN];
__device__ float  g_shift[Bn*HIDDEN];
// repacked weights: [ci][pair p=q*9+k] float2 = (w[2q][ci][k], w[2q+1][ci][k])
__device__ float2 g_w1p[IN_CH*216];
__device__ float2 g_w2p[HIDDEN*216];
__device__ float2 g_w3p[HIDDEN*216];

// ---------------------------------------------------------------------------
// Weight repack: [o][ci][k] -> [ci][pair] (216 pairs = 24 q x 9 taps)
// ---------------------------------------------------------------------------
template<int IN>
__global__ void repack_w_kernel(const float* __restrict__ w, float2* __restrict__ d)
{
    int idx = blockIdx.x*256 + threadIdx.x;
    if (idx >= IN*216) return;
    int ci = idx/216, p = idx%216, q = p/9, k = p%9;
    d[idx] = make_float2(w[((size_t)(2*q  )*IN + ci)*9 + k],
                         w[((size_t)(2*q+1)*IN + ci)*9 + k]);
}

// ---------------------------------------------------------------------------
// Kernel 1: build x = concat(fL, warp(fR,d), feat, d, sx, sy, conf, corr)
// ---------------------------------------------------------------------------
__global__ void __launch_bounds__(Wn) build_x_kernel(
    const float* __restrict__ dm, const float* __restrict__ sx,
    const float* __restrict__ sy, const float* __restrict__ feat,
    const float* __restrict__ conf, const float* __restrict__ fL,
    const float* __restrict__ fR)
{
    __shared__ float srow[8*Wn];
    const int b = blockIdx.x / Hn;
    const int y = blockIdx.x % Hn;
    const int x = threadIdx.x;
    const int prow = b*HW + y*Wn;

    const float dval = dm[prow + x];
    int i0[5], i1[5]; float fr[5];
#pragma unroll
    for (int i = 0; i < 5; i++) {
        float xs = (float)x - dval - (float)(i-2);
        xs = fminf(fmaxf(xs, 0.f), (float)(Wn-1));
        float f0 = floorf(xs);
        i0[i] = (int)f0;
        fr[i] = xs - f0;
        i1[i] = min(i0[i]+1, Wn-1);
    }

    float* xb = g_x + (size_t)b*IN_CH*HW + (size_t)y*Wn + x;
    const float* fLp = fL + (size_t)b*Cn*HW + (size_t)y*Wn + x;
    const float* fRp = fR + (size_t)b*Cn*HW + (size_t)y*Wn;

    for (int g = 0; g < 8; g++) {
        __syncthreads();
#pragma unroll
        for (int j = 0; j < 8; j++)
            srow[j*Wn + x] = fRp[(size_t)(g*8+j)*HW + x];
        __syncthreads();

        float acc[5] = {0.f,0.f,0.f,0.f,0.f};
#pragma unroll
        for (int j = 0; j < 8; j++) {
            const int c = g*8 + j;
            const float fl = fLp[(size_t)c*HW];
            xb[(size_t)c*HW] = fl;
#pragma unroll
            for (int i = 0; i < 5; i++) {
                float v = srow[j*Wn+i0[i]]*(1.f-fr[i]) + srow[j*Wn+i1[i]]*fr[i];
                acc[i] += fl*v;
                if (i == 2) xb[(size_t)(64+c)*HW] = v;
            }
        }
#pragma unroll
        for (int i = 0; i < 5; i++)
            xb[(size_t)(148 + g*5 + i)*HW] = acc[i]*(1.f/8.f);
    }
#pragma unroll
    for (int j = 0; j < TFn; j++)
        xb[(size_t)(128+j)*HW] = feat[((size_t)b*TFn + j)*HW + y*Wn + x];
    xb[(size_t)144*HW] = dval;
    xb[(size_t)145*HW] = sx[prow + x];
    xb[(size_t)146*HW] = sy[prow + x];
    xb[(size_t)147*HW] = conf[prow + x];
}

// ---------------------------------------------------------------------------
// Kernel 2 v4: 3x3 conv, f32x2 FMA, 64x4 tile, 128 threads, 3 CTAs/SM.
// Two input channels per pipeline stage (one barrier per 2 channels).
// Weights from repacked [ci][pair] layout: 1 coalesced LDG.128/thread/channel.
// ---------------------------------------------------------------------------
template<int IN, bool HASGN>
__global__ void __launch_bounds__(128, 3) conv3x3_v4(
    const float* __restrict__ in, const float2* __restrict__ wp,
    float* __restrict__ out)
{
    __shared__ float ts[2][2][6*68];                  // [buf][ch][row*68]
    __shared__ __align__(16) float2 ws[2][2][24*10];  // [buf][ch][q*10+k]

    const int tid = threadIdx.x;
    const int tx = tid & 31, ty = tid >> 5;           // 32 x-pairs, 4 rows
    const int x0 = blockIdx.x*64, y0 = blockIdx.y*4;
    const int b  = blockIdx.z;

    const float* inb = in + (size_t)b*IN*HW;
    const float* scb = g_scale + b*HIDDEN;
    const float* shb = g_shift + b*HIDDEN;

    // tile-load slots (4 per thread; 396 = 6 rows x 66 cols)
    int   toff[4], soff[4];
    bool  timg[4], tin[4];
#pragma unroll
    for (int j = 0; j < 4; j++) {
        int idx = tid + j*128;
        int r = idx/66, c = idx%66;
        int gy = y0-1+r, gx = x0-1+c;
        tin[j]  = (idx < 396);
        timg[j] = tin[j] && gy >= 0 && gy < Hn && gx >= 0 && gx < Wn;
        toff[j] = timg[j] ? gy*Wn + gx : 0;
        soff[j] = r*68 + c;
    }
    // weight slot: tid<108 loads one float4 (= pairs 2*tid, 2*tid+1)
    const bool wact = tid < 108;
    const int p0 = 2*tid, p1 = 2*tid + 1;
    const int wd0 = (p0/9)*10 + p0%9;
    const int wd1 = (p1/9)*10 + p1%9;
    const float4* wp4 = (const float4*)wp;

    ull acc[48];
#pragma unroll
    for (int i = 0; i < 48; i++) acc[i] = 0ull;

    // ---- prologue: stage 0 (channels 0,1) ----
#pragma unroll
    for (int c2 = 0; c2 < 2; c2++) {
        float sc = 1.f, sh = 0.f;
        if (HASGN) { sc = scb[c2]; sh = shb[c2]; }
        const float* ip = inb + (size_t)c2*HW;
#pragma unroll
        for (int j = 0; j < 4; j++) {
            if (tin[j]) {
                float v = 0.f;
                if (timg[j]) {
                    v = ip[toff[j]];
                    if (HASGN) { float z = v*sc + sh; v = z / (1.f + expf(-z)); }
                }
                ts[0][c2][soff[j]] = v;
            }
        }
        if (wact) {
            float4 w = wp4[(size_t)c2*108 + tid];
            ws[0][c2][wd0] = make_float2(w.x, w.y);
            ws[0][c2][wd1] = make_float2(w.z, w.w);
        }
    }
    __syncthreads();

    const int NST = IN/2;
    int cur = 0;
#pragma unroll 1
    for (int s = 0; s < NST; s++) {
        // ---- prefetch stage s+1 into registers ----
        float tv[2][4];
        float4 wv[2];
        float psc[2], psh[2];
        const bool more = (s + 1 < NST);
        if (more) {
#pragma unroll
            for (int c2 = 0; c2 < 2; c2++) {
                const int ci = 2*(s+1) + c2;
                const float* ip = inb + (size_t)ci*HW;
#pragma unroll
                for (int j = 0; j < 4; j++)
                    tv[c2][j] = timg[j] ? ip[toff[j]] : 0.f;
                if (wact) wv[c2] = wp4[(size_t)ci*108 + tid];
                if (HASGN) { psc[c2] = scb[ci]; psh[c2] = shb[ci]; }
            }
        }

        // ---- compute both channels of current stage ----
#pragma unroll
        for (int c2 = 0; c2 < 2; c2++) {
            ull dv[12];
            {
                const float* base = &ts[cur][c2][ty*68 + 2*tx];
                float2 a0 = *(const float2*)(base + 0);
                float2 a1 = *(const float2*)(base + 2);
                float2 b0 = *(const float2*)(base + 68);
                float2 b1 = *(const float2*)(base + 70);
                float2 c0 = *(const float2*)(base + 136);
                float2 c1 = *(const float2*)(base + 138);
                PACK2(dv[0], a0.x, a0.x); PACK2(dv[1],  a0.y, a0.y);
                PACK2(dv[2], a1.x, a1.x); PACK2(dv[3],  a1.y, a1.y);
                PACK2(dv[4], b0.x, b0.x); PACK2(dv[5],  b0.y, b0.y);
                PACK2(dv[6], b1.x, b1.x); PACK2(dv[7],  b1.y, b1.y);
                PACK2(dv[8], c0.x, c0.x); PACK2(dv[9],  c0.y, c0.y);
                PACK2(dv[10],c1.x, c1.x); PACK2(dv[11], c1.y, c1.y);
            }
#pragma unroll
            for (int q = 0; q < 24; q++) {
                const ull* wrow = (const ull*)&ws[cur][c2][q*10];
                ulonglong2 w01 = *(const ulonglong2*)(wrow + 0);
                ulonglong2 w23 = *(const ulonglong2*)(wrow + 2);
                ulonglong2 w45 = *(const ulonglong2*)(wrow + 4);
                ulonglong2 w67 = *(const ulonglong2*)(wrow + 6);
                ull w8 = wrow[8];
                ull a0 = acc[2*q], a1 = acc[2*q+1];
                FMA2(a0, w01.x, dv[0]);  FMA2(a1, w01.x, dv[1]);
                FMA2(a0, w01.y, dv[1]);  FMA2(a1, w01.y, dv[2]);
                FMA2(a0, w23.x, dv[2]);  FMA2(a1, w23.x, dv[3]);
                FMA2(a0, w23.y, dv[4]);  FMA2(a1, w23.y, dv[5]);
                FMA2(a0, w45.x, dv[5]);  FMA2(a1, w45.x, dv[6]);
                FMA2(a0, w45.y, dv[6]);  FMA2(a1, w45.y, dv[7]);
                FMA2(a0, w67.x, dv[8]);  FMA2(a1, w67.x, dv[9]);
                FMA2(a0, w67.y, dv[9]);  FMA2(a1, w67.y, dv[10]);
                FMA2(a0, w8,    dv[10]); FMA2(a1, w8,    dv[11]);
                acc[2*q] = a0; acc[2*q+1] = a1;
            }
        }

        // ---- stage prefetched data ----
        if (more) {
            const int nb = cur ^ 1;
#pragma unroll
            for (int c2 = 0; c2 < 2; c2++) {
#pragma unroll
                for (int j = 0; j < 4; j++) {
                    if (tin[j]) {
                        float v = tv[c2][j];
                        if (HASGN && timg[j]) {
                            float z = v*psc[c2] + psh[c2];
                            v = z / (1.f + expf(-z));
                        }
                        ts[nb][c2][soff[j]] = v;
                    }
                }
                if (wact) {
                    ws[nb][c2][wd0] = make_float2(wv[c2].x, wv[c2].y);
                    ws[nb][c2][wd1] = make_float2(wv[c2].z, wv[c2].w);
                }
            }
        }
        __syncthreads();
        cur ^= 1;
    }

    float* op = out + (size_t)b*HIDDEN*HW + (size_t)(y0+ty)*Wn + (x0 + 2*tx);
#pragma unroll
    for (int q = 0; q < 24; q++) {
        float p0o0, p0o1, p1o0, p1o1;
        UNPACK2(p0o0, p0o1, acc[2*q]);
        UNPACK2(p1o0, p1o1, acc[2*q+1]);
        *(float2*)&op[(size_t)(2*q  )*HW] = make_float2(p0o0, p1o0);
        *(float2*)&op[(size_t)(2*q+1)*HW] = make_float2(p0o1, p1o1);
    }
}

// ---------------------------------------------------------------------------
// GN stats
// ---------------------------------------------------------------------------
__global__ void zero_stats_kernel() {
    if (threadIdx.x < Bn*GROUPS*2) g_stats[threadIdx.x] = 0.0;
}

__global__ void __launch_bounds__(256) gn_reduce_kernel(const float* __restrict__ h)
{
    const int bc = blockIdx.x;
    const int slice = blockIdx.y;
    const float4* p = (const float4*)(h + (size_t)bc*HW) + slice*6400 + threadIdx.x;

    float s0=0.f,s1=0.f,s2=0.f,s3=0.f;
    float q0=0.f,q1=0.f,q2=0.f,q3=0.f;
#pragma unroll
    for (int k = 0; k < 25; k++) {
        float4 f = p[k*256];
        s0 += f.x; s1 += f.y; s2 += f.z; s3 += f.w;
        q0 += f.x*f.x; q1 += f.y*f.y; q2 += f.z*f.z; q3 += f.w*f.w;
    }
    double s = ((double)s0 + s1) + ((double)s2 + s3);
    double q = ((double)q0 + q1) + ((double)q2 + q3);
#pragma unroll
    for (int o = 16; o > 0; o >>= 1) {
        s += __shfl_down_sync(0xFFFFFFFFu, s, o);
        q += __shfl_down_sync(0xFFFFFFFFu, q, o);
    }
    __shared__ double ss[8], qq[8];
    if ((threadIdx.x & 31) == 0) { ss[threadIdx.x>>5] = s; qq[threadIdx.x>>5] = q; }
    __syncthreads();
    if (threadIdx.x == 0) {
        double S = 0.0, Q = 0.0;
#pragma unroll
        for (int w = 0; w < 8; w++) { S += ss[w]; Q += qq[w]; }
        const int b = bc / HIDDEN, c = bc % HIDDEN, g = c / CPG;
        atomicAdd(&g_stats[(b*GROUPS+g)*2+0], S);
        atomicAdd(&g_stats[(b*GROUPS+g)*2+1], Q);
    }
}

__global__ void finalize_stats_kernel(const float* __restrict__ gamma,
                                      const float* __restrict__ beta)
{
    const int i = threadIdx.x;
    if (i >= Bn*HIDDEN) return;
    const int b = i / HIDDEN, c = i % HIDDEN, g = c / CPG;
    double s = g_stats[(b*GROUPS+g)*2+0];
    double q = g_stats[(b*GROUPS+g)*2+1];
    double mean = s / (double)GN_N;
    double var  = q / (double)GN_N - mean*mean;
    float inv = (float)rsqrt(var + 1e-5);
    float sc = gamma[c]*inv;
    g_scale[i] = sc;
    g_shift[i] = beta[c] - (float)mean*sc;
}

// ---------------------------------------------------------------------------
// Kernel 3: fused GN3+SiLU + five 1x1 heads + epilogues (f32x2 output pairs).
// ---------------------------------------------------------------------------
__global__ void __launch_bounds__(256) heads_kernel(
    const float* __restrict__ h,
    const float* __restrict__ dm, const float* __restrict__ sxp,
    const float* __restrict__ syp, const float* __restrict__ feat,
    const float* __restrict__ conf,
    const float* __restrict__ hd_w,  const float* __restrict__ hd_b,
    const float* __restrict__ hsx_w, const float* __restrict__ hsx_b,
    const float* __restrict__ hsy_w, const float* __restrict__ hsy_b,
    const float* __restrict__ hc_w,  const float* __restrict__ hc_b,
    const float* __restrict__ hf_w,  const float* __restrict__ hf_b,
    float* __restrict__ out)
{
    __shared__ __align__(16) float2 wsmT[HIDDEN*10];
    __shared__ float bia[20];
    __shared__ float sc[HIDDEN], sh[HIDDEN];

    const int tid = threadIdx.x;
    const int b   = blockIdx.y;

    for (int idx = tid; idx < 10*HIDDEN; idx += 256) {
        int c = idx / 10, q = idx % 10;
        float w[2];
#pragma unroll
        for (int j = 0; j < 2; j++) {
            int o = 2*q + j;
            if (o == 0)      w[j] = hd_w[c];
            else if (o == 1) w[j] = hsx_w[c];
            else if (o == 2) w[j] = hsy_w[c];
            else if (o == 3) w[j] = hc_w[c];
            else             w[j] = hf_w[(o-4)*HIDDEN + c];
        }
        wsmT[idx] = make_float2(w[0], w[1]);
    }
    if (tid < 20) {
        bia[tid] = (tid==0) ? hd_b[0] : (tid==1) ? hsx_b[0] : (tid==2) ? hsy_b[0]
                 : (tid==3) ? hc_b[0] : hf_b[tid-4];
    }
    if (tid < HIDDEN) {
        sc[tid] = g_scale[b*HIDDEN + tid];
        sh[tid] = g_shift[b*HIDDEN + tid];
    }
    __syncthreads();

    const int rem = blockIdx.x*256 + tid;
    const float* hp = h + (size_t)b*HIDDEN*HW + rem;

    ull acc[10];
#pragma unroll
    for (int q = 0; q < 10; q++) acc[q] = 0ull;
#pragma unroll 4
    for (int c = 0; c < HIDDEN; c++) {
        float z = hp[(size_t)c*HW]*sc[c] + sh[c];
        float a = z / (1.f + expf(-z));
        ull da; PACK2(da, a, a);
        const ull* wrow = (const ull*)&wsmT[c*10];
        ulonglong2 w01 = *(const ulonglong2*)(wrow + 0);
        ulonglong2 w23 = *(const ulonglong2*)(wrow + 2);
        ulonglong2 w45 = *(const ulonglong2*)(wrow + 4);
        ulonglong2 w67 = *(const ulonglong2*)(wrow + 6);
        ulonglong2 w89 = *(const ulonglong2*)(wrow + 8);
        FMA2(acc[0], w01.x, da); FMA2(acc[1], w01.y, da);
        FMA2(acc[2], w23.x, da); FMA2(acc[3], w23.y, da);
        FMA2(acc[4], w45.x, da); FMA2(acc[5], w45.y, da);
        FMA2(acc[6], w67.x, da); FMA2(acc[7], w67.y, da);
        FMA2(acc[8], w89.x, da); FMA2(acc[9], w89.y, da);
    }

    float ao[20];
#pragma unroll
    for (int q = 0; q < 10; q++) UNPACK2(ao[2*q], ao[2*q+1], acc[q]);

    const int p = b*HW + rem;
    float t = ao[0] + bia[0] + dm[p];
    out[p] = fmaxf(t, 0.f) + log1pf(expf(-fabsf(t)));
    out[BHW   + p] = sxp[p] + (ao[1] + bia[1])*0.1f;
    out[2*BHW + p] = syp[p] + (ao[2] + bia[2])*0.1f;
#pragma unroll
    for (int j = 0; j < TFn; j++) {
        size_t fi = ((size_t)b*TFn + j)*HW + rem;
        out[3*(size_t)BHW + fi] = feat[fi] + ao[4+j] + bia[4+j];
    }
    float cz = ao[3] + bia[3] + 2.f*conf[p] - 1.f;
    out[19*(size_t)BHW + p] = 1.f / (1.f + expf(-cz));
}

// ---------------------------------------------------------------------------
extern "C" void kernel_launch(void* const* d_in, const int* in_sizes, int n_in,
                              void* d_out, int out_size)
{
    const float* dm   = (const float*)d_in[0];
    const float* sx   = (const float*)d_in[1];
    const float* sy   = (const float*)d_in[2];
    const float* feat = (const float*)d_in[3];
    const float* conf = (const float*)d_in[4];
    const float* fL   = (const float*)d_in[5];
    const float* fR   = (const float*)d_in[6];
    const float* w1   = (const float*)d_in[7];
    const float* w2   = (const float*)d_in[8];
    const float* w3   = (const float*)d_in[9];
    const float* g1g  = (const float*)d_in[10];
    const float* g1b  = (const float*)d_in[11];
    const float* g2g  = (const float*)d_in[12];
    const float* g2b  = (const float*)d_in[13];
    const float* g3g  = (const float*)d_in[14];
    const float* g3b  = (const float*)d_in[15];
    const float* hd_w  = (const float*)d_in[16];
    const float* hd_b  = (const float*)d_in[17];
    const float* hsx_w = (const float*)d_in[18];
    const float* hsx_b = (const float*)d_in[19];
    const float* hsy_w = (const float*)d_in[20];
    const float* hsy_b = (const float*)d_in[21];
    const float* hc_w  = (const float*)d_in[22];
    const float* hc_b  = (const float*)d_in[23];
    const float* hf_w  = (const float*)d_in[24];
    const float* hf_b  = (const float*)d_in[25];
    float* out = (float*)d_out;

    float *px, *ph1, *ph2;
    float2 *pw1, *pw2, *pw3;
    cudaGetSymbolAddress((void**)&px,  g_x);
    cudaGetSymbolAddress((void**)&ph1, g_h1);
    cudaGetSymbolAddress((void**)&ph2, g_h2);
    cudaGetSymbolAddress((void**)&pw1, g_w1p);
    cudaGetSymbolAddress((void**)&pw2, g_w2p);
    cudaGetSymbolAddress((void**)&pw3, g_w3p);

    const dim3 cgrid(Wn/64, Hn/4, Bn);   // (10, 80, 2)
    const dim3 rgrid(Bn*HIDDEN, 8);      // (96, 8)
    const dim3 hgrid(HW/256, Bn);        // (800, 2)

    // weight repacks (tiny; overlap with build_x on same stream order)
    repack_w_kernel<IN_CH><<<(IN_CH*216+255)/256, 256>>>(w1, pw1);
    repack_w_kernel<HIDDEN><<<(HIDDEN*216+255)/256, 256>>>(w2, pw2);
    repack_w_kernel<HIDDEN><<<(HIDDEN*216+255)/256, 256>>>(w3, pw3);

    build_x_kernel<<<Bn*Hn, Wn>>>(dm, sx, sy, feat, conf, fL, fR);

    conv3x3_v4<IN_CH, false><<<cgrid, 128>>>(px, pw1, ph1);
    zero_stats_kernel<<<1, 64>>>();
    gn_reduce_kernel<<<rgrid, 256>>>(ph1);
    finalize_stats_kernel<<<1, 96>>>(g1g, g1b);

    conv3x3_v4<HIDDEN, true><<<cgrid, 128>>>(ph1, pw2, ph2);
    zero_stats_kernel<<<1, 64>>>();
    gn_reduce_kernel<<<rgrid, 256>>>(ph2);
    finalize_stats_kernel<<<1, 96>>>(g2g, g2b);

    conv3x3_v4<HIDDEN, true><<<cgrid, 128>>>(ph2, pw3, ph1);
    zero_stats_kernel<<<1, 64>>>();
    gn_reduce_kernel<<<rgrid, 256>>>(ph1);
    finalize_stats_kernel<<<1, 96>>>(g3g, g3b);

    heads_kernel<<<hgrid, 256>>>(ph1,
                                 dm, sx, sy, feat, conf,
                                 hd_w, hd_b, hsx_w, hsx_b, hsy_w, hsy_b,
                                 hc_w, hc_b, hf_w, hf_b, out);
}

// round 11
// speedup vs baseline: 3.6901x; 1.4442x over previous
#include <cuda_runtime.h>
#include <cuda_bf16.h>
#include <math.h>
#include <stdint.h>

#define Bn 2
#define Cn 64
#define Hn 320
#define Wn 640
#define TFn 16
#define HIDDEN 48
#define GROUPS 8
#define CPG 6
#define IN_CH 188
#define XST 192
#define HW (Hn*Wn)
#define GN_N (CPG*HW)
#define BHW (Bn*HW)
#define NT2 (Bn*Hn*10)

typedef unsigned long long ull;

#define PACK2(d, lo, hi) asm("mov.b64 %0, {%1,%2};" : "=l"(d) : "f"(lo), "f"(hi))
#define UNPACK2(lo, hi, v) asm("mov.b64 {%0,%1}, %2;" : "=f"(lo), "=f"(hi) : "l"(v))
#define FMA2(acc, a, b)  asm("fma.rn.f32x2 %0, %1, %2, %0;" : "+l"(acc) : "l"(a), "l"(b))

// Ampere-era bf16 HMMA — available on baseline compute_103 (no 'a' needed).
#define MMA_BF16(c, a0,a1,a2,a3, b0,b1) \
  asm volatile("mma.sync.aligned.m16n8k16.row.col.f32.bf16.bf16.f32 " \
      "{%0,%1,%2,%3}, {%4,%5,%6,%7}, {%8,%9}, {%0,%1,%2,%3};" \
      : "+f"((c)[0]),"+f"((c)[1]),"+f"((c)[2]),"+f"((c)[3]) \
      : "r"(a0),"r"(a1),"r"(a2),"r"(a3), "r"(b0),"r"(b1))

__device__ __forceinline__ uint32_t split_pack(float v) {
    __nv_bfloat16 h = __float2bfloat16(v);
    __nv_bfloat16 l = __float2bfloat16(v - __bfloat162float(h));
    return (uint32_t)__bfloat16_as_ushort(h) | ((uint32_t)__bfloat16_as_ushort(l) << 16);
}
__device__ __forceinline__ uint32_t bf16hi(float a, float b) {  // pack bf16(a),bf16(b)
    return (uint32_t)__bfloat16_as_ushort(__float2bfloat16(a)) |
           ((uint32_t)__bfloat16_as_ushort(__float2bfloat16(b)) << 16);
}

// ---------------- scratch ----------------
__device__ __align__(16) uint32_t g_xs[(size_t)Bn*HW*XST];
__device__ __align__(16) uint32_t g_hs[(size_t)Bn*HW*HIDDEN];
__device__ float  g_h1[(size_t)Bn*HIDDEN*HW];
__device__ float  g_h2[(size_t)Bn*HIDDEN*HW];
__device__ double g_stats[Bn*GROUPS*2];
__device__ float  g_scale[Bn*HIDDEN];
__device__ float  g_shift[Bn*HIDDEN];
// B fragments: [tap][chunk][ks][nb][lane] -> uint4 {bhi0,bhi1,blo0,blo1}
__device__ uint4 g_Bf1[9*4*3*6*32];
__device__ uint4 g_Bf2[9*1*3*6*32];
__device__ uint4 g_Bf3[9*1*3*6*32];

// ---------------- B fragment repack ----------------
template<int IN, int NCHUNK>
__global__ void repack_frag_kernel(const float* __restrict__ w, uint4* __restrict__ dst)
{
    int idx = blockIdx.x*256 + threadIdx.x;
    if (idx >= 9*NCHUNK*3*6*32) return;
    int lane = idx & 31, t = idx >> 5;
    int nb = t % 6; t /= 6;
    int ks = t % 3; t /= 3;
    int chunk = t % NCHUNK;
    int tap = t / NCHUNK;
    int n  = nb*8 + (lane >> 2);
    int k0 = chunk*48 + ks*16 + (lane & 3)*2;
    float v[4];
#pragma unroll
    for (int j = 0; j < 4; j++) {
        int k = k0 + ((j >> 1) ? 8 : 0) + (j & 1);
        v[j] = (k < IN) ? w[((size_t)n*IN + k)*9 + tap] : 0.f;
    }
    float h0 = __bfloat162float(__float2bfloat16(v[0]));
    float h1 = __bfloat162float(__float2bfloat16(v[1]));
    float h2 = __bfloat162float(__float2bfloat16(v[2]));
    float h3 = __bfloat162float(__float2bfloat16(v[3]));
    dst[idx] = make_uint4(bf16hi(v[0], v[1]), bf16hi(v[2], v[3]),
                          bf16hi(v[0]-h0, v[1]-h1), bf16hi(v[2]-h2, v[3]-h3));
}

// ---------------- build x (packed NHWC, stride 192, zero-padded) ----------------
__global__ void __launch_bounds__(Wn) build_x_kernel(
    const float* __restrict__ dm, const float* __restrict__ sx,
    const float* __restrict__ sy, const float* __restrict__ feat,
    const float* __restrict__ conf, const float* __restrict__ fL,
    const float* __restrict__ fR)
{
    __shared__ float srow[8*Wn];
    const int b = blockIdx.x / Hn, y = blockIdx.x % Hn, x = threadIdx.x;
    const int prow = b*HW + y*Wn;
    const float dval = dm[prow + x];
    int i0[5], i1[5]; float fr[5];
#pragma unroll
    for (int i = 0; i < 5; i++) {
        float xs = fminf(fmaxf((float)x - dval - (float)(i-2), 0.f), (float)(Wn-1));
        float f0 = floorf(xs);
        i0[i] = (int)f0; fr[i] = xs - f0; i1[i] = min(i0[i]+1, Wn-1);
    }
    uint32_t* xb = g_xs + ((size_t)(b*Hn + y)*Wn + x)*XST;
    const float* fLp = fL + (size_t)b*Cn*HW + (size_t)y*Wn + x;
    const float* fRp = fR + (size_t)b*Cn*HW + (size_t)y*Wn;
    uint32_t cw[40];
    for (int g = 0; g < 8; g++) {
        __syncthreads();
#pragma unroll
        for (int j = 0; j < 8; j++) srow[j*Wn + x] = fRp[(size_t)(g*8+j)*HW + x];
        __syncthreads();
        float acc[5] = {0.f,0.f,0.f,0.f,0.f};
        uint32_t flw[8], wpw[8];
#pragma unroll
        for (int j = 0; j < 8; j++) {
            const float fl = fLp[(size_t)(g*8+j)*HW];
            flw[j] = split_pack(fl);
#pragma unroll
            for (int i = 0; i < 5; i++) {
                float v = srow[j*Wn+i0[i]]*(1.f-fr[i]) + srow[j*Wn+i1[i]]*fr[i];
                acc[i] += fl*v;
                if (i == 2) wpw[j] = split_pack(v);
            }
        }
        *(uint4*)(xb + g*8)     = make_uint4(flw[0], flw[1], flw[2], flw[3]);
        *(uint4*)(xb + g*8 + 4) = make_uint4(flw[4], flw[5], flw[6], flw[7]);
        *(uint4*)(xb + 64 + g*8)     = make_uint4(wpw[0], wpw[1], wpw[2], wpw[3]);
        *(uint4*)(xb + 64 + g*8 + 4) = make_uint4(wpw[4], wpw[5], wpw[6], wpw[7]);
#pragma unroll
        for (int i = 0; i < 5; i++) cw[g*5+i] = split_pack(acc[i]*(1.f/8.f));
    }
    uint32_t fw[16];
#pragma unroll
    for (int j = 0; j < TFn; j++) fw[j] = split_pack(feat[((size_t)b*TFn + j)*HW + y*Wn + x]);
#pragma unroll
    for (int i = 0; i < 4; i++)
        *(uint4*)(xb + 128 + i*4) = make_uint4(fw[4*i], fw[4*i+1], fw[4*i+2], fw[4*i+3]);
    *(uint4*)(xb + 144) = make_uint4(split_pack(dval), split_pack(sx[prow+x]),
                                     split_pack(sy[prow+x]), split_pack(conf[prow+x]));
#pragma unroll
    for (int i = 0; i < 10; i++)
        *(uint4*)(xb + 148 + i*4) = make_uint4(cw[4*i], cw[4*i+1], cw[4*i+2], cw[4*i+3]);
    *(uint4*)(xb + 188) = make_uint4(0,0,0,0);
}

// ---------------- HMMA implicit-GEMM 3x3 conv ----------------
// CTA: 64 px of one row x 48 oc. Warp = m16. A direct from packed NHWC gmem,
// B prepacked fragments from gmem (L1-resident). No smem, no barriers.
template<int NCHUNK, int CHS>
__global__ void __launch_bounds__(128) conv_hmma_kernel(
    const uint32_t* __restrict__ xin, const uint4* __restrict__ Bf,
    float* __restrict__ out)
{
    const int lane = threadIdx.x & 31, wrp = threadIdx.x >> 5;
    const int t = blockIdx.x;
    const int b = t / (Hn*10);
    const int r = t % (Hn*10);
    const int y = r / 10;
    const int x0 = (r % 10)*64 + wrp*16;
    const int r0 = lane >> 2;            // fragment row 0..7
    const int cq = (lane & 3)*2;         // channel sub-offset

    float acc[6][4];
#pragma unroll
    for (int nb = 0; nb < 6; nb++)
#pragma unroll
        for (int j = 0; j < 4; j++) acc[nb][j] = 0.f;

    const uint4* Bp = Bf + lane;

#pragma unroll
    for (int tap = 0; tap < 9; tap++) {
        const int dy = tap/3, dx = tap%3;
        const int gy = y + dy - 1;
        if (gy < 0 || gy >= Hn) { Bp += NCHUNK*3*6*32; continue; }
        const int gx0 = x0 + r0 + dx - 1;
        const int gx1 = gx0 + 8;
        const bool v0 = (gx0 >= 0) && (gx0 < Wn);
        const bool v1 = (gx1 < Wn);      // gx1 >= 7 always
        const uint32_t* p0 = xin + ((size_t)(b*Hn + gy)*Wn + (v0 ? gx0 : 0))*CHS;
        const uint32_t* p1 = xin + ((size_t)(b*Hn + gy)*Wn + (v1 ? gx1 : 0))*CHS;
#pragma unroll
        for (int chunk = 0; chunk < NCHUNK; chunk++) {
#pragma unroll
            for (int ks = 0; ks < 3; ks++) {
                const int c = chunk*48 + ks*16 + cq;
                uint2 z = make_uint2(0u, 0u);
                uint2 w00 = v0 ? *(const uint2*)(p0 + c)     : z;
                uint2 w01 = v0 ? *(const uint2*)(p0 + c + 8) : z;
                uint2 w10 = v1 ? *(const uint2*)(p1 + c)     : z;
                uint2 w11 = v1 ? *(const uint2*)(p1 + c + 8) : z;
                uint32_t ah0 = __byte_perm(w00.x, w00.y, 0x5410);
                uint32_t al0 = __byte_perm(w00.x, w00.y, 0x7632);
                uint32_t ah1 = __byte_perm(w10.x, w10.y, 0x5410);
                uint32_t al1 = __byte_perm(w10.x, w10.y, 0x7632);
                uint32_t ah2 = __byte_perm(w01.x, w01.y, 0x5410);
                uint32_t al2 = __byte_perm(w01.x, w01.y, 0x7632);
                uint32_t ah3 = __byte_perm(w11.x, w11.y, 0x5410);
                uint32_t al3 = __byte_perm(w11.x, w11.y, 0x7632);
#pragma unroll
                for (int nb = 0; nb < 6; nb++) {
                    uint4 bb = Bp[nb*32];
                    MMA_BF16(acc[nb], ah0, ah1, ah2, ah3, bb.x, bb.y);  // Ahi*Whi
                    MMA_BF16(acc[nb], ah0, ah1, ah2, ah3, bb.z, bb.w);  // Ahi*Wlo
                    MMA_BF16(acc[nb], al0, al1, al2, al3, bb.x, bb.y);  // Alo*Whi
                }
                Bp += 6*32;
            }
        }
    }

    const int px0 = x0 + r0, px1 = px0 + 8;
    float* ob = out + (size_t)b*HIDDEN*HW + (size_t)y*Wn;
#pragma unroll
    for (int nb = 0; nb < 6; nb++) {
        const int n0 = nb*8 + cq;
        ob[(size_t)n0*HW + px0]     = acc[nb][0];
        ob[(size_t)(n0+1)*HW + px0] = acc[nb][1];
        ob[(size_t)n0*HW + px1]     = acc[nb][2];
        ob[(size_t)(n0+1)*HW + px1] = acc[nb][3];
    }
}

// ---------------- GN stats ----------------
__global__ void zero_stats_kernel() {
    if (threadIdx.x < Bn*GROUPS*2) g_stats[threadIdx.x] = 0.0;
}
__global__ void __launch_bounds__(256) gn_reduce_kernel(const float* __restrict__ h)
{
    const int bc = blockIdx.x, slice = blockIdx.y;
    const float4* p = (const float4*)(h + (size_t)bc*HW) + slice*6400 + threadIdx.x;
    float s0=0.f,s1=0.f,s2=0.f,s3=0.f, q0=0.f,q1=0.f,q2=0.f,q3=0.f;
#pragma unroll
    for (int k = 0; k < 25; k++) {
        float4 f = p[k*256];
        s0 += f.x; s1 += f.y; s2 += f.z; s3 += f.w;
        q0 += f.x*f.x; q1 += f.y*f.y; q2 += f.z*f.z; q3 += f.w*f.w;
    }
    double s = ((double)s0 + s1) + ((double)s2 + s3);
    double q = ((double)q0 + q1) + ((double)q2 + q3);
#pragma unroll
    for (int o = 16; o > 0; o >>= 1) {
        s += __shfl_down_sync(0xFFFFFFFFu, s, o);
        q += __shfl_down_sync(0xFFFFFFFFu, q, o);
    }
    __shared__ double ss[8], qq[8];
    if ((threadIdx.x & 31) == 0) { ss[threadIdx.x>>5] = s; qq[threadIdx.x>>5] = q; }
    __syncthreads();
    if (threadIdx.x == 0) {
        double S = 0.0, Q = 0.0;
#pragma unroll
        for (int w = 0; w < 8; w++) { S += ss[w]; Q += qq[w]; }
        const int b = bc / HIDDEN, c = bc % HIDDEN, g = c / CPG;
        atomicAdd(&g_stats[(b*GROUPS+g)*2+0], S);
        atomicAdd(&g_stats[(b*GROUPS+g)*2+1], Q);
    }
}
__global__ void finalize_stats_kernel(const float* __restrict__ gamma, const float* __restrict__ beta)
{
    const int i = threadIdx.x;
    if (i >= Bn*HIDDEN) return;
    const int b = i / HIDDEN, c = i % HIDDEN, g = c / CPG;
    double mean = g_stats[(b*GROUPS+g)*2+0] / (double)GN_N;
    double var  = g_stats[(b*GROUPS+g)*2+1] / (double)GN_N - mean*mean;
    float inv = (float)rsqrt(var + 1e-5);
    float sc = gamma[c]*inv;
    g_scale[i] = sc;
    g_shift[i] = beta[c] - (float)mean*sc;
}

// ---------------- GN+SiLU -> packed NHWC (stride 48) ----------------
__global__ void __launch_bounds__(256) hsplit_kernel(const float* __restrict__ h, uint32_t* __restrict__ dst)
{
    const int idx = blockIdx.x*256 + threadIdx.x;
    const int b = idx / HW, rem = idx % HW;
    const float* hp = h + (size_t)b*HIDDEN*HW + rem;
    const float* scb = g_scale + b*HIDDEN;
    const float* shb = g_shift + b*HIDDEN;
    uint32_t w[HIDDEN];
#pragma unroll
    for (int c = 0; c < HIDDEN; c++) {
        float z = hp[(size_t)c*HW]*scb[c] + shb[c];
        w[c] = split_pack(z / (1.f + expf(-z)));
    }
    uint4* op = (uint4*)(dst + (size_t)idx*HIDDEN);
#pragma unroll
    for (int i = 0; i < 12; i++) op[i] = make_uint4(w[4*i], w[4*i+1], w[4*i+2], w[4*i+3]);
}

// ---------------- heads ----------------
__global__ void __launch_bounds__(256) heads_kernel(
    const float* __restrict__ h,
    const float* __restrict__ dm, const float* __restrict__ sxp,
    const float* __restrict__ syp, const float* __restrict__ feat,
    const float* __restrict__ conf,
    const float* __restrict__ hd_w,  const float* __restrict__ hd_b,
    const float* __restrict__ hsx_w, const float* __restrict__ hsx_b,
    const float* __restrict__ hsy_w, const float* __restrict__ hsy_b,
    const float* __restrict__ hc_w,  const float* __restrict__ hc_b,
    const float* __restrict__ hf_w,  const float* __restrict__ hf_b,
    float* __restrict__ out)
{
    __shared__ __align__(16) float2 wsmT[HIDDEN*10];
    __shared__ float bia[20];
    __shared__ float sc[HIDDEN], sh[HIDDEN];
    const int tid = threadIdx.x, b = blockIdx.y;
    for (int idx = tid; idx < 10*HIDDEN; idx += 256) {
        int c = idx / 10, q = idx % 10;
        float w[2];
#pragma unroll
        for (int j = 0; j < 2; j++) {
            int o = 2*q + j;
            if (o == 0)      w[j] = hd_w[c];
            else if (o == 1) w[j] = hsx_w[c];
            else if (o == 2) w[j] = hsy_w[c];
            else if (o == 3) w[j] = hc_w[c];
            else             w[j] = hf_w[(o-4)*HIDDEN + c];
        }
        wsmT[idx] = make_float2(w[0], w[1]);
    }
    if (tid < 20)
        bia[tid] = (tid==0) ? hd_b[0] : (tid==1) ? hsx_b[0] : (tid==2) ? hsy_b[0]
                 : (tid==3) ? hc_b[0] : hf_b[tid-4];
    if (tid < HIDDEN) { sc[tid] = g_scale[b*HIDDEN + tid]; sh[tid] = g_shift[b*HIDDEN + tid]; }
    __syncthreads();

    const int rem = blockIdx.x*256 + tid;
    const float* hp = h + (size_t)b*HIDDEN*HW + rem;
    ull acc[10];
#pragma unroll
    for (int q = 0; q < 10; q++) acc[q] = 0ull;
#pragma unroll 4
    for (int c = 0; c < HIDDEN; c++) {
        float z = hp[(size_t)c*HW]*sc[c] + sh[c];
        float a = z / (1.f + expf(-z));
        ull da; PACK2(da, a, a);
        const ull* wrow = (const ull*)&wsmT[c*10];
        ulonglong2 w01 = *(const ulonglong2*)(wrow + 0);
        ulonglong2 w23 = *(const ulonglong2*)(wrow + 2);
        ulonglong2 w45 = *(const ulonglong2*)(wrow + 4);
        ulonglong2 w67 = *(const ulonglong2*)(wrow + 6);
        ulonglong2 w89 = *(const ulonglong2*)(wrow + 8);
        FMA2(acc[0], w01.x, da); FMA2(acc[1], w01.y, da);
        FMA2(acc[2], w23.x, da); FMA2(acc[3], w23.y, da);
        FMA2(acc[4], w45.x, da); FMA2(acc[5], w45.y, da);
        FMA2(acc[6], w67.x, da); FMA2(acc[7], w67.y, da);
        FMA2(acc[8], w89.x, da); FMA2(acc[9], w89.y, da);
    }
    float ao[20];
#pragma unroll
    for (int q = 0; q < 10; q++) UNPACK2(ao[2*q], ao[2*q+1], acc[q]);
    const int p = b*HW + rem;
    float t = ao[0] + bia[0] + dm[p];
    out[p] = fmaxf(t, 0.f) + log1pf(expf(-fabsf(t)));
    out[BHW   + p] = sxp[p] + (ao[1] + bia[1])*0.1f;
    out[2*BHW + p] = syp[p] + (ao[2] + bia[2])*0.1f;
#pragma unroll
    for (int j = 0; j < TFn; j++) {
        size_t fi = ((size_t)b*TFn + j)*HW + rem;
        out[3*(size_t)BHW + fi] = feat[fi] + ao[4+j] + bia[4+j];
    }
    float cz = ao[3] + bia[3] + 2.f*conf[p] - 1.f;
    out[19*(size_t)BHW + p] = 1.f / (1.f + expf(-cz));
}

// ---------------- launcher ----------------
extern "C" void kernel_launch(void* const* d_in, const int* in_sizes, int n_in,
                              void* d_out, int out_size)
{
    const float* dm   = (const float*)d_in[0];
    const float* sx   = (const float*)d_in[1];
    const float* sy   = (const float*)d_in[2];
    const float* feat = (const float*)d_in[3];
    const float* conf = (const float*)d_in[4];
    const float* fL   = (const float*)d_in[5];
    const float* fR   = (const float*)d_in[6];
    const float* w1   = (const float*)d_in[7];
    const float* w2   = (const float*)d_in[8];
    const float* w3   = (const float*)d_in[9];
    float* out = (float*)d_out;

    uint32_t *pxs, *phs; float *ph1, *ph2; uint4 *pB1, *pB2, *pB3;
    cudaGetSymbolAddress((void**)&pxs, g_xs);
    cudaGetSymbolAddress((void**)&phs, g_hs);
    cudaGetSymbolAddress((void**)&ph1, g_h1);
    cudaGetSymbolAddress((void**)&ph2, g_h2);
    cudaGetSymbolAddress((void**)&pB1, g_Bf1);
    cudaGetSymbolAddress((void**)&pB2, g_Bf2);
    cudaGetSymbolAddress((void**)&pB3, g_Bf3);

    const dim3 rgrid(Bn*HIDDEN, 8);
    const dim3 hgrid(HW/256, Bn);

    repack_frag_kernel<IN_CH, 4><<<(9*4*3*6*32 + 255)/256, 256>>>(w1, pB1);
    repack_frag_kernel<HIDDEN, 1><<<(9*1*3*6*32 + 255)/256, 256>>>(w2, pB2);
    repack_frag_kernel<HIDDEN, 1><<<(9*1*3*6*32 + 255)/256, 256>>>(w3, pB3);

    build_x_kernel<<<Bn*Hn, Wn>>>(dm, sx, sy, feat, conf, fL, fR);

    conv_hmma_kernel<4, XST><<<NT2, 128>>>(pxs, pB1, ph1);
    zero_stats_kernel<<<1, 64>>>();
    gn_reduce_kernel<<<rgrid, 256>>>(ph1);
    finalize_stats_kernel<<<1, 96>>>((const float*)d_in[10], (const float*)d_in[11]);
    hsplit_kernel<<<BHW/256, 256>>>(ph1, phs);

    conv_hmma_kernel<1, HIDDEN><<<NT2, 128>>>(phs, pB2, ph2);
    zero_stats_kernel<<<1, 64>>>();
    gn_reduce_kernel<<<rgrid, 256>>>(ph2);
    finalize_stats_kernel<<<1, 96>>>((const float*)d_in[12], (const float*)d_in[13]);
    hsplit_kernel<<<BHW/256, 256>>>(ph2, phs);

    conv_hmma_kernel<1, HIDDEN><<<NT2, 128>>>(phs, pB3, ph1);
    zero_stats_kernel<<<1, 64>>>();
    gn_reduce_kernel<<<rgrid, 256>>>(ph1);
    finalize_stats_kernel<<<1, 96>>>((const float*)d_in[14], (const float*)d_in[15]);

    heads_kernel<<<hgrid, 256>>>(ph1, dm, sx, sy, feat, conf,
                                 (const float*)d_in[16], (const float*)d_in[17],
                                 (const float*)d_in[18], (const float*)d_in[19],
                                 (const float*)d_in[20], (const float*)d_in[21],
                                 (const float*)d_in[22], (const float*)d_in[23],
                                 (const float*)d_in[24], (const float*)d_in[25], out);
}